// round 3
// baseline (speedup 1.0000x reference)
#include <cuda_runtime.h>
#include <math.h>

// Problem constants
#define BB   64
#define TENC 64
#define HH   1024
#define EE   512
#define VV   32000
#define LAT  128
#define STY  64
#define KCAT 192      // LAT + STY
#define G3   3072     // 3*H
#define XCK  2048     // 2*H

// SGEMM tiling
#define BM  64
#define BN  128
#define BKD 16

// ---------------- static device scratch (allocation-free) ----------------
__device__ float g_WihT[EE * G3];        // W_ih transposed [E, 3H]
__device__ float g_WhhT[HH * G3];        // W_hh transposed [H, 3H]
__device__ float g_WaT [HH * HH];        // W_a transposed  [H, H]
__device__ float g_encwa[BB * TENC * HH];// enc @ W_a^T
__device__ float g_h  [BB * HH];         // hidden state
__device__ float g_x  [BB * EE];         // current input embedding
__device__ float g_xc [BB * XCK];        // [h_new | ctx] for logits GEMM
__device__ float g_gpart[16 * BB * G3];  // split-K partials: 0..7 = gi, 8..15 = gh

// ---------------- shared-memory layout for SGEMM ----------------
struct SmemT {
    float A [2][BKD][BM];
    float Bt[2][BKD][BN];
};

// Double-buffered register-blocked fp32 GEMM tile: C[BM,BN] = A[BM,K] @ B[K,BN] (+bias)
// A row-major (lda), B row-major (ldb), C row-major (ldc). K % 16 == 0.
__device__ __forceinline__ void gemm_body(
    const float* __restrict__ A, int lda,
    const float* __restrict__ Bm, int ldb,
    float* __restrict__ C, int ldc,
    const float* __restrict__ bias, int K, SmemT* s)
{
    const int tid = threadIdx.x;          // 256 threads
    const int m0  = (tid >> 4) * 4;       // 16 thread-rows * 4
    const int n0  = (tid & 15) * 8;       // 16 thread-cols * 8
    const int ar  = tid >> 2;             // A load: 64 rows
    const int ac  = (tid & 3) * 4;        // 4 float4-cols of 16 k
    const int br  = tid >> 5;             // B load: 8 rows per pass (x2)
    const int bc  = (tid & 31) * 4;       // 32 float4-cols of 128 n

    float acc[4][8];
#pragma unroll
    for (int i = 0; i < 4; i++)
#pragma unroll
        for (int j = 0; j < 8; j++) acc[i][j] = 0.f;

    const int nt = K / BKD;

    // preload tile 0
    float4 pa  = *(const float4*)(A  + (size_t)ar * lda + ac);
    float4 pb0 = *(const float4*)(Bm + (size_t)br * ldb + bc);
    float4 pb1 = *(const float4*)(Bm + (size_t)(br + 8) * ldb + bc);
    s->A[0][ac + 0][ar] = pa.x; s->A[0][ac + 1][ar] = pa.y;
    s->A[0][ac + 2][ar] = pa.z; s->A[0][ac + 3][ar] = pa.w;
    *(float4*)&s->Bt[0][br][bc]     = pb0;
    *(float4*)&s->Bt[0][br + 8][bc] = pb1;
    __syncthreads();

    for (int kt = 0; kt < nt; kt++) {
        const int buf = kt & 1;
        if (kt + 1 < nt) {
            const float* Ap = A  + (kt + 1) * BKD;
            const float* Bp = Bm + (size_t)(kt + 1) * BKD * ldb;
            pa  = *(const float4*)(Ap + (size_t)ar * lda + ac);
            pb0 = *(const float4*)(Bp + (size_t)br * ldb + bc);
            pb1 = *(const float4*)(Bp + (size_t)(br + 8) * ldb + bc);
        }
#pragma unroll
        for (int k = 0; k < BKD; k++) {
            float4 av  = *(const float4*)&s->A [buf][k][m0];
            float4 bv0 = *(const float4*)&s->Bt[buf][k][n0];
            float4 bv1 = *(const float4*)&s->Bt[buf][k][n0 + 4];
            float a0 = av.x, a1 = av.y, a2 = av.z, a3 = av.w;
            float b[8] = {bv0.x, bv0.y, bv0.z, bv0.w, bv1.x, bv1.y, bv1.z, bv1.w};
#pragma unroll
            for (int j = 0; j < 8; j++) {
                acc[0][j] += a0 * b[j];
                acc[1][j] += a1 * b[j];
                acc[2][j] += a2 * b[j];
                acc[3][j] += a3 * b[j];
            }
        }
        if (kt + 1 < nt) {
            const int nb = buf ^ 1;
            s->A[nb][ac + 0][ar] = pa.x; s->A[nb][ac + 1][ar] = pa.y;
            s->A[nb][ac + 2][ar] = pa.z; s->A[nb][ac + 3][ar] = pa.w;
            *(float4*)&s->Bt[nb][br][bc]     = pb0;
            *(float4*)&s->Bt[nb][br + 8][bc] = pb1;
        }
        __syncthreads();
    }

    float bv[8];
#pragma unroll
    for (int j = 0; j < 8; j++) bv[j] = bias ? bias[n0 + j] : 0.f;
#pragma unroll
    for (int i = 0; i < 4; i++) {
        float* Cr = C + (size_t)(m0 + i) * ldc + n0;
        float4 o0 = make_float4(acc[i][0] + bv[0], acc[i][1] + bv[1],
                                acc[i][2] + bv[2], acc[i][3] + bv[3]);
        float4 o1 = make_float4(acc[i][4] + bv[4], acc[i][5] + bv[5],
                                acc[i][6] + bv[6], acc[i][7] + bv[7]);
        *(float4*)(Cr)     = o0;
        *(float4*)(Cr + 4) = o1;
    }
}

// Generic SGEMM: grid = (N/BN, M/BM)
__global__ __launch_bounds__(256) void sgemm_nn(
    const float* __restrict__ A, int lda,
    const float* __restrict__ Bm, int ldb,
    float* __restrict__ C, int ldc,
    const float* __restrict__ bias, int K)
{
    __shared__ SmemT s;
    const float* At = A  + (size_t)blockIdx.y * BM * lda;
    const float* Bt = Bm + (size_t)blockIdx.x * BN;
    float*       Ct = C  + (size_t)blockIdx.y * BM * ldc + (size_t)blockIdx.x * BN;
    const float* bt = bias ? bias + blockIdx.x * BN : (const float*)0;
    gemm_body(At, lda, Bt, ldb, Ct, ldc, bt, K, &s);
}

// GRU gate GEMMs with split-K=8 (needed: otherwise only 24 blocks for 148 SMs).
// grid = (G3/BN = 24, 16). z<8: gi split z of K=512; z>=8: gh split of K=1024.
__global__ __launch_bounds__(256) void gru_gates(void)
{
    __shared__ SmemT s;
    const int z  = blockIdx.y;
    const int nt = blockIdx.x;
    const float *A, *Bm;
    int lda, K;
    if (z < 8) {
        const int k0 = z * (EE / 8);                       // 64-wide chunks
        A = g_x + k0; lda = EE; K = EE / 8;
        Bm = g_WihT + (size_t)k0 * G3 + nt * BN;
    } else {
        const int k0 = (z - 8) * (HH / 8);                 // 128-wide chunks
        A = g_h + k0; lda = HH; K = HH / 8;
        Bm = g_WhhT + (size_t)k0 * G3 + nt * BN;
    }
    float* C = g_gpart + (size_t)z * BB * G3 + nt * BN;
    gemm_body(A, lda, Bm, G3, C, G3, (const float*)0, K, &s);
}

// ---------------- small kernels ----------------

// out[cols, rows] = in[rows, cols]^T  (coalesced writes)
__global__ void transpose_kernel(const float* __restrict__ in, float* __restrict__ out,
                                 int rows, int cols)
{
    size_t idx = (size_t)blockIdx.x * blockDim.x + threadIdx.x;
    size_t total = (size_t)rows * cols;
    if (idx < total) {
        size_t oc = idx % rows;   // in row
        size_t orow = idx / rows; // in col
        out[idx] = in[oc * cols + orow];
    }
}

// h0 = cat(latent, style_emb[style]) @ W_l2h + b ; x0 = emb[BOS=1]
__global__ __launch_bounds__(256) void init_kernel(
    const float* __restrict__ latent, const int* __restrict__ style,
    const float* __restrict__ style_emb, const float* __restrict__ W_l2h,
    const float* __restrict__ b_l2h, const float* __restrict__ emb)
{
    __shared__ float cat[KCAT];
    const int b = blockIdx.x, tid = threadIdx.x;
    if (tid < LAT) cat[tid] = latent[b * LAT + tid];
    else if (tid < KCAT) cat[tid] = style_emb[style[b] * STY + (tid - LAT)];
    __syncthreads();
    for (int j = tid; j < HH; j += 256) {
        float acc = b_l2h[j];
#pragma unroll 4
        for (int k = 0; k < KCAT; k++) acc += cat[k] * W_l2h[k * HH + j];
        g_h[b * HH + j] = acc;
    }
    for (int i = tid; i < EE; i += 256) g_x[b * EE + i] = emb[1 * EE + i]; // BOS
}

// GRU combine: reduce split-K partials, apply gates (torch order r,z,n), update h.
__global__ __launch_bounds__(256) void gru_combine(
    const float* __restrict__ b_ih, const float* __restrict__ b_hh)
{
    const int idx = blockIdx.x * 256 + threadIdx.x;   // B*H threads
    const int b = idx >> 10, j = idx & 1023;
    float ir = b_ih[j], iz = b_ih[HH + j], inn = b_ih[2 * HH + j];
    float hr = b_hh[j], hz = b_hh[HH + j], hn  = b_hh[2 * HH + j];
#pragma unroll
    for (int sp = 0; sp < 8; sp++) {
        const float* P = g_gpart + (size_t)sp * BB * G3 + (size_t)b * G3;
        ir += P[j]; iz += P[HH + j]; inn += P[2 * HH + j];
    }
#pragma unroll
    for (int sp = 8; sp < 16; sp++) {
        const float* P = g_gpart + (size_t)sp * BB * G3 + (size_t)b * G3;
        hr += P[j]; hz += P[HH + j]; hn += P[2 * HH + j];
    }
    float r  = 1.f / (1.f + expf(-(ir + hr)));
    float zz = 1.f / (1.f + expf(-(iz + hz)));
    float n  = tanhf(inn + r * hn);
    float hold = g_h[idx];
    float hnew = (1.f - zz) * n + zz * hold;
    g_h[idx] = hnew;
    g_xc[(size_t)b * XCK + j] = hnew;
}

// Attention: scores = h . enc_wa[b,t,:], softmax over t, ctx = attn @ enc. One block per b.
__global__ __launch_bounds__(256) void attention_kernel(const float* __restrict__ enc)
{
    __shared__ float hs[HH];
    __shared__ float sc[TENC];
    const int b = blockIdx.x, tid = threadIdx.x;
    for (int j = tid; j < HH; j += 256) hs[j] = g_h[b * HH + j];
    __syncthreads();

    const int t  = tid >> 2;
    const int l4 = tid & 3;
    const float* ew = g_encwa + ((size_t)b * TENC + t) * HH;
    float p = 0.f;
    for (int k = l4; k < HH; k += 4) p += hs[k] * ew[k];
    p += __shfl_down_sync(0xffffffffu, p, 1);
    p += __shfl_down_sync(0xffffffffu, p, 2);
    if (l4 == 0) sc[t] = p;
    __syncthreads();

    if (tid == 0) {
        float m = sc[0];
        for (int i = 1; i < TENC; i++) m = fmaxf(m, sc[i]);
        float ssum = 0.f;
        for (int i = 0; i < TENC; i++) { float e2 = expf(sc[i] - m); sc[i] = e2; ssum += e2; }
        float inv = 1.f / ssum;
        for (int i = 0; i < TENC; i++) sc[i] *= inv;
    }
    __syncthreads();

    for (int j = tid; j < HH; j += 256) {
        float c = 0.f;
        const float* eb = enc + (size_t)b * TENC * HH + j;
#pragma unroll 8
        for (int t2 = 0; t2 < TENC; t2++) c += sc[t2] * eb[(size_t)t2 * HH];
        g_xc[(size_t)b * XCK + HH + j] = c;
    }
}

// Greedy argmax over V (first-index tiebreak, matching jnp.argmax) + embedding gather.
__global__ __launch_bounds__(256) void argmax_embed(
    const float* __restrict__ out_base, int t, int TD, const float* __restrict__ emb)
{
    __shared__ float vmax[256];
    __shared__ int   vidx[256];
    const int b = blockIdx.x, tid = threadIdx.x;
    const float* row = out_base + (size_t)b * TD * VV + (size_t)t * VV;
    float bm = -3.402823466e38f; int bi = 0;
    for (int v = tid; v < VV; v += 256) {
        float val = row[v];
        if (val > bm) { bm = val; bi = v; }
    }
    vmax[tid] = bm; vidx[tid] = bi;
    __syncthreads();
    for (int sft = 128; sft > 0; sft >>= 1) {
        if (tid < sft) {
            float ov = vmax[tid + sft]; int oi = vidx[tid + sft];
            if (ov > vmax[tid] || (ov == vmax[tid] && oi < vidx[tid])) {
                vmax[tid] = ov; vidx[tid] = oi;
            }
        }
        __syncthreads();
    }
    const int tok = vidx[0];
    for (int i = tid; i < EE; i += 256) g_x[b * EE + i] = emb[(size_t)tok * EE + i];
}

// ---------------- host launcher ----------------
extern "C" void kernel_launch(void* const* d_in, const int* in_sizes, int n_in,
                              void* d_out, int out_size)
{
    int ci = 0;
    const float* latent    = (const float*)d_in[ci++];
    const int*   style     = (const int*)  d_in[ci++];
    const float* enc       = (const float*)d_in[ci++];
    if (ci < n_in && in_sizes[ci] == 1) ci++;           // skip max_length scalar if present
    const float* emb       = (const float*)d_in[ci++];
    const float* style_emb = (const float*)d_in[ci++];
    const float* W_l2h     = (const float*)d_in[ci++];
    const float* b_l2h     = (const float*)d_in[ci++];
    const float* W_ih      = (const float*)d_in[ci++];
    const float* W_hh      = (const float*)d_in[ci++];
    const float* b_ih      = (const float*)d_in[ci++];
    const float* b_hh      = (const float*)d_in[ci++];
    const float* W_a       = (const float*)d_in[ci++];
    const float* W_out     = (const float*)d_in[ci++];
    const float* b_out     = (const float*)d_in[ci++];
    float* out = (float*)d_out;

    const int TD = out_size / (BB * VV);                // decode length (32)

    float *pWihT, *pWhhT, *pWaT, *pencwa, *pxc;
    cudaGetSymbolAddress((void**)&pWihT, g_WihT);
    cudaGetSymbolAddress((void**)&pWhhT, g_WhhT);
    cudaGetSymbolAddress((void**)&pWaT,  g_WaT);
    cudaGetSymbolAddress((void**)&pencwa, g_encwa);
    cudaGetSymbolAddress((void**)&pxc,   g_xc);

    // one-time per-launch prep
    transpose_kernel<<<(G3 * EE + 255) / 256, 256>>>(W_ih, pWihT, G3, EE);
    transpose_kernel<<<(G3 * HH + 255) / 256, 256>>>(W_hh, pWhhT, G3, HH);
    transpose_kernel<<<(HH * HH + 255) / 256, 256>>>(W_a,  pWaT,  HH, HH);
    init_kernel<<<BB, 256>>>(latent, style, style_emb, W_l2h, b_l2h, emb);

    // enc_wa[b,t,k] = sum_h enc[b,t,h] * W_a[k,h]   (M=4096,N=1024,K=1024)
    {
        dim3 g(HH / BN, (BB * TENC) / BM);
        sgemm_nn<<<g, 256>>>(enc, HH, pWaT, HH, pencwa, HH, (const float*)0, HH);
    }

    for (int t = 0; t < TD; t++) {
        gru_gates<<<dim3(G3 / BN, 16), 256>>>();
        gru_combine<<<(BB * HH) / 256, 256>>>(b_ih, b_hh);
        attention_kernel<<<BB, 256>>>(enc);
        // logits[b, v] = xc[b,:] @ W_out + b_out, written straight into out[b, t, :]
        {
            dim3 g(VV / BN, 1);
            sgemm_nn<<<g, 256>>>(pxc, XCK, W_out, VV, out + (size_t)t * VV,
                                 TD * VV, b_out, XCK);
        }
        argmax_embed<<<BB, 256>>>(out, t, TD, emb);
    }
}

// round 4
// speedup vs baseline: 1.9638x; 1.9638x over previous
#include <cuda_runtime.h>
#include <cuda_bf16.h>
#include <math.h>

// Problem constants
#define BB   64
#define TENC 64
#define HH   1024
#define EE   512
#define VV   32000
#define LAT  128
#define STY  64
#define KCAT 192      // LAT + STY
#define G3   3072     // 3*H
#define XCK  2048     // 2*H

// fp32 SGEMM tiling (prep + GRU gates)
#define BM  64
#define BN  128
#define BKD 16

// logits mma tiling
#define APAD 72       // padded k-row length for A tiles (bank-conflict-free)
#define WPAD 72       // padded k-row length for W tiles
#define LOGITS_SMEM ((64*APAD*2 + 128*WPAD*2) * 2)   // 55296 bytes

// ---------------- static device scratch (allocation-free) ----------------
__device__ float g_WihT[EE * G3];        // W_ih transposed [E, 3H]
__device__ float g_WhhT[HH * G3];        // W_hh transposed [H, 3H]
__device__ float g_WaT [HH * HH];        // W_a transposed  [H, H]
__device__ float g_encwa[BB * TENC * HH];// enc @ W_a^T
__device__ float g_h  [BB * HH];         // hidden state
__device__ float g_x  [BB * EE];         // current input embedding
__device__ float g_xc [BB * XCK];        // [h_new | ctx] for logits GEMM
__device__ float g_gpart[16 * BB * G3];  // split-K partials: 0..7 = gi, 8..15 = gh
__device__ float g_scores[BB * TENC];    // attention scores

// bf16 hi/lo split of W_out, TRANSPOSED to [V][K] (k contiguous)
__device__ __nv_bfloat16 g_WoutHiT[(size_t)VV * XCK];
__device__ __nv_bfloat16 g_WoutLoT[(size_t)VV * XCK];
// bf16 hi/lo split of activations xc [64][2048]
__device__ __nv_bfloat16 g_Ahi[BB * XCK];
__device__ __nv_bfloat16 g_Alo[BB * XCK];

// ---------------- fp32 SGEMM (kept for prep + GRU gates) ----------------
struct SmemT {
    float A [2][BKD][BM];
    float Bt[2][BKD][BN];
};

__device__ __forceinline__ void gemm_body(
    const float* __restrict__ A, int lda,
    const float* __restrict__ Bm, int ldb,
    float* __restrict__ C, int ldc,
    const float* __restrict__ bias, int K, SmemT* s)
{
    const int tid = threadIdx.x;          // 256 threads
    const int m0  = (tid >> 4) * 4;
    const int n0  = (tid & 15) * 8;
    const int ar  = tid >> 2;
    const int ac  = (tid & 3) * 4;
    const int br  = tid >> 5;
    const int bc  = (tid & 31) * 4;

    float acc[4][8];
#pragma unroll
    for (int i = 0; i < 4; i++)
#pragma unroll
        for (int j = 0; j < 8; j++) acc[i][j] = 0.f;

    const int nt = K / BKD;

    float4 pa  = *(const float4*)(A  + (size_t)ar * lda + ac);
    float4 pb0 = *(const float4*)(Bm + (size_t)br * ldb + bc);
    float4 pb1 = *(const float4*)(Bm + (size_t)(br + 8) * ldb + bc);
    s->A[0][ac + 0][ar] = pa.x; s->A[0][ac + 1][ar] = pa.y;
    s->A[0][ac + 2][ar] = pa.z; s->A[0][ac + 3][ar] = pa.w;
    *(float4*)&s->Bt[0][br][bc]     = pb0;
    *(float4*)&s->Bt[0][br + 8][bc] = pb1;
    __syncthreads();

    for (int kt = 0; kt < nt; kt++) {
        const int buf = kt & 1;
        if (kt + 1 < nt) {
            const float* Ap = A  + (kt + 1) * BKD;
            const float* Bp = Bm + (size_t)(kt + 1) * BKD * ldb;
            pa  = *(const float4*)(Ap + (size_t)ar * lda + ac);
            pb0 = *(const float4*)(Bp + (size_t)br * ldb + bc);
            pb1 = *(const float4*)(Bp + (size_t)(br + 8) * ldb + bc);
        }
#pragma unroll
        for (int k = 0; k < BKD; k++) {
            float4 av  = *(const float4*)&s->A [buf][k][m0];
            float4 bv0 = *(const float4*)&s->Bt[buf][k][n0];
            float4 bv1 = *(const float4*)&s->Bt[buf][k][n0 + 4];
            float a0 = av.x, a1 = av.y, a2 = av.z, a3 = av.w;
            float b[8] = {bv0.x, bv0.y, bv0.z, bv0.w, bv1.x, bv1.y, bv1.z, bv1.w};
#pragma unroll
            for (int j = 0; j < 8; j++) {
                acc[0][j] += a0 * b[j];
                acc[1][j] += a1 * b[j];
                acc[2][j] += a2 * b[j];
                acc[3][j] += a3 * b[j];
            }
        }
        if (kt + 1 < nt) {
            const int nb = buf ^ 1;
            s->A[nb][ac + 0][ar] = pa.x; s->A[nb][ac + 1][ar] = pa.y;
            s->A[nb][ac + 2][ar] = pa.z; s->A[nb][ac + 3][ar] = pa.w;
            *(float4*)&s->Bt[nb][br][bc]     = pb0;
            *(float4*)&s->Bt[nb][br + 8][bc] = pb1;
        }
        __syncthreads();
    }

    float bv[8];
#pragma unroll
    for (int j = 0; j < 8; j++) bv[j] = bias ? bias[n0 + j] : 0.f;
#pragma unroll
    for (int i = 0; i < 4; i++) {
        float* Cr = C + (size_t)(m0 + i) * ldc + n0;
        float4 o0 = make_float4(acc[i][0] + bv[0], acc[i][1] + bv[1],
                                acc[i][2] + bv[2], acc[i][3] + bv[3]);
        float4 o1 = make_float4(acc[i][4] + bv[4], acc[i][5] + bv[5],
                                acc[i][6] + bv[6], acc[i][7] + bv[7]);
        *(float4*)(Cr)     = o0;
        *(float4*)(Cr + 4) = o1;
    }
}

__global__ __launch_bounds__(256) void sgemm_nn(
    const float* __restrict__ A, int lda,
    const float* __restrict__ Bm, int ldb,
    float* __restrict__ C, int ldc,
    const float* __restrict__ bias, int K)
{
    __shared__ SmemT s;
    const float* At = A  + (size_t)blockIdx.y * BM * lda;
    const float* Bt = Bm + (size_t)blockIdx.x * BN;
    float*       Ct = C  + (size_t)blockIdx.y * BM * ldc + (size_t)blockIdx.x * BN;
    const float* bt = bias ? bias + blockIdx.x * BN : (const float*)0;
    gemm_body(At, lda, Bt, ldb, Ct, ldc, bt, K, &s);
}

// GRU gate GEMMs with split-K=8. grid = (G3/BN = 24, 16).
__global__ __launch_bounds__(256) void gru_gates(void)
{
    __shared__ SmemT s;
    const int z  = blockIdx.y;
    const int nt = blockIdx.x;
    const float *A, *Bm;
    int lda, K;
    if (z < 8) {
        const int k0 = z * (EE / 8);
        A = g_x + k0; lda = EE; K = EE / 8;
        Bm = g_WihT + (size_t)k0 * G3 + nt * BN;
    } else {
        const int k0 = (z - 8) * (HH / 8);
        A = g_h + k0; lda = HH; K = HH / 8;
        Bm = g_WhhT + (size_t)k0 * G3 + nt * BN;
    }
    float* C = g_gpart + (size_t)z * BB * G3 + nt * BN;
    gemm_body(A, lda, Bm, G3, C, G3, (const float*)0, K, &s);
}

// ---------------- prep kernels ----------------

__global__ void transpose_kernel(const float* __restrict__ in, float* __restrict__ out,
                                 int rows, int cols)
{
    size_t idx = (size_t)blockIdx.x * blockDim.x + threadIdx.x;
    size_t total = (size_t)rows * cols;
    if (idx < total) {
        size_t oc = idx % rows;
        size_t orow = idx / rows;
        out[idx] = in[oc * cols + orow];
    }
}

// W_out [K=2048][V=32000] fp32 -> hi/lo bf16 transposed [V][K]
__global__ __launch_bounds__(256) void wout_split(const float* __restrict__ W)
{
    __shared__ float tile[32][33];
    const int v0 = blockIdx.x * 32, k0 = blockIdx.y * 32;
    const int tx = threadIdx.x, ty = threadIdx.y;   // block (32, 8)
#pragma unroll
    for (int i = 0; i < 4; i++)
        tile[ty + i * 8][tx] = W[(size_t)(k0 + ty + i * 8) * VV + v0 + tx];
    __syncthreads();
#pragma unroll
    for (int i = 0; i < 4; i++) {
        const int v = v0 + ty + i * 8;
        const int k = k0 + tx;
        float w = tile[tx][ty + i * 8];
        __nv_bfloat16 hi = __float2bfloat16_rn(w);
        __nv_bfloat16 lo = __float2bfloat16_rn(w - __bfloat162float(hi));
        g_WoutHiT[(size_t)v * XCK + k] = hi;
        g_WoutLoT[(size_t)v * XCK + k] = lo;
    }
}

__global__ __launch_bounds__(256) void init_kernel(
    const float* __restrict__ latent, const int* __restrict__ style,
    const float* __restrict__ style_emb, const float* __restrict__ W_l2h,
    const float* __restrict__ b_l2h, const float* __restrict__ emb)
{
    __shared__ float cat[KCAT];
    const int b = blockIdx.x, tid = threadIdx.x;
    if (tid < LAT) cat[tid] = latent[b * LAT + tid];
    else if (tid < KCAT) cat[tid] = style_emb[style[b] * STY + (tid - LAT)];
    __syncthreads();
    for (int j = tid; j < HH; j += 256) {
        float acc = b_l2h[j];
#pragma unroll 4
        for (int k = 0; k < KCAT; k++) acc += cat[k] * W_l2h[k * HH + j];
        g_h[b * HH + j] = acc;
    }
    for (int i = tid; i < EE; i += 256) g_x[b * EE + i] = emb[1 * EE + i]; // BOS
}

// ---------------- per-step small kernels ----------------

__global__ __launch_bounds__(256) void gru_combine(
    const float* __restrict__ b_ih, const float* __restrict__ b_hh)
{
    const int idx = blockIdx.x * 256 + threadIdx.x;   // B*H threads
    const int b = idx >> 10, j = idx & 1023;
    float ir = b_ih[j], iz = b_ih[HH + j], inn = b_ih[2 * HH + j];
    float hr = b_hh[j], hz = b_hh[HH + j], hn  = b_hh[2 * HH + j];
#pragma unroll
    for (int sp = 0; sp < 8; sp++) {
        const float* P = g_gpart + (size_t)sp * BB * G3 + (size_t)b * G3;
        ir += P[j]; iz += P[HH + j]; inn += P[2 * HH + j];
    }
#pragma unroll
    for (int sp = 8; sp < 16; sp++) {
        const float* P = g_gpart + (size_t)sp * BB * G3 + (size_t)b * G3;
        hr += P[j]; hz += P[HH + j]; hn += P[2 * HH + j];
    }
    float r  = 1.f / (1.f + expf(-(ir + hr)));
    float zz = 1.f / (1.f + expf(-(iz + hz)));
    float n  = tanhf(inn + r * hn);
    float hold = g_h[idx];
    float hnew = (1.f - zz) * n + zz * hold;
    g_h[idx] = hnew;
    g_xc[(size_t)b * XCK + j] = hnew;
}

// scores[b][t] = h[b] . enc_wa[b][t].  grid = BB*TENC blocks, 128 threads.
__global__ __launch_bounds__(128) void scores_kernel(void)
{
    __shared__ float red[4];
    const int b = blockIdx.x >> 6, t = blockIdx.x & 63;
    const int tid = threadIdx.x;
    const float* hw = g_h + b * HH;
    const float* ew = g_encwa + ((size_t)b * TENC + t) * HH;
    float p = 0.f;
#pragma unroll 2
    for (int k = tid; k < HH; k += 128) p += hw[k] * ew[k];
#pragma unroll
    for (int s = 16; s > 0; s >>= 1) p += __shfl_down_sync(0xffffffffu, p, s);
    if ((tid & 31) == 0) red[tid >> 5] = p;
    __syncthreads();
    if (tid == 0) g_scores[b * TENC + t] = red[0] + red[1] + red[2] + red[3];
}

// ctx: softmax(scores[b]) then ctx[b][j] = sum_t attn[t] * enc[b][t][j].
// grid (BB, 8), 128 threads -> each block covers 128 j.
__global__ __launch_bounds__(128) void ctx_kernel(const float* __restrict__ enc)
{
    __shared__ float at[TENC];
    const int b = blockIdx.x, jc = blockIdx.y, tid = threadIdx.x;
    if (tid < TENC) at[tid] = g_scores[b * TENC + tid];
    __syncthreads();
    if (tid == 0) {
        float m = at[0];
        for (int i = 1; i < TENC; i++) m = fmaxf(m, at[i]);
        float ssum = 0.f;
        for (int i = 0; i < TENC; i++) { float e2 = expf(at[i] - m); at[i] = e2; ssum += e2; }
        float inv = 1.f / ssum;
        for (int i = 0; i < TENC; i++) at[i] *= inv;
    }
    __syncthreads();
    const int j = jc * 128 + tid;
    const float* eb = enc + (size_t)b * TENC * HH + j;
    float c = 0.f;
#pragma unroll 8
    for (int t2 = 0; t2 < TENC; t2++) c += at[t2] * eb[(size_t)t2 * HH];
    g_xc[(size_t)b * XCK + HH + j] = c;
}

// Convert xc (fp32) to bf16 hi/lo for the mma logits GEMM.
__global__ __launch_bounds__(256) void aconv_kernel(void)
{
    const int idx = blockIdx.x * 256 + threadIdx.x;   // BB*XCK threads
    float x = g_xc[idx];
    __nv_bfloat16 hi = __float2bfloat16_rn(x);
    __nv_bfloat16 lo = __float2bfloat16_rn(x - __bfloat162float(hi));
    g_Ahi[idx] = hi;
    g_Alo[idx] = lo;
}

// ---------------- logits via bf16 mma with hi/lo compensation ----------------
// out[b][t][v] = xc[b] . W_out[:,v] + b_out[v]
// = Ahi.Whi + Alo.Whi + Ahi.Wlo (fp32 accum); dropped Alo.Wlo ~ 2^-18.
__device__ __forceinline__ void mma16816(float* c, const unsigned* a, const unsigned* b)
{
    asm volatile(
        "mma.sync.aligned.m16n8k16.row.col.f32.bf16.bf16.f32 "
        "{%0,%1,%2,%3}, {%4,%5,%6,%7}, {%8,%9}, {%0,%1,%2,%3};\n"
        : "+f"(c[0]), "+f"(c[1]), "+f"(c[2]), "+f"(c[3])
        : "r"(a[0]), "r"(a[1]), "r"(a[2]), "r"(a[3]), "r"(b[0]), "r"(b[1]));
}

// grid = VV/128 = 250 blocks, 256 threads (8 warps). Each warp: 64m x 16n.
__global__ __launch_bounds__(256) void logits_mma(
    const float* __restrict__ bias, float* __restrict__ out, int t, int TD)
{
    extern __shared__ __nv_bfloat16 sm[];
    __nv_bfloat16* sAhi = sm;
    __nv_bfloat16* sAlo = sAhi + 64 * APAD;
    __nv_bfloat16* sWhi = sAlo + 64 * APAD;
    __nv_bfloat16* sWlo = sWhi + 128 * WPAD;

    const int tid = threadIdx.x, warp = tid >> 5, lane = tid & 31;
    const int g = lane >> 2, tg = lane & 3;
    const int n0 = blockIdx.x * 128;

    float acc[4][2][4];
#pragma unroll
    for (int mt = 0; mt < 4; mt++)
#pragma unroll
        for (int nf = 0; nf < 2; nf++)
#pragma unroll
            for (int i = 0; i < 4; i++) acc[mt][nf][i] = 0.f;

    for (int kc = 0; kc < XCK / 64; kc++) {
        const int k0 = kc * 64;
        // A tiles: 64 rows x 64 k = 1024 uint2 each, 4 per thread
#pragma unroll
        for (int i = 0; i < 4; i++) {
            int idx = tid + i * 256;
            int m = idx >> 4, c = idx & 15;
            *(uint2*)&sAhi[m * APAD + c * 4] = *(const uint2*)&g_Ahi[m * XCK + k0 + c * 4];
            *(uint2*)&sAlo[m * APAD + c * 4] = *(const uint2*)&g_Alo[m * XCK + k0 + c * 4];
        }
        // W tiles: 128 rows x 64 k = 2048 uint2 each, 8 per thread
#pragma unroll
        for (int i = 0; i < 8; i++) {
            int idx = tid + i * 256;
            int v = idx >> 4, c = idx & 15;
            *(uint2*)&sWhi[v * WPAD + c * 4] =
                *(const uint2*)&g_WoutHiT[(size_t)(n0 + v) * XCK + k0 + c * 4];
            *(uint2*)&sWlo[v * WPAD + c * 4] =
                *(const uint2*)&g_WoutLoT[(size_t)(n0 + v) * XCK + k0 + c * 4];
        }
        __syncthreads();
#pragma unroll
        for (int kf = 0; kf < 4; kf++) {
            const int kb = kf * 16 + tg * 2;
            unsigned bhi[2][2], blo[2][2];
#pragma unroll
            for (int nf = 0; nf < 2; nf++) {
                const int nr = warp * 16 + nf * 8 + g;
                bhi[nf][0] = *(const unsigned*)&sWhi[nr * WPAD + kb];
                bhi[nf][1] = *(const unsigned*)&sWhi[nr * WPAD + kb + 8];
                blo[nf][0] = *(const unsigned*)&sWlo[nr * WPAD + kb];
                blo[nf][1] = *(const unsigned*)&sWlo[nr * WPAD + kb + 8];
            }
#pragma unroll
            for (int mt = 0; mt < 4; mt++) {
                const int r0 = mt * 16 + g, r1 = r0 + 8;
                unsigned ahi[4], alo[4];
                ahi[0] = *(const unsigned*)&sAhi[r0 * APAD + kb];
                ahi[1] = *(const unsigned*)&sAhi[r1 * APAD + kb];
                ahi[2] = *(const unsigned*)&sAhi[r0 * APAD + kb + 8];
                ahi[3] = *(const unsigned*)&sAhi[r1 * APAD + kb + 8];
                alo[0] = *(const unsigned*)&sAlo[r0 * APAD + kb];
                alo[1] = *(const unsigned*)&sAlo[r1 * APAD + kb];
                alo[2] = *(const unsigned*)&sAlo[r0 * APAD + kb + 8];
                alo[3] = *(const unsigned*)&sAlo[r1 * APAD + kb + 8];
#pragma unroll
                for (int nf = 0; nf < 2; nf++) {
                    mma16816(acc[mt][nf], ahi, bhi[nf]);
                    mma16816(acc[mt][nf], alo, bhi[nf]);
                    mma16816(acc[mt][nf], ahi, blo[nf]);
                }
            }
        }
        __syncthreads();
    }

    // epilogue: add bias, write fp32 logits into out[b][t][v]
#pragma unroll
    for (int mt = 0; mt < 4; mt++) {
#pragma unroll
        for (int nf = 0; nf < 2; nf++) {
            const int n = n0 + warp * 16 + nf * 8 + tg * 2;
            const float b0v = bias[n], b1v = bias[n + 1];
            const int m0r = mt * 16 + g, m1r = m0r + 8;
            float2 o0 = make_float2(acc[mt][nf][0] + b0v, acc[mt][nf][1] + b1v);
            float2 o1 = make_float2(acc[mt][nf][2] + b0v, acc[mt][nf][3] + b1v);
            *(float2*)&out[((size_t)m0r * TD + t) * VV + n] = o0;
            *(float2*)&out[((size_t)m1r * TD + t) * VV + n] = o1;
        }
    }
}

// Greedy argmax over V (first-index tiebreak) + embedding gather.
__global__ __launch_bounds__(256) void argmax_embed(
    const float* __restrict__ out_base, int t, int TD, const float* __restrict__ emb)
{
    __shared__ float vmax[256];
    __shared__ int   vidx[256];
    const int b = blockIdx.x, tid = threadIdx.x;
    const float* row = out_base + (size_t)b * TD * VV + (size_t)t * VV;
    float bm = -3.402823466e38f; int bi = 0;
    for (int v = tid; v < VV; v += 256) {
        float val = row[v];
        if (val > bm) { bm = val; bi = v; }
    }
    vmax[tid] = bm; vidx[tid] = bi;
    __syncthreads();
    for (int sft = 128; sft > 0; sft >>= 1) {
        if (tid < sft) {
            float ov = vmax[tid + sft]; int oi = vidx[tid + sft];
            if (ov > vmax[tid] || (ov == vmax[tid] && oi < vidx[tid])) {
                vmax[tid] = ov; vidx[tid] = oi;
            }
        }
        __syncthreads();
    }
    const int tok = vidx[0];
    for (int i = tid; i < EE; i += 256) g_x[b * EE + i] = emb[(size_t)tok * EE + i];
}

// ---------------- host launcher ----------------
extern "C" void kernel_launch(void* const* d_in, const int* in_sizes, int n_in,
                              void* d_out, int out_size)
{
    int ci = 0;
    const float* latent    = (const float*)d_in[ci++];
    const int*   style     = (const int*)  d_in[ci++];
    const float* enc       = (const float*)d_in[ci++];
    if (ci < n_in && in_sizes[ci] == 1) ci++;           // skip max_length scalar if present
    const float* emb       = (const float*)d_in[ci++];
    const float* style_emb = (const float*)d_in[ci++];
    const float* W_l2h     = (const float*)d_in[ci++];
    const float* b_l2h     = (const float*)d_in[ci++];
    const float* W_ih      = (const float*)d_in[ci++];
    const float* W_hh      = (const float*)d_in[ci++];
    const float* b_ih      = (const float*)d_in[ci++];
    const float* b_hh      = (const float*)d_in[ci++];
    const float* W_a       = (const float*)d_in[ci++];
    const float* W_out     = (const float*)d_in[ci++];
    const float* b_out     = (const float*)d_in[ci++];
    float* out = (float*)d_out;

    const int TD = out_size / (BB * VV);                // decode length (32)

    float *pWihT, *pWhhT, *pWaT, *pencwa;
    cudaGetSymbolAddress((void**)&pWihT, g_WihT);
    cudaGetSymbolAddress((void**)&pWhhT, g_WhhT);
    cudaGetSymbolAddress((void**)&pWaT,  g_WaT);
    cudaGetSymbolAddress((void**)&pencwa, g_encwa);

    cudaFuncSetAttribute(logits_mma, cudaFuncAttributeMaxDynamicSharedMemorySize,
                         LOGITS_SMEM);

    // one-time per-launch prep
    transpose_kernel<<<(G3 * EE + 255) / 256, 256>>>(W_ih, pWihT, G3, EE);
    transpose_kernel<<<(G3 * HH + 255) / 256, 256>>>(W_hh, pWhhT, G3, HH);
    transpose_kernel<<<(HH * HH + 255) / 256, 256>>>(W_a,  pWaT,  HH, HH);
    wout_split<<<dim3(VV / 32, XCK / 32), dim3(32, 8)>>>(W_out);
    init_kernel<<<BB, 256>>>(latent, style, style_emb, W_l2h, b_l2h, emb);

    // enc_wa[b,t,k] = sum_h enc[b,t,h] * W_a[k,h]   (M=4096,N=1024,K=1024)
    {
        dim3 g(HH / BN, (BB * TENC) / BM);
        sgemm_nn<<<g, 256>>>(enc, HH, pWaT, HH, pencwa, HH, (const float*)0, HH);
    }

    for (int t = 0; t < TD; t++) {
        gru_gates<<<dim3(G3 / BN, 16), 256>>>();
        gru_combine<<<(BB * HH) / 256, 256>>>(b_ih, b_hh);
        scores_kernel<<<BB * TENC, 128>>>();
        ctx_kernel<<<dim3(BB, 8), 128>>>(enc);
        aconv_kernel<<<(BB * XCK) / 256, 256>>>();
        logits_mma<<<VV / 128, 256, LOGITS_SMEM>>>(b_out, out, t, TD);
        argmax_embed<<<BB, 256>>>(out, t, TD, emb);
    }
}

// round 5
// speedup vs baseline: 2.1221x; 1.0806x over previous
#include <cuda_runtime.h>
#include <cuda_bf16.h>
#include <math.h>

// Problem constants
#define BB   64
#define TENC 64
#define HH   1024
#define EE   512
#define VV   32000
#define LAT  128
#define STY  64
#define KCAT 192      // LAT + STY
#define G3   3072     // 3*H
#define XCK  2048     // 2*H

// fp32 SGEMM tiling (GRU gates)
#define BM  64
#define BN  128
#define BKD 16

// hi/lo MMA tiling: block = 64m x 128n x 64k chunks, 2-stage cp.async pipeline
#define APAD 72
// per-stage element counts (bf16)
#define SA_ELE (64 * APAD)          // 4608
#define SW_ELE (128 * APAD)         // 9216
#define STAGE_ELE (2 * SA_ELE + 2 * SW_ELE)   // 27648 bf16 = 55296 B
#define MMA_SMEM (2 * STAGE_ELE * 2)          // 110592 bytes

// ---------------- static device scratch (allocation-free) ----------------
__device__ float g_WihT[EE * G3];        // W_ih transposed [E, 3H]
__device__ float g_WhhT[HH * G3];        // W_hh transposed [H, 3H]
__device__ float g_encwa[BB * TENC * HH];// enc @ W_a^T
__device__ float g_h  [BB * HH];         // hidden state
__device__ float g_x  [BB * EE];         // current input embedding
__device__ float g_gpart[16 * BB * G3];  // split-K partials: 0..7 = gi, 8..15 = gh

// bf16 hi/lo splits
__device__ __nv_bfloat16 g_WoutHiT[(size_t)VV * XCK];  // W_out^T [V][K]
__device__ __nv_bfloat16 g_WoutLoT[(size_t)VV * XCK];
__device__ __nv_bfloat16 g_Ahi[BB * XCK];              // activations [h|ctx]
__device__ __nv_bfloat16 g_Alo[BB * XCK];
__device__ __nv_bfloat16 g_EncHi[BB * TENC * HH];      // encoder outputs
__device__ __nv_bfloat16 g_EncLo[BB * TENC * HH];
__device__ __nv_bfloat16 g_WaHi[HH * HH];              // W_a (rows k, cols h)
__device__ __nv_bfloat16 g_WaLo[HH * HH];

// ---------------- fp32 SGEMM (GRU gates) ----------------
struct SmemT {
    float A [2][BKD][BM];
    float Bt[2][BKD][BN];
};

__device__ __forceinline__ void gemm_body(
    const float* __restrict__ A, int lda,
    const float* __restrict__ Bm, int ldb,
    float* __restrict__ C, int ldc, int K, SmemT* s)
{
    const int tid = threadIdx.x;
    const int m0  = (tid >> 4) * 4;
    const int n0  = (tid & 15) * 8;
    const int ar  = tid >> 2;
    const int ac  = (tid & 3) * 4;
    const int br  = tid >> 5;
    const int bc  = (tid & 31) * 4;

    float acc[4][8];
#pragma unroll
    for (int i = 0; i < 4; i++)
#pragma unroll
        for (int j = 0; j < 8; j++) acc[i][j] = 0.f;

    const int nt = K / BKD;

    float4 pa  = *(const float4*)(A  + (size_t)ar * lda + ac);
    float4 pb0 = *(const float4*)(Bm + (size_t)br * ldb + bc);
    float4 pb1 = *(const float4*)(Bm + (size_t)(br + 8) * ldb + bc);
    s->A[0][ac + 0][ar] = pa.x; s->A[0][ac + 1][ar] = pa.y;
    s->A[0][ac + 2][ar] = pa.z; s->A[0][ac + 3][ar] = pa.w;
    *(float4*)&s->Bt[0][br][bc]     = pb0;
    *(float4*)&s->Bt[0][br + 8][bc] = pb1;
    __syncthreads();

    for (int kt = 0; kt < nt; kt++) {
        const int buf = kt & 1;
        if (kt + 1 < nt) {
            const float* Ap = A  + (kt + 1) * BKD;
            const float* Bp = Bm + (size_t)(kt + 1) * BKD * ldb;
            pa  = *(const float4*)(Ap + (size_t)ar * lda + ac);
            pb0 = *(const float4*)(Bp + (size_t)br * ldb + bc);
            pb1 = *(const float4*)(Bp + (size_t)(br + 8) * ldb + bc);
        }
#pragma unroll
        for (int k = 0; k < BKD; k++) {
            float4 av  = *(const float4*)&s->A [buf][k][m0];
            float4 bv0 = *(const float4*)&s->Bt[buf][k][n0];
            float4 bv1 = *(const float4*)&s->Bt[buf][k][n0 + 4];
            float a0 = av.x, a1 = av.y, a2 = av.z, a3 = av.w;
            float b[8] = {bv0.x, bv0.y, bv0.z, bv0.w, bv1.x, bv1.y, bv1.z, bv1.w};
#pragma unroll
            for (int j = 0; j < 8; j++) {
                acc[0][j] += a0 * b[j];
                acc[1][j] += a1 * b[j];
                acc[2][j] += a2 * b[j];
                acc[3][j] += a3 * b[j];
            }
        }
        if (kt + 1 < nt) {
            const int nb = buf ^ 1;
            s->A[nb][ac + 0][ar] = pa.x; s->A[nb][ac + 1][ar] = pa.y;
            s->A[nb][ac + 2][ar] = pa.z; s->A[nb][ac + 3][ar] = pa.w;
            *(float4*)&s->Bt[nb][br][bc]     = pb0;
            *(float4*)&s->Bt[nb][br + 8][bc] = pb1;
        }
        __syncthreads();
    }

#pragma unroll
    for (int i = 0; i < 4; i++) {
        float* Cr = C + (size_t)(m0 + i) * ldc + n0;
        *(float4*)(Cr)     = make_float4(acc[i][0], acc[i][1], acc[i][2], acc[i][3]);
        *(float4*)(Cr + 4) = make_float4(acc[i][4], acc[i][5], acc[i][6], acc[i][7]);
    }
}

// GRU gate GEMMs with split-K=8. grid = (G3/BN = 24, 16).
__global__ __launch_bounds__(256) void gru_gates(void)
{
    __shared__ SmemT s;
    const int z  = blockIdx.y;
    const int nt = blockIdx.x;
    const float *A, *Bm;
    int lda, K;
    if (z < 8) {
        const int k0 = z * (EE / 8);
        A = g_x + k0; lda = EE; K = EE / 8;
        Bm = g_WihT + (size_t)k0 * G3 + nt * BN;
    } else {
        const int k0 = (z - 8) * (HH / 8);
        A = g_h + k0; lda = HH; K = HH / 8;
        Bm = g_WhhT + (size_t)k0 * G3 + nt * BN;
    }
    float* C = g_gpart + (size_t)z * BB * G3 + nt * BN;
    gemm_body(A, lda, Bm, G3, C, G3, K, &s);
}

// ---------------- hi/lo bf16 MMA with cp.async pipeline ----------------

__device__ __forceinline__ void mma16816(float* c, const unsigned* a, const unsigned* b)
{
    asm volatile(
        "mma.sync.aligned.m16n8k16.row.col.f32.bf16.bf16.f32 "
        "{%0,%1,%2,%3}, {%4,%5,%6,%7}, {%8,%9}, {%0,%1,%2,%3};\n"
        : "+f"(c[0]), "+f"(c[1]), "+f"(c[2]), "+f"(c[3])
        : "r"(a[0]), "r"(a[1]), "r"(a[2]), "r"(a[3]), "r"(b[0]), "r"(b[1]));
}

__device__ __forceinline__ void cpasync16(void* sdst, const void* gsrc)
{
    unsigned sa = (unsigned)__cvta_generic_to_shared(sdst);
    asm volatile("cp.async.cg.shared.global [%0], [%1], 16;\n" :: "r"(sa), "l"(gsrc));
}

// issue one stage's loads: A 64x64 (hi+lo), W 128x64 (hi+lo)
__device__ __forceinline__ void load_stage(
    __nv_bfloat16* sAhi, __nv_bfloat16* sAlo,
    __nv_bfloat16* sWhi, __nv_bfloat16* sWlo,
    const __nv_bfloat16* __restrict__ Ahi, const __nv_bfloat16* __restrict__ Alo, int lda,
    const __nv_bfloat16* __restrict__ Whi, const __nv_bfloat16* __restrict__ Wlo, int ldw,
    int k0, int tid)
{
#pragma unroll
    for (int i = 0; i < 2; i++) {
        int c = tid + i * 256;
        int r = c >> 3, cc = (c & 7) * 8;
        cpasync16(&sAhi[r * APAD + cc], &Ahi[(size_t)r * lda + k0 + cc]);
        cpasync16(&sAlo[r * APAD + cc], &Alo[(size_t)r * lda + k0 + cc]);
    }
#pragma unroll
    for (int i = 0; i < 4; i++) {
        int c = tid + i * 256;
        int r = c >> 3, cc = (c & 7) * 8;
        cpasync16(&sWhi[r * APAD + cc], &Whi[(size_t)r * ldw + k0 + cc]);
        cpasync16(&sWlo[r * APAD + cc], &Wlo[(size_t)r * ldw + k0 + cc]);
    }
    asm volatile("cp.async.commit_group;\n");
}

__device__ __forceinline__ void compute_stage(
    const __nv_bfloat16* sAhi, const __nv_bfloat16* sAlo,
    const __nv_bfloat16* sWhi, const __nv_bfloat16* sWlo,
    int warp, int lane, float acc[4][2][4])
{
    const int g = lane >> 2, tg = lane & 3;
#pragma unroll
    for (int kf = 0; kf < 4; kf++) {
        const int kb = kf * 16 + tg * 2;
        unsigned bhi[2][2], blo[2][2];
#pragma unroll
        for (int nf = 0; nf < 2; nf++) {
            const int nr = warp * 16 + nf * 8 + g;
            bhi[nf][0] = *(const unsigned*)&sWhi[nr * APAD + kb];
            bhi[nf][1] = *(const unsigned*)&sWhi[nr * APAD + kb + 8];
            blo[nf][0] = *(const unsigned*)&sWlo[nr * APAD + kb];
            blo[nf][1] = *(const unsigned*)&sWlo[nr * APAD + kb + 8];
        }
#pragma unroll
        for (int mt = 0; mt < 4; mt++) {
            const int r0 = mt * 16 + g, r1 = r0 + 8;
            unsigned ahi[4], alo[4];
            ahi[0] = *(const unsigned*)&sAhi[r0 * APAD + kb];
            ahi[1] = *(const unsigned*)&sAhi[r1 * APAD + kb];
            ahi[2] = *(const unsigned*)&sAhi[r0 * APAD + kb + 8];
            ahi[3] = *(const unsigned*)&sAhi[r1 * APAD + kb + 8];
            alo[0] = *(const unsigned*)&sAlo[r0 * APAD + kb];
            alo[1] = *(const unsigned*)&sAlo[r1 * APAD + kb];
            alo[2] = *(const unsigned*)&sAlo[r0 * APAD + kb + 8];
            alo[3] = *(const unsigned*)&sAlo[r1 * APAD + kb + 8];
#pragma unroll
            for (int nf = 0; nf < 2; nf++) {
                mma16816(acc[mt][nf], ahi, bhi[nf]);
                mma16816(acc[mt][nf], alo, bhi[nf]);
                mma16816(acc[mt][nf], ahi, blo[nf]);
            }
        }
    }
}

// pipelined mainloop; smem = extern dynamic; returns acc
__device__ __forceinline__ void mma_mainloop(
    const __nv_bfloat16* Ahi, const __nv_bfloat16* Alo, int lda,
    const __nv_bfloat16* Whi, const __nv_bfloat16* Wlo, int ldw,
    int nchunks, float acc[4][2][4], __nv_bfloat16* sm)
{
    const int tid = threadIdx.x, warp = tid >> 5, lane = tid & 31;
    __nv_bfloat16* st[2];
    st[0] = sm; st[1] = sm + STAGE_ELE;
#define S_AHI(s) (st[s])
#define S_ALO(s) (st[s] + SA_ELE)
#define S_WHI(s) (st[s] + 2 * SA_ELE)
#define S_WLO(s) (st[s] + 2 * SA_ELE + SW_ELE)

#pragma unroll
    for (int mt = 0; mt < 4; mt++)
#pragma unroll
        for (int nf = 0; nf < 2; nf++)
#pragma unroll
            for (int i = 0; i < 4; i++) acc[mt][nf][i] = 0.f;

    load_stage(S_AHI(0), S_ALO(0), S_WHI(0), S_WLO(0),
               Ahi, Alo, lda, Whi, Wlo, ldw, 0, tid);

    for (int kc = 0; kc < nchunks; kc++) {
        const int cur = kc & 1;
        if (kc + 1 < nchunks) {
            const int nxt = cur ^ 1;
            load_stage(S_AHI(nxt), S_ALO(nxt), S_WHI(nxt), S_WLO(nxt),
                       Ahi, Alo, lda, Whi, Wlo, ldw, (kc + 1) * 64, tid);
        } else {
            asm volatile("cp.async.commit_group;\n");   // empty group for in-order drain
        }
        asm volatile("cp.async.wait_group 1;\n");
        __syncthreads();
        compute_stage(S_AHI(cur), S_ALO(cur), S_WHI(cur), S_WLO(cur), warp, lane, acc);
        __syncthreads();
    }
}

// logits: out[b][t][v] = A[b] . WoutT[v] + bias[v].  grid = VV/128 = 250.
__global__ __launch_bounds__(256) void logits_mma(
    const float* __restrict__ bias, float* __restrict__ out, int t, int TD)
{
    extern __shared__ __nv_bfloat16 sm_l[];
    const int n0 = blockIdx.x * 128;
    float acc[4][2][4];
    mma_mainloop(g_Ahi, g_Alo, XCK,
                 g_WoutHiT + (size_t)n0 * XCK, g_WoutLoT + (size_t)n0 * XCK, XCK,
                 XCK / 64, acc, sm_l);

    const int tid = threadIdx.x, warp = tid >> 5, lane = tid & 31;
    const int g = lane >> 2, tg = lane & 3;
#pragma unroll
    for (int mt = 0; mt < 4; mt++) {
#pragma unroll
        for (int nf = 0; nf < 2; nf++) {
            const int n = n0 + warp * 16 + nf * 8 + tg * 2;
            const float b0v = bias[n], b1v = bias[n + 1];
            const int m0r = mt * 16 + g, m1r = m0r + 8;
            *(float2*)&out[((size_t)m0r * TD + t) * VV + n] =
                make_float2(acc[mt][nf][0] + b0v, acc[mt][nf][1] + b1v);
            *(float2*)&out[((size_t)m1r * TD + t) * VV + n] =
                make_float2(acc[mt][nf][2] + b0v, acc[mt][nf][3] + b1v);
        }
    }
}

// enc_wa[m][n] = enc[m] . W_a[n]   (m over B*T, n over H, K = H). grid (8, 64).
__global__ __launch_bounds__(256) void encwa_mma(void)
{
    extern __shared__ __nv_bfloat16 sm_e[];
    const int n0 = blockIdx.x * 128;
    const int m0g = blockIdx.y * 64;
    float acc[4][2][4];
    mma_mainloop(g_EncHi + (size_t)m0g * HH, g_EncLo + (size_t)m0g * HH, HH,
                 g_WaHi + (size_t)n0 * HH, g_WaLo + (size_t)n0 * HH, HH,
                 HH / 64, acc, sm_e);

    const int tid = threadIdx.x, warp = tid >> 5, lane = tid & 31;
    const int g = lane >> 2, tg = lane & 3;
#pragma unroll
    for (int mt = 0; mt < 4; mt++) {
#pragma unroll
        for (int nf = 0; nf < 2; nf++) {
            const int n = n0 + warp * 16 + nf * 8 + tg * 2;
            const int m0r = m0g + mt * 16 + g, m1r = m0r + 8;
            *(float2*)&g_encwa[(size_t)m0r * HH + n] =
                make_float2(acc[mt][nf][0], acc[mt][nf][1]);
            *(float2*)&g_encwa[(size_t)m1r * HH + n] =
                make_float2(acc[mt][nf][2], acc[mt][nf][3]);
        }
    }
}

// ---------------- prep kernels ----------------

__global__ void transpose_kernel(const float* __restrict__ in, float* __restrict__ out,
                                 int rows, int cols)
{
    size_t idx = (size_t)blockIdx.x * blockDim.x + threadIdx.x;
    size_t total = (size_t)rows * cols;
    if (idx < total) {
        size_t oc = idx % rows;
        size_t orow = idx / rows;
        out[idx] = in[oc * cols + orow];
    }
}

// fp32 -> bf16 hi/lo elementwise
__global__ void split_hilo(const float* __restrict__ in,
                           __nv_bfloat16* __restrict__ hi,
                           __nv_bfloat16* __restrict__ lo, int n)
{
    int idx = blockIdx.x * 256 + threadIdx.x;
    if (idx < n) {
        float x = in[idx];
        __nv_bfloat16 h = __float2bfloat16_rn(x);
        hi[idx] = h;
        lo[idx] = __float2bfloat16_rn(x - __bfloat162float(h));
    }
}

// W_out [K=2048][V=32000] fp32 -> hi/lo bf16 transposed [V][K]
__global__ __launch_bounds__(256) void wout_split(const float* __restrict__ W)
{
    __shared__ float tile[32][33];
    const int v0 = blockIdx.x * 32, k0 = blockIdx.y * 32;
    const int tx = threadIdx.x, ty = threadIdx.y;   // block (32, 8)
#pragma unroll
    for (int i = 0; i < 4; i++)
        tile[ty + i * 8][tx] = W[(size_t)(k0 + ty + i * 8) * VV + v0 + tx];
    __syncthreads();
#pragma unroll
    for (int i = 0; i < 4; i++) {
        const int v = v0 + ty + i * 8;
        const int k = k0 + tx;
        float w = tile[tx][ty + i * 8];
        __nv_bfloat16 hi = __float2bfloat16_rn(w);
        __nv_bfloat16 lo = __float2bfloat16_rn(w - __bfloat162float(hi));
        g_WoutHiT[(size_t)v * XCK + k] = hi;
        g_WoutLoT[(size_t)v * XCK + k] = lo;
    }
}

// h0 init + BOS embed. grid (4 j-groups, 8 b-groups), 256 threads.
__global__ __launch_bounds__(256) void init_kernel(
    const float* __restrict__ latent, const int* __restrict__ style,
    const float* __restrict__ style_emb, const float* __restrict__ W_l2h,
    const float* __restrict__ b_l2h, const float* __restrict__ emb)
{
    __shared__ float cat[8][KCAT];
    const int bg = blockIdx.y, tid = threadIdx.x;
    const int j = blockIdx.x * 256 + tid;
    for (int idx = tid; idx < 8 * KCAT; idx += 256) {
        int bb = idx / KCAT, k = idx % KCAT;
        int b = bg * 8 + bb;
        cat[bb][k] = (k < LAT) ? latent[b * LAT + k]
                               : style_emb[style[b] * STY + (k - LAT)];
    }
    __syncthreads();
    float acc[8];
    const float bj = b_l2h[j];
#pragma unroll
    for (int bb = 0; bb < 8; bb++) acc[bb] = bj;
    for (int k = 0; k < KCAT; k++) {
        float w = W_l2h[(size_t)k * HH + j];
#pragma unroll
        for (int bb = 0; bb < 8; bb++) acc[bb] += cat[bb][k] * w;
    }
#pragma unroll
    for (int bb = 0; bb < 8; bb++) g_h[(bg * 8 + bb) * HH + j] = acc[bb];

    if (blockIdx.x == 0) {
        for (int idx = tid; idx < 8 * EE; idx += 256) {
            int bb = idx / EE, i = idx % EE;
            g_x[(bg * 8 + bb) * EE + i] = emb[EE + i];   // BOS token = 1
        }
    }
}

// ---------------- fused per-step middle kernel ----------------
// combine split-K GRU partials -> h_new; attention scores+softmax+ctx; bf16 split.
// grid = BB blocks, 256 threads.
__global__ __launch_bounds__(256) void step_mid(
    const float* __restrict__ b_ih, const float* __restrict__ b_hh,
    const float* __restrict__ enc)
{
    __shared__ float hs[HH];
    __shared__ float at[TENC];
    __shared__ float red_unused;   // keep compiler happy if needed
    (void)red_unused;
    const int b = blockIdx.x, tid = threadIdx.x;

    // Phase 1: GRU combine for this batch row
    for (int j = tid; j < HH; j += 256) {
        float ir = b_ih[j], iz = b_ih[HH + j], inn = b_ih[2 * HH + j];
        float hr = b_hh[j], hz = b_hh[HH + j], hn  = b_hh[2 * HH + j];
#pragma unroll
        for (int sp = 0; sp < 8; sp++) {
            const float* P = g_gpart + (size_t)sp * BB * G3 + (size_t)b * G3;
            ir += P[j]; iz += P[HH + j]; inn += P[2 * HH + j];
        }
#pragma unroll
        for (int sp = 8; sp < 16; sp++) {
            const float* P = g_gpart + (size_t)sp * BB * G3 + (size_t)b * G3;
            hr += P[j]; hz += P[HH + j]; hn += P[2 * HH + j];
        }
        float r  = 1.f / (1.f + expf(-(ir + hr)));
        float zz = 1.f / (1.f + expf(-(iz + hz)));
        float n  = tanhf(inn + r * hn);
        float hold = g_h[b * HH + j];
        float hnew = (1.f - zz) * n + zz * hold;
        hs[j] = hnew;
        g_h[b * HH + j] = hnew;
        __nv_bfloat16 hi = __float2bfloat16_rn(hnew);
        g_Ahi[(size_t)b * XCK + j] = hi;
        g_Alo[(size_t)b * XCK + j] = __float2bfloat16_rn(hnew - __bfloat162float(hi));
    }
    __syncthreads();

    // Phase 2: scores[t] = hs . enc_wa[b][t]  (4 threads per t)
    {
        const int t  = tid >> 2;
        const int l4 = tid & 3;
        const float* ew = g_encwa + ((size_t)b * TENC + t) * HH;
        float p = 0.f;
        for (int k = l4; k < HH; k += 4) p += hs[k] * ew[k];
        p += __shfl_down_sync(0xffffffffu, p, 1);
        p += __shfl_down_sync(0xffffffffu, p, 2);
        if (l4 == 0) at[t] = p;
    }
    __syncthreads();

    // softmax (single thread, 64 elems)
    if (tid == 0) {
        float m = at[0];
        for (int i = 1; i < TENC; i++) m = fmaxf(m, at[i]);
        float ssum = 0.f;
        for (int i = 0; i < TENC; i++) { float e2 = expf(at[i] - m); at[i] = e2; ssum += e2; }
        float inv = 1.f / ssum;
        for (int i = 0; i < TENC; i++) at[i] *= inv;
    }
    __syncthreads();

    // Phase 3: ctx[j] = sum_t attn[t] * enc[b][t][j]; write hi/lo upper half
    for (int j = tid; j < HH; j += 256) {
        float c = 0.f;
        const float* eb = enc + (size_t)b * TENC * HH + j;
#pragma unroll 8
        for (int t2 = 0; t2 < TENC; t2++) c += at[t2] * eb[(size_t)t2 * HH];
        __nv_bfloat16 hi = __float2bfloat16_rn(c);
        g_Ahi[(size_t)b * XCK + HH + j] = hi;
        g_Alo[(size_t)b * XCK + HH + j] = __float2bfloat16_rn(c - __bfloat162float(hi));
    }
}

// Greedy argmax over V (first-index tiebreak) + embedding gather.
__global__ __launch_bounds__(256) void argmax_embed(
    const float* __restrict__ out_base, int t, int TD, const float* __restrict__ emb)
{
    __shared__ float vmax[256];
    __shared__ int   vidx[256];
    const int b = blockIdx.x, tid = threadIdx.x;
    const float* row = out_base + (size_t)b * TD * VV + (size_t)t * VV;
    float bm = -3.402823466e38f; int bi = 0;
    for (int v = tid; v < VV; v += 256) {
        float val = row[v];
        if (val > bm) { bm = val; bi = v; }
    }
    vmax[tid] = bm; vidx[tid] = bi;
    __syncthreads();
    for (int sft = 128; sft > 0; sft >>= 1) {
        if (tid < sft) {
            float ov = vmax[tid + sft]; int oi = vidx[tid + sft];
            if (ov > vmax[tid] || (ov == vmax[tid] && oi < vidx[tid])) {
                vmax[tid] = ov; vidx[tid] = oi;
            }
        }
        __syncthreads();
    }
    const int tok = vidx[0];
    for (int i = tid; i < EE; i += 256) g_x[b * EE + i] = emb[(size_t)tok * EE + i];
}

// ---------------- host launcher ----------------
extern "C" void kernel_launch(void* const* d_in, const int* in_sizes, int n_in,
                              void* d_out, int out_size)
{
    int ci = 0;
    const float* latent    = (const float*)d_in[ci++];
    const int*   style     = (const int*)  d_in[ci++];
    const float* enc       = (const float*)d_in[ci++];
    if (ci < n_in && in_sizes[ci] == 1) ci++;           // skip max_length scalar if present
    const float* emb       = (const float*)d_in[ci++];
    const float* style_emb = (const float*)d_in[ci++];
    const float* W_l2h     = (const float*)d_in[ci++];
    const float* b_l2h     = (const float*)d_in[ci++];
    const float* W_ih      = (const float*)d_in[ci++];
    const float* W_hh      = (const float*)d_in[ci++];
    const float* b_ih      = (const float*)d_in[ci++];
    const float* b_hh      = (const float*)d_in[ci++];
    const float* W_a       = (const float*)d_in[ci++];
    const float* W_out     = (const float*)d_in[ci++];
    const float* b_out     = (const float*)d_in[ci++];
    float* out = (float*)d_out;

    const int TD = out_size / (BB * VV);                // decode length (32)

    float *pWihT, *pWhhT;
    __nv_bfloat16 *pEncHi, *pEncLo, *pWaHi, *pWaLo;
    cudaGetSymbolAddress((void**)&pWihT, g_WihT);
    cudaGetSymbolAddress((void**)&pWhhT, g_WhhT);
    cudaGetSymbolAddress((void**)&pEncHi, g_EncHi);
    cudaGetSymbolAddress((void**)&pEncLo, g_EncLo);
    cudaGetSymbolAddress((void**)&pWaHi, g_WaHi);
    cudaGetSymbolAddress((void**)&pWaLo, g_WaLo);

    cudaFuncSetAttribute(logits_mma, cudaFuncAttributeMaxDynamicSharedMemorySize,
                         MMA_SMEM);
    cudaFuncSetAttribute(encwa_mma, cudaFuncAttributeMaxDynamicSharedMemorySize,
                         MMA_SMEM);

    // one-time per-launch prep
    transpose_kernel<<<(G3 * EE + 255) / 256, 256>>>(W_ih, pWihT, G3, EE);
    transpose_kernel<<<(G3 * HH + 255) / 256, 256>>>(W_hh, pWhhT, G3, HH);
    wout_split<<<dim3(VV / 32, XCK / 32), dim3(32, 8)>>>(W_out);
    split_hilo<<<(BB * TENC * HH + 255) / 256, 256>>>(enc, pEncHi, pEncLo, BB * TENC * HH);
    split_hilo<<<(HH * HH + 255) / 256, 256>>>(W_a, pWaHi, pWaLo, HH * HH);
    init_kernel<<<dim3(4, 8), 256>>>(latent, style, style_emb, W_l2h, b_l2h, emb);
    encwa_mma<<<dim3(HH / 128, (BB * TENC) / 64), 256, MMA_SMEM>>>();

    for (int t = 0; t < TD; t++) {
        gru_gates<<<dim3(G3 / BN, 16), 256>>>();
        step_mid<<<BB, 256>>>(b_ih, b_hh, enc);
        logits_mma<<<VV / 128, 256, MMA_SMEM>>>(b_out, out, t, TD);
        argmax_embed<<<BB, 256>>>(out, t, TD, emb);
    }
}

// round 7
// speedup vs baseline: 2.8567x; 1.3461x over previous
#include <cuda_runtime.h>
#include <cuda_bf16.h>
#include <math.h>
#include <float.h>

// Problem constants
#define BB   64
#define TENC 64
#define HH   1024
#define EE   512
#define VV   32000
#define LAT  128
#define STY  64
#define KCAT 192      // LAT + STY
#define G3   3072     // 3*H
#define XCK  2048     // 2*H
#define NBLK (VV / 256)   // 125 logits blocks

#define APAD 72

typedef __nv_bfloat16 bf;

// ---------------- static device scratch (allocation-free) ----------------
__device__ __align__(256) float g_encwaT[BB * HH * TENC]; // enc@Wa^T transposed [b][k][t]
__device__ __align__(256) float g_h  [BB * HH];           // hidden state fp32
__device__ __align__(256) float g_gi [BB * G3];           // x @ W_ih^T
__device__ __align__(256) float g_gh [BB * G3];           // h @ W_hh^T
__device__ __align__(256) float g_pval[NBLK * BB];        // per-block argmax partial vals
__device__ __align__(256) int   g_pidx[NBLK * BB];        // per-block argmax partial idx

// bf16 hi/lo splits
__device__ __align__(256) bf g_WoutHiT[(size_t)VV * XCK]; // W_out^T [V][K]
__device__ __align__(256) bf g_WoutLoT[(size_t)VV * XCK];
__device__ __align__(256) bf g_Ahi[BB * XCK];             // logits A: [h|ctx]
__device__ __align__(256) bf g_Alo[BB * XCK];
__device__ __align__(256) bf g_XEhi[BB * EE];             // gates A (x part)
__device__ __align__(256) bf g_XElo[BB * EE];
__device__ __align__(256) bf g_XHhi[BB * HH];             // gates A (h part)
__device__ __align__(256) bf g_XHlo[BB * HH];
__device__ __align__(256) bf g_EncHi[BB * TENC * HH];     // encoder outputs
__device__ __align__(256) bf g_EncLo[BB * TENC * HH];
__device__ __align__(256) bf g_WaHi[HH * HH];             // W_a [k][h]
__device__ __align__(256) bf g_WaLo[HH * HH];
__device__ __align__(256) bf g_WihHi[G3 * EE];            // W_ih [n][k] (native layout)
__device__ __align__(256) bf g_WihLo[G3 * EE];
__device__ __align__(256) bf g_WhhHi[G3 * HH];            // W_hh [n][k] (native layout)
__device__ __align__(256) bf g_WhhLo[G3 * HH];

// ---------------- hi/lo bf16 MMA machinery ----------------

__device__ __forceinline__ void mma16816(float* c, const unsigned* a, const unsigned* b)
{
    asm volatile(
        "mma.sync.aligned.m16n8k16.row.col.f32.bf16.bf16.f32 "
        "{%0,%1,%2,%3}, {%4,%5,%6,%7}, {%8,%9}, {%0,%1,%2,%3};\n"
        : "+f"(c[0]), "+f"(c[1]), "+f"(c[2]), "+f"(c[3])
        : "r"(a[0]), "r"(a[1]), "r"(a[2]), "r"(a[3]), "r"(b[0]), "r"(b[1]));
}

__device__ __forceinline__ void cpasync16(void* sdst, const void* gsrc)
{
    unsigned sa = (unsigned)__cvta_generic_to_shared(sdst);
    asm volatile("cp.async.cg.shared.global [%0], [%1], 16;\n" :: "r"(sa), "l"(gsrc));
}

// stage layout helpers: [Ahi | Alo | Whi | Wlo], APAD-padded rows of 64 k
template<int NF> struct Cfg {
    static const int BN = 64 * NF;
    static const int SA = 64 * APAD;
    static const int SW = BN * APAD;
    static const int STAGE = 2 * SA + 2 * SW;
    static const int SMEM = 2 * STAGE * 2;     // bytes (2 stages)
};

template<int NF>
__device__ __forceinline__ void load_stage_t(
    bf* st,
    const bf* __restrict__ Ahi, const bf* __restrict__ Alo, int lda,
    const bf* __restrict__ Whi, const bf* __restrict__ Wlo, int ldw,
    int k0, int tid)
{
    bf* sAhi = st;
    bf* sAlo = st + Cfg<NF>::SA;
    bf* sWhi = st + 2 * Cfg<NF>::SA;
    bf* sWlo = st + 2 * Cfg<NF>::SA + Cfg<NF>::SW;
#pragma unroll
    for (int i = 0; i < 2; i++) {                 // A: 64x64, 512 chunks per array
        int c = tid + i * 256;
        int r = c >> 3, cc = (c & 7) * 8;
        cpasync16(&sAhi[r * APAD + cc], &Ahi[(size_t)r * lda + k0 + cc]);
        cpasync16(&sAlo[r * APAD + cc], &Alo[(size_t)r * lda + k0 + cc]);
    }
#pragma unroll
    for (int i = 0; i < 2 * NF; i++) {            // W: BNx64
        int c = tid + i * 256;
        int r = c >> 3, cc = (c & 7) * 8;
        cpasync16(&sWhi[r * APAD + cc], &Whi[(size_t)r * ldw + k0 + cc]);
        cpasync16(&sWlo[r * APAD + cc], &Wlo[(size_t)r * ldw + k0 + cc]);
    }
    asm volatile("cp.async.commit_group;\n");
}

template<int NF>
__device__ __forceinline__ void compute_stage_t(
    const bf* st, int warp, int lane, float acc[4][NF][4])
{
    const bf* sAhi = st;
    const bf* sAlo = st + Cfg<NF>::SA;
    const bf* sWhi = st + 2 * Cfg<NF>::SA;
    const bf* sWlo = st + 2 * Cfg<NF>::SA + Cfg<NF>::SW;
    const int g = lane >> 2, tg = lane & 3;
#pragma unroll
    for (int kf = 0; kf < 4; kf++) {
        const int kb = kf * 16 + tg * 2;
        unsigned bhi[NF][2], blo[NF][2];
#pragma unroll
        for (int nf = 0; nf < NF; nf++) {
            const int nr = warp * (8 * NF) + nf * 8 + g;
            bhi[nf][0] = *(const unsigned*)&sWhi[nr * APAD + kb];
            bhi[nf][1] = *(const unsigned*)&sWhi[nr * APAD + kb + 8];
            blo[nf][0] = *(const unsigned*)&sWlo[nr * APAD + kb];
            blo[nf][1] = *(const unsigned*)&sWlo[nr * APAD + kb + 8];
        }
#pragma unroll
        for (int mt = 0; mt < 4; mt++) {
            const int r0 = mt * 16 + g, r1 = r0 + 8;
            unsigned ahi[4], alo[4];
            ahi[0] = *(const unsigned*)&sAhi[r0 * APAD + kb];
            ahi[1] = *(const unsigned*)&sAhi[r1 * APAD + kb];
            ahi[2] = *(const unsigned*)&sAhi[r0 * APAD + kb + 8];
            ahi[3] = *(const unsigned*)&sAhi[r1 * APAD + kb + 8];
            alo[0] = *(const unsigned*)&sAlo[r0 * APAD + kb];
            alo[1] = *(const unsigned*)&sAlo[r1 * APAD + kb];
            alo[2] = *(const unsigned*)&sAlo[r0 * APAD + kb + 8];
            alo[3] = *(const unsigned*)&sAlo[r1 * APAD + kb + 8];
#pragma unroll
            for (int nf = 0; nf < NF; nf++) {
                mma16816(acc[mt][nf], ahi, bhi[nf]);
                mma16816(acc[mt][nf], alo, bhi[nf]);
                mma16816(acc[mt][nf], ahi, blo[nf]);
            }
        }
    }
}

template<int NF>
__device__ __forceinline__ void mainloop_t(
    const bf* Ahi, const bf* Alo, int lda,
    const bf* Whi, const bf* Wlo, int ldw,
    int nchunks, float acc[4][NF][4], bf* sm)
{
    const int tid = threadIdx.x, warp = tid >> 5, lane = tid & 31;
#pragma unroll
    for (int mt = 0; mt < 4; mt++)
#pragma unroll
        for (int nf = 0; nf < NF; nf++)
#pragma unroll
            for (int i = 0; i < 4; i++) acc[mt][nf][i] = 0.f;

    load_stage_t<NF>(sm, Ahi, Alo, lda, Whi, Wlo, ldw, 0, tid);

    for (int kc = 0; kc < nchunks; kc++) {
        bf* cur = sm + (kc & 1) * Cfg<NF>::STAGE;
        if (kc + 1 < nchunks) {
            bf* nxt = sm + ((kc + 1) & 1) * Cfg<NF>::STAGE;
            load_stage_t<NF>(nxt, Ahi, Alo, lda, Whi, Wlo, ldw, (kc + 1) * 64, tid);
        } else {
            asm volatile("cp.async.commit_group;\n");
        }
        asm volatile("cp.async.wait_group 1;\n");
        __syncthreads();
        compute_stage_t<NF>(cur, threadIdx.x >> 5, threadIdx.x & 31, acc);
        __syncthreads();
    }
}

// ---------------- GEMM kernels ----------------

// GRU gates: y==0: gi = x @ W_ih^T (K=512); y==1: gh = h @ W_hh^T (K=1024).
// grid (24, 2), 256 threads, NF=2 (BN=128).
__global__ __launch_bounds__(256) void gates_mma(void)
{
    extern __shared__ bf smg[];
    const int nt = blockIdx.x;
    float acc[4][2][4];
    float* C;
    if (blockIdx.y == 0) {
        mainloop_t<2>(g_XEhi, g_XElo, EE,
                      g_WihHi + (size_t)nt * 128 * EE, g_WihLo + (size_t)nt * 128 * EE, EE,
                      EE / 64, acc, smg);
        C = g_gi;
    } else {
        mainloop_t<2>(g_XHhi, g_XHlo, HH,
                      g_WhhHi + (size_t)nt * 128 * HH, g_WhhLo + (size_t)nt * 128 * HH, HH,
                      HH / 64, acc, smg);
        C = g_gh;
    }
    const int tid = threadIdx.x, warp = tid >> 5, lane = tid & 31;
    const int g = lane >> 2, tg = lane & 3;
#pragma unroll
    for (int mt = 0; mt < 4; mt++) {
#pragma unroll
        for (int nf = 0; nf < 2; nf++) {
            const int n = nt * 128 + warp * 16 + nf * 8 + tg * 2;
            const int m0r = mt * 16 + g, m1r = m0r + 8;
            *(float2*)&C[(size_t)m0r * G3 + n] = make_float2(acc[mt][nf][0], acc[mt][nf][1]);
            *(float2*)&C[(size_t)m1r * G3 + n] = make_float2(acc[mt][nf][2], acc[mt][nf][3]);
        }
    }
}

// enc_wa: A = enc hi/lo [4096][1024], W = W_a hi/lo [1024][1024].
// Epilogue writes TRANSPOSED per batch: g_encwaT[b][k][t]. grid (8, 64), NF=2.
__global__ __launch_bounds__(256) void encwa_mma(void)
{
    extern __shared__ bf sme[];
    const int n0 = blockIdx.x * 128;
    const int m0g = blockIdx.y * 64;     // 64-aligned => single batch b
    float acc[4][2][4];
    mainloop_t<2>(g_EncHi + (size_t)m0g * HH, g_EncLo + (size_t)m0g * HH, HH,
                  g_WaHi + (size_t)n0 * HH, g_WaLo + (size_t)n0 * HH, HH,
                  HH / 64, acc, sme);
    const int tid = threadIdx.x, warp = tid >> 5, lane = tid & 31;
    const int g = lane >> 2, tg = lane & 3;
    const int b = m0g >> 6;
    float* dst = g_encwaT + (size_t)b * HH * TENC;
#pragma unroll
    for (int mt = 0; mt < 4; mt++) {
#pragma unroll
        for (int nf = 0; nf < 2; nf++) {
            const int n = n0 + warp * 16 + nf * 8 + tg * 2;  // k index
            const int t0 = (m0g + mt * 16 + g) & 63, t1 = t0 + 8;
            dst[(size_t)n * TENC + t0]       = acc[mt][nf][0];
            dst[(size_t)(n + 1) * TENC + t0] = acc[mt][nf][1];
            dst[(size_t)n * TENC + t1]       = acc[mt][nf][2];
            dst[(size_t)(n + 1) * TENC + t1] = acc[mt][nf][3];
        }
    }
}

// logits + fused per-block argmax partials. grid = 125, 256 threads, NF=4 (BN=256).
__global__ __launch_bounds__(256) void logits_mma(
    const float* __restrict__ bias, float* __restrict__ out, int t, int TD)
{
    extern __shared__ bf sml[];
    const int n0 = blockIdx.x * 256;
    float acc[4][4][4];
    mainloop_t<4>(g_Ahi, g_Alo, XCK,
                  g_WoutHiT + (size_t)n0 * XCK, g_WoutLoT + (size_t)n0 * XCK, XCK,
                  XCK / 64, acc, sml);

    const int tid = threadIdx.x, warp = tid >> 5, lane = tid & 31;
    const int g = lane >> 2, tg = lane & 3;

    // add bias, write logits, track per-thread row maxima
    float bv[8]; int bix[8];
#pragma unroll
    for (int e = 0; e < 8; e++) { bv[e] = -FLT_MAX; bix[e] = 0; }

#pragma unroll
    for (int mt = 0; mt < 4; mt++) {
#pragma unroll
        for (int nf = 0; nf < 4; nf++) {
            const int n = n0 + warp * 32 + nf * 8 + tg * 2;
            const float b0v = bias[n], b1v = bias[n + 1];
            acc[mt][nf][0] += b0v; acc[mt][nf][1] += b1v;
            acc[mt][nf][2] += b0v; acc[mt][nf][3] += b1v;
            const int m0r = mt * 16 + g, m1r = m0r + 8;
            *(float2*)&out[((size_t)m0r * TD + t) * VV + n] =
                make_float2(acc[mt][nf][0], acc[mt][nf][1]);
            *(float2*)&out[((size_t)m1r * TD + t) * VV + n] =
                make_float2(acc[mt][nf][2], acc[mt][nf][3]);
            // row m0r -> e = mt*2, row m1r -> e = mt*2+1 ; ascending n scan
            if (acc[mt][nf][0] > bv[mt * 2])     { bv[mt * 2] = acc[mt][nf][0];     bix[mt * 2] = n; }
            if (acc[mt][nf][1] > bv[mt * 2])     { bv[mt * 2] = acc[mt][nf][1];     bix[mt * 2] = n + 1; }
            if (acc[mt][nf][2] > bv[mt * 2 + 1]) { bv[mt * 2 + 1] = acc[mt][nf][2]; bix[mt * 2 + 1] = n; }
            if (acc[mt][nf][3] > bv[mt * 2 + 1]) { bv[mt * 2 + 1] = acc[mt][nf][3]; bix[mt * 2 + 1] = n + 1; }
        }
    }
    // reduce across tg (lanes g*4+tg): xor 1, 2 stay within the 4-lane group
#pragma unroll
    for (int off = 1; off <= 2; off <<= 1) {
#pragma unroll
        for (int e = 0; e < 8; e++) {
            float ov = __shfl_xor_sync(0xffffffffu, bv[e], off);
            int   oi = __shfl_xor_sync(0xffffffffu, bix[e], off);
            if (ov > bv[e] || (ov == bv[e] && oi < bix[e])) { bv[e] = ov; bix[e] = oi; }
        }
    }
    // smem reuse (after mainloop's final syncthreads)
    float* sval = (float*)sml;             // [8 warps][64 rows]
    int*   sidx = (int*)(sval + 8 * 64);
    if (tg == 0) {
#pragma unroll
        for (int mt = 0; mt < 4; mt++) {
#pragma unroll
            for (int rr = 0; rr < 2; rr++) {
                const int row = mt * 16 + rr * 8 + g;
                sval[warp * 64 + row] = bv[mt * 2 + rr];
                sidx[warp * 64 + row] = bix[mt * 2 + rr];
            }
        }
    }
    __syncthreads();
    if (tid < 64) {
        float best = sval[tid]; int bi = sidx[tid];
#pragma unroll
        for (int w = 1; w < 8; w++) {
            float ov = sval[w * 64 + tid]; int oi = sidx[w * 64 + tid];
            if (ov > best || (ov == best && oi < bi)) { best = ov; bi = oi; }
        }
        g_pval[blockIdx.x * 64 + tid] = best;
        g_pidx[blockIdx.x * 64 + tid] = bi;
    }
}

// ---------------- prep kernels ----------------

// fp32 -> bf16 hi/lo elementwise
__global__ void split_hilo(const float* __restrict__ in,
                           bf* __restrict__ hi, bf* __restrict__ lo, int n)
{
    int idx = blockIdx.x * 256 + threadIdx.x;
    if (idx < n) {
        float x = in[idx];
        bf h = __float2bfloat16_rn(x);
        hi[idx] = h;
        lo[idx] = __float2bfloat16_rn(x - __bfloat162float(h));
    }
}

// W_out [K=2048][V=32000] fp32 -> hi/lo bf16 transposed [V][K]
__global__ __launch_bounds__(256) void wout_split(const float* __restrict__ W)
{
    __shared__ float tile[32][33];
    const int v0 = blockIdx.x * 32, k0 = blockIdx.y * 32;
    const int tx = threadIdx.x, ty = threadIdx.y;   // block (32, 8)
#pragma unroll
    for (int i = 0; i < 4; i++)
        tile[ty + i * 8][tx] = W[(size_t)(k0 + ty + i * 8) * VV + v0 + tx];
    __syncthreads();
#pragma unroll
    for (int i = 0; i < 4; i++) {
        const int v = v0 + ty + i * 8;
        const int k = k0 + tx;
        float w = tile[tx][ty + i * 8];
        bf hi = __float2bfloat16_rn(w);
        g_WoutHiT[(size_t)v * XCK + k] = hi;
        g_WoutLoT[(size_t)v * XCK + k] = __float2bfloat16_rn(w - __bfloat162float(hi));
    }
}

// h0 init + BOS embed (split). grid (4 j-groups, 8 b-groups), 256 threads.
__global__ __launch_bounds__(256) void init_kernel(
    const float* __restrict__ latent, const int* __restrict__ style,
    const float* __restrict__ style_emb, const float* __restrict__ W_l2h,
    const float* __restrict__ b_l2h, const float* __restrict__ emb)
{
    __shared__ float cat[8][KCAT];
    const int bg = blockIdx.y, tid = threadIdx.x;
    const int j = blockIdx.x * 256 + tid;
    for (int idx = tid; idx < 8 * KCAT; idx += 256) {
        int bb = idx / KCAT, k = idx % KCAT;
        int b = bg * 8 + bb;
        cat[bb][k] = (k < LAT) ? latent[b * LAT + k]
                               : style_emb[style[b] * STY + (k - LAT)];
    }
    __syncthreads();
    float acc[8];
    const float bj = b_l2h[j];
#pragma unroll
    for (int bb = 0; bb < 8; bb++) acc[bb] = bj;
    for (int k = 0; k < KCAT; k++) {
        float w = W_l2h[(size_t)k * HH + j];
#pragma unroll
        for (int bb = 0; bb < 8; bb++) acc[bb] += cat[bb][k] * w;
    }
#pragma unroll
    for (int bb = 0; bb < 8; bb++) {
        const int b = bg * 8 + bb;
        g_h[b * HH + j] = acc[bb];
        bf hi = __float2bfloat16_rn(acc[bb]);
        g_XHhi[b * HH + j] = hi;
        g_XHlo[b * HH + j] = __float2bfloat16_rn(acc[bb] - __bfloat162float(hi));
    }
    if (blockIdx.x == 0) {
        for (int idx = tid; idx < 8 * EE; idx += 256) {
            int bb = idx / EE, i = idx % EE;
            float x = emb[EE + i];                 // BOS token = 1
            bf hi = __float2bfloat16_rn(x);
            g_XEhi[(bg * 8 + bb) * EE + i] = hi;
            g_XElo[(bg * 8 + bb) * EE + i] = __float2bfloat16_rn(x - __bfloat162float(hi));
        }
    }
}

// ---------------- fused per-step middle kernel ----------------
// GRU combine -> h_new; attention scores (coalesced via encwaT) + softmax + ctx.
// grid = BB blocks, 512 threads.
__global__ __launch_bounds__(512) void step_mid(
    const float* __restrict__ b_ih, const float* __restrict__ b_hh,
    const float* __restrict__ enc)
{
    __shared__ float hs[HH];
    __shared__ float at[TENC];
    __shared__ float part[8][TENC];
    const int b = blockIdx.x, tid = threadIdx.x;

    // Phase 1: GRU combine
#pragma unroll
    for (int j = tid; j < HH; j += 512) {
        float ir = g_gi[(size_t)b * G3 + j]            + b_ih[j];
        float iz = g_gi[(size_t)b * G3 + HH + j]       + b_ih[HH + j];
        float inn = g_gi[(size_t)b * G3 + 2 * HH + j]  + b_ih[2 * HH + j];
        float hr = g_gh[(size_t)b * G3 + j]            + b_hh[j];
        float hz = g_gh[(size_t)b * G3 + HH + j]       + b_hh[HH + j];
        float hn = g_gh[(size_t)b * G3 + 2 * HH + j]   + b_hh[2 * HH + j];
        float r  = 1.f / (1.f + expf(-(ir + hr)));
        float zz = 1.f / (1.f + expf(-(iz + hz)));
        float n  = tanhf(inn + r * hn);
        float hnew = (1.f - zz) * n + zz * g_h[b * HH + j];
        hs[j] = hnew;
        g_h[b * HH + j] = hnew;
        bf hi = __float2bfloat16_rn(hnew);
        bf lo = __float2bfloat16_rn(hnew - __bfloat162float(hi));
        g_XHhi[b * HH + j] = hi;             g_XHlo[b * HH + j] = lo;
        g_Ahi[(size_t)b * XCK + j] = hi;     g_Alo[(size_t)b * XCK + j] = lo;
    }
    __syncthreads();

    // Phase 2: scores[t] = sum_k hs[k] * encwaT[b][k][t]  (coalesced over t)
    {
        const int t = tid & 63, sl = tid >> 6;       // 8 k-slices of 128
        const float* ew = g_encwaT + (size_t)b * HH * TENC;
        float p = 0.f;
        const int kend = sl * 128 + 128;
#pragma unroll 4
        for (int k = sl * 128; k < kend; k++) p += hs[k] * ew[(size_t)k * TENC + t];
        part[sl][t] = p;
    }
    __syncthreads();
    if (tid < 64) {
        float s = 0.f;
#pragma unroll
        for (int sl = 0; sl < 8; sl++) s += part[sl][tid];
        at[tid] = s;
    }
    __syncthreads();
    if (tid == 0) {
        float m = at[0];
        for (int i = 1; i < TENC; i++) m = fmaxf(m, at[i]);
        float ssum = 0.f;
        for (int i = 0; i < TENC; i++) { float e2 = expf(at[i] - m); at[i] = e2; ssum += e2; }
        float inv = 1.f / ssum;
        for (int i = 0; i < TENC; i++) at[i] *= inv;
    }
    __syncthreads();

    // Phase 3: ctx[j] = sum_t attn[t] * enc[b][t][j]
#pragma unroll
    for (int j = tid; j < HH; j += 512) {
        float c = 0.f;
        const float* eb = enc + (size_t)b * TENC * HH + j;
#pragma unroll 8
        for (int t2 = 0; t2 < TENC; t2++) c += at[t2] * eb[(size_t)t2 * HH];
        bf hi = __float2bfloat16_rn(c);
        g_Ahi[(size_t)b * XCK + HH + j] = hi;
        g_Alo[(size_t)b * XCK + HH + j] = __float2bfloat16_rn(c - __bfloat162float(hi));
    }
}

// Final argmax reduce over NBLK partials + embedding gather (split inline).
// grid = BB, 128 threads.
__global__ __launch_bounds__(128) void argmax_final(const float* __restrict__ emb)
{
    __shared__ float sv[128];
    __shared__ int   si[128];
    const int b = blockIdx.x, tid = threadIdx.x;
    float best = -FLT_MAX; int bi = 0x7fffffff;
    if (tid < NBLK) { best = g_pval[tid * 64 + b]; bi = g_pidx[tid * 64 + b]; }
    sv[tid] = best; si[tid] = bi;
    __syncthreads();
    for (int sft = 64; sft > 0; sft >>= 1) {
        if (tid < sft) {
            float ov = sv[tid + sft]; int oi = si[tid + sft];
            if (ov > sv[tid] || (ov == sv[tid] && oi < si[tid])) { sv[tid] = ov; si[tid] = oi; }
        }
        __syncthreads();
    }
    const int tok = si[0];
    for (int e = tid; e < EE; e += 128) {
        float x = emb[(size_t)tok * EE + e];
        bf hi = __float2bfloat16_rn(x);
        g_XEhi[b * EE + e] = hi;
        g_XElo[b * EE + e] = __float2bfloat16_rn(x - __bfloat162float(hi));
    }
}

// ---------------- host launcher ----------------
extern "C" void kernel_launch(void* const* d_in, const int* in_sizes, int n_in,
                              void* d_out, int out_size)
{
    int ci = 0;
    const float* latent    = (const float*)d_in[ci++];
    const int*   style     = (const int*)  d_in[ci++];
    const float* enc       = (const float*)d_in[ci++];
    if (ci < n_in && in_sizes[ci] == 1) ci++;           // skip max_length scalar if present
    const float* emb       = (const float*)d_in[ci++];
    const float* style_emb = (const float*)d_in[ci++];
    const float* W_l2h     = (const float*)d_in[ci++];
    const float* b_l2h     = (const float*)d_in[ci++];
    const float* W_ih      = (const float*)d_in[ci++];
    const float* W_hh      = (const float*)d_in[ci++];
    const float* b_ih      = (const float*)d_in[ci++];
    const float* b_hh      = (const float*)d_in[ci++];
    const float* W_a       = (const float*)d_in[ci++];
    const float* W_out     = (const float*)d_in[ci++];
    const float* b_out     = (const float*)d_in[ci++];
    float* out = (float*)d_out;

    const int TD = out_size / (BB * VV);                // decode length (32)

    bf *pEncHi, *pEncLo, *pWaHi, *pWaLo, *pWihHi, *pWihLo, *pWhhHi, *pWhhLo;
    cudaGetSymbolAddress((void**)&pEncHi, g_EncHi);
    cudaGetSymbolAddress((void**)&pEncLo, g_EncLo);
    cudaGetSymbolAddress((void**)&pWaHi, g_WaHi);
    cudaGetSymbolAddress((void**)&pWaLo, g_WaLo);
    cudaGetSymbolAddress((void**)&pWihHi, g_WihHi);
    cudaGetSymbolAddress((void**)&pWihLo, g_WihLo);
    cudaGetSymbolAddress((void**)&pWhhHi, g_WhhHi);
    cudaGetSymbolAddress((void**)&pWhhLo, g_WhhLo);

    cudaFuncSetAttribute(logits_mma, cudaFuncAttributeMaxDynamicSharedMemorySize,
                         Cfg<4>::SMEM);
    cudaFuncSetAttribute(gates_mma, cudaFuncAttributeMaxDynamicSharedMemorySize,
                         Cfg<2>::SMEM);
    cudaFuncSetAttribute(encwa_mma, cudaFuncAttributeMaxDynamicSharedMemorySize,
                         Cfg<2>::SMEM);

    // one-time per-launch prep
    wout_split<<<dim3(VV / 32, XCK / 32), dim3(32, 8)>>>(W_out);
    split_hilo<<<(BB * TENC * HH + 255) / 256, 256>>>(enc, pEncHi, pEncLo, BB * TENC * HH);
    split_hilo<<<(HH * HH + 255) / 256, 256>>>(W_a, pWaHi, pWaLo, HH * HH);
    split_hilo<<<(G3 * EE + 255) / 256, 256>>>(W_ih, pWihHi, pWihLo, G3 * EE);
    split_hilo<<<(G3 * HH + 255) / 256, 256>>>(W_hh, pWhhHi, pWhhLo, G3 * HH);
    init_kernel<<<dim3(4, 8), 256>>>(latent, style, style_emb, W_l2h, b_l2h, emb);
    encwa_mma<<<dim3(HH / 128, (BB * TENC) / 64), 256, Cfg<2>::SMEM>>>();

    for (int t = 0; t < TD; t++) {
        gates_mma<<<dim3(G3 / 128, 2), 256, Cfg<2>::SMEM>>>();
        step_mid<<<BB, 512>>>(b_ih, b_hh, enc);
        logits_mma<<<NBLK, 256, Cfg<4>::SMEM>>>(b_out, out, t, TD);
        argmax_final<<<BB, 128>>>(emb);
    }
}

// round 10
// speedup vs baseline: 2.9609x; 1.0365x over previous
#include <cuda_runtime.h>
#include <cuda_bf16.h>
#include <math.h>
#include <float.h>
#include <stdint.h>

// Problem constants
#define BB   64
#define TENC 64
#define HH   1024
#define EE   512
#define VV   32000
#define LAT  128
#define STY  64
#define KCAT 192      // LAT + STY
#define G3   3072     // 3*H
#define XCK  2048     // 2*H
#define NBLK (VV / 256)   // 125 logits blocks

#define APAD 72

typedef __nv_bfloat16 bf;

// ---------------- static device scratch (allocation-free) ----------------
__device__ __align__(256) float g_encwaT[BB * HH * TENC]; // enc@Wa^T transposed [b][k][t]
__device__ __align__(256) float g_h  [BB * HH];           // hidden state fp32
__device__ __align__(256) float g_gi [BB * G3];           // x @ W_ih^T
__device__ __align__(256) float g_gh [BB * G3];           // h @ W_hh^T
__device__ __align__(256) float g_pval[NBLK * BB];        // per-block argmax partial vals
__device__ __align__(256) int   g_pidx[NBLK * BB];        // per-block argmax partial idx

// bf16 hi/lo splits
__device__ __align__(256) bf g_WoutHiT[(size_t)VV * XCK]; // W_out^T [V][K]
__device__ __align__(256) bf g_WoutLoT[(size_t)VV * XCK];
__device__ __align__(256) bf g_Ahi[BB * XCK];             // logits A: [h|ctx]
__device__ __align__(256) bf g_Alo[BB * XCK];
__device__ __align__(256) bf g_XEhi[BB * EE];             // gates A (x part)
__device__ __align__(256) bf g_XElo[BB * EE];
__device__ __align__(256) bf g_XHhi[BB * HH];             // gates A (h part)
__device__ __align__(256) bf g_XHlo[BB * HH];
__device__ __align__(256) bf g_EncHi[BB * TENC * HH];     // encoder outputs
__device__ __align__(256) bf g_EncLo[BB * TENC * HH];
__device__ __align__(256) bf g_WaHi[HH * HH];             // W_a [k][h]
__device__ __align__(256) bf g_WaLo[HH * HH];
__device__ __align__(256) bf g_WihHi[G3 * EE];            // W_ih [n][k] (native layout)
__device__ __align__(256) bf g_WihLo[G3 * EE];
__device__ __align__(256) bf g_WhhHi[G3 * HH];            // W_hh [n][k] (native layout)
__device__ __align__(256) bf g_WhhLo[G3 * HH];

// ---------------- PTX helpers ----------------

__device__ __forceinline__ void mma16816(float* c, const unsigned* a, const unsigned* b)
{
    asm volatile(
        "mma.sync.aligned.m16n8k16.row.col.f32.bf16.bf16.f32 "
        "{%0,%1,%2,%3}, {%4,%5,%6,%7}, {%8,%9}, {%0,%1,%2,%3};\n"
        : "+f"(c[0]), "+f"(c[1]), "+f"(c[2]), "+f"(c[3])
        : "r"(a[0]), "r"(a[1]), "r"(a[2]), "r"(a[3]), "r"(b[0]), "r"(b[1]));
}

__device__ __forceinline__ void cpasync16(void* sdst, const void* gsrc)
{
    unsigned sa = (unsigned)__cvta_generic_to_shared(sdst);
    asm volatile("cp.async.cg.shared.global [%0], [%1], 16;\n" :: "r"(sa), "l"(gsrc));
}

__device__ __forceinline__ void ldsm4(unsigned& r0, unsigned& r1, unsigned& r2, unsigned& r3,
                                      uint32_t saddr)
{
    asm volatile("ldmatrix.sync.aligned.m8n8.x4.shared.b16 {%0,%1,%2,%3}, [%4];"
                 : "=r"(r0), "=r"(r1), "=r"(r2), "=r"(r3) : "r"(saddr));
}

__device__ __forceinline__ uint32_t smem_u32(const void* p)
{
    uint32_t a;
    asm("{ .reg .u64 t; cvta.to.shared.u64 t, %1; cvt.u32.u64 %0, t; }" : "=r"(a) : "l"(p));
    return a;
}

// ---------------- hi/lo bf16 warp-MMA with cp.async pipeline + ldmatrix ----------------

template<int NF> struct Cfg {
    static const int BN = 64 * NF;
    static const int SA = 64 * APAD;            // A stream elems (rows x APAD)
    static const int SW = BN * APAD;            // W stream elems
    static const int STAGE = 2 * SA + 2 * SW;
    static const int SMEM = 2 * STAGE * 2;      // bytes
};

template<int NF>
__device__ __forceinline__ void load_stage_t(
    bf* st,
    const bf* __restrict__ Ahi, const bf* __restrict__ Alo, int lda,
    const bf* __restrict__ Whi, const bf* __restrict__ Wlo, int ldw,
    int k0, int tid)
{
    bf* sAhi = st;
    bf* sAlo = st + Cfg<NF>::SA;
    bf* sWhi = st + 2 * Cfg<NF>::SA;
    bf* sWlo = st + 2 * Cfg<NF>::SA + Cfg<NF>::SW;
#pragma unroll
    for (int i = 0; i < 2; i++) {
        int c = tid + i * 256;
        int r = c >> 3, cc = (c & 7) * 8;
        cpasync16(&sAhi[r * APAD + cc], &Ahi[(size_t)r * lda + k0 + cc]);
        cpasync16(&sAlo[r * APAD + cc], &Alo[(size_t)r * lda + k0 + cc]);
    }
#pragma unroll
    for (int i = 0; i < 2 * NF; i++) {
        int c = tid + i * 256;
        int r = c >> 3, cc = (c & 7) * 8;
        cpasync16(&sWhi[r * APAD + cc], &Whi[(size_t)r * ldw + k0 + cc]);
        cpasync16(&sWlo[r * APAD + cc], &Wlo[(size_t)r * ldw + k0 + cc]);
    }
    asm volatile("cp.async.commit_group;\n");
}

// ldmatrix-based fragment compute over one 64-k stage.
// A fragment lane map (x4, m16k16): laneRow=(l&7)+((l>>3)&1)*8, laneColByte=(l>>4)*16
// B fragment pair lane map (x4, two n8k16): laneRow=(l&7)+(l>>4)*8, laneColByte=((l>>3)&1)*16
template<int NF>
__device__ __forceinline__ void compute_stage_t(
    uint32_t sbase, int warp, int lane, float acc[4][NF][4])
{
    const uint32_t oAlo = Cfg<NF>::SA * 2;
    const uint32_t oWhi = 2 * Cfg<NF>::SA * 2;
    const uint32_t oWlo = (2 * Cfg<NF>::SA + Cfg<NF>::SW) * 2;
    const uint32_t aoff = ((uint32_t)((lane & 7) + ((lane >> 3) & 1) * 8)) * (APAD * 2)
                        + ((uint32_t)(lane >> 4)) * 16;
    const uint32_t boff = ((uint32_t)((lane & 7) + (lane >> 4) * 8)) * (APAD * 2)
                        + ((uint32_t)((lane >> 3) & 1)) * 16;
    const uint32_t wn = (uint32_t)warp * (8 * NF) * (APAD * 2);

#pragma unroll
    for (int kf = 0; kf < 4; kf++) {
        const uint32_t kb = (uint32_t)kf * 32;
        unsigned bhi[NF][2], blo[NF][2];
#pragma unroll
        for (int np = 0; np < NF / 2; np++) {
            const uint32_t ba = sbase + wn + (uint32_t)np * 16 * (APAD * 2) + boff + kb;
            ldsm4(bhi[2 * np][0], bhi[2 * np][1], bhi[2 * np + 1][0], bhi[2 * np + 1][1],
                  ba + oWhi);
            ldsm4(blo[2 * np][0], blo[2 * np][1], blo[2 * np + 1][0], blo[2 * np + 1][1],
                  ba + oWlo);
        }
#pragma unroll
        for (int mt = 0; mt < 4; mt++) {
            const uint32_t aa = sbase + (uint32_t)mt * 16 * (APAD * 2) + aoff + kb;
            unsigned ahi[4], alo[4];
            ldsm4(ahi[0], ahi[1], ahi[2], ahi[3], aa);
            ldsm4(alo[0], alo[1], alo[2], alo[3], aa + oAlo);
#pragma unroll
            for (int nf = 0; nf < NF; nf++) {
                mma16816(acc[mt][nf], ahi, bhi[nf]);
                mma16816(acc[mt][nf], alo, bhi[nf]);
                mma16816(acc[mt][nf], ahi, blo[nf]);
            }
        }
    }
}

template<int NF>
__device__ __forceinline__ void mainloop_t(
    const bf* Ahi, const bf* Alo, int lda,
    const bf* Whi, const bf* Wlo, int ldw,
    int nchunks, float acc[4][NF][4], bf* sm)
{
    const int tid = threadIdx.x, warp = tid >> 5, lane = tid & 31;
    const uint32_t sb = smem_u32(sm);
#pragma unroll
    for (int mt = 0; mt < 4; mt++)
#pragma unroll
        for (int nf = 0; nf < NF; nf++)
#pragma unroll
            for (int i = 0; i < 4; i++) acc[mt][nf][i] = 0.f;

    load_stage_t<NF>(sm, Ahi, Alo, lda, Whi, Wlo, ldw, 0, tid);

    for (int kc = 0; kc < nchunks; kc++) {
        const uint32_t curb = sb + (uint32_t)(kc & 1) * (Cfg<NF>::STAGE * 2);
        if (kc + 1 < nchunks) {
            bf* nxt = sm + ((kc + 1) & 1) * Cfg<NF>::STAGE;
            load_stage_t<NF>(nxt, Ahi, Alo, lda, Whi, Wlo, ldw, (kc + 1) * 64, tid);
        } else {
            asm volatile("cp.async.commit_group;\n");
        }
        asm volatile("cp.async.wait_group 1;\n");
        __syncthreads();
        compute_stage_t<NF>(curb, warp, lane, acc);
        __syncthreads();
    }
}

// ---------------- GEMM kernels ----------------

// GRU gates: y==0: gi = x @ W_ih^T (K=512); y==1: gh = h @ W_hh^T (K=1024).
__global__ __launch_bounds__(256) void gates_mma(void)
{
    extern __shared__ bf smg[];
    const int nt = blockIdx.x;
    float acc[4][2][4];
    float* C;
    if (blockIdx.y == 0) {
        mainloop_t<2>(g_XEhi, g_XElo, EE,
                      g_WihHi + (size_t)nt * 128 * EE, g_WihLo + (size_t)nt * 128 * EE, EE,
                      EE / 64, acc, smg);
        C = g_gi;
    } else {
        mainloop_t<2>(g_XHhi, g_XHlo, HH,
                      g_WhhHi + (size_t)nt * 128 * HH, g_WhhLo + (size_t)nt * 128 * HH, HH,
                      HH / 64, acc, smg);
        C = g_gh;
    }
    const int tid = threadIdx.x, warp = tid >> 5, lane = tid & 31;
    const int g = lane >> 2, tg = lane & 3;
#pragma unroll
    for (int mt = 0; mt < 4; mt++) {
#pragma unroll
        for (int nf = 0; nf < 2; nf++) {
            const int n = nt * 128 + warp * 16 + nf * 8 + tg * 2;
            const int m0r = mt * 16 + g, m1r = m0r + 8;
            *(float2*)&C[(size_t)m0r * G3 + n] = make_float2(acc[mt][nf][0], acc[mt][nf][1]);
            *(float2*)&C[(size_t)m1r * G3 + n] = make_float2(acc[mt][nf][2], acc[mt][nf][3]);
        }
    }
}

// enc_wa with transposed epilogue: g_encwaT[b][k][t]. grid (8, 64), NF=2.
__global__ __launch_bounds__(256) void encwa_mma(void)
{
    extern __shared__ bf sme[];
    const int n0 = blockIdx.x * 128;
    const int m0g = blockIdx.y * 64;
    float acc[4][2][4];
    mainloop_t<2>(g_EncHi + (size_t)m0g * HH, g_EncLo + (size_t)m0g * HH, HH,
                  g_WaHi + (size_t)n0 * HH, g_WaLo + (size_t)n0 * HH, HH,
                  HH / 64, acc, sme);
    const int tid = threadIdx.x, warp = tid >> 5, lane = tid & 31;
    const int g = lane >> 2, tg = lane & 3;
    const int b = m0g >> 6;
    float* dst = g_encwaT + (size_t)b * HH * TENC;
#pragma unroll
    for (int mt = 0; mt < 4; mt++) {
#pragma unroll
        for (int nf = 0; nf < 2; nf++) {
            const int n = n0 + warp * 16 + nf * 8 + tg * 2;
            const int t0 = (m0g + mt * 16 + g) & 63, t1 = t0 + 8;
            dst[(size_t)n * TENC + t0]       = acc[mt][nf][0];
            dst[(size_t)(n + 1) * TENC + t0] = acc[mt][nf][1];
            dst[(size_t)n * TENC + t1]       = acc[mt][nf][2];
            dst[(size_t)(n + 1) * TENC + t1] = acc[mt][nf][3];
        }
    }
}

// logits + fused per-block argmax partials. grid = 125, 256 threads, NF=4 (BN=256).
__global__ __launch_bounds__(256) void logits_mma(
    const float* __restrict__ bias, float* __restrict__ out, int t, int TD)
{
    extern __shared__ bf sml[];
    const int n0 = blockIdx.x * 256;
    float acc[4][4][4];
    mainloop_t<4>(g_Ahi, g_Alo, XCK,
                  g_WoutHiT + (size_t)n0 * XCK, g_WoutLoT + (size_t)n0 * XCK, XCK,
                  XCK / 64, acc, sml);

    const int tid = threadIdx.x, warp = tid >> 5, lane = tid & 31;
    const int g = lane >> 2, tg = lane & 3;

    float bv[8]; int bix[8];
#pragma unroll
    for (int e = 0; e < 8; e++) { bv[e] = -FLT_MAX; bix[e] = 0; }

#pragma unroll
    for (int mt = 0; mt < 4; mt++) {
#pragma unroll
        for (int nf = 0; nf < 4; nf++) {
            const int n = n0 + warp * 32 + nf * 8 + tg * 2;
            const float b0v = bias[n], b1v = bias[n + 1];
            acc[mt][nf][0] += b0v; acc[mt][nf][1] += b1v;
            acc[mt][nf][2] += b0v; acc[mt][nf][3] += b1v;
            const int m0r = mt * 16 + g, m1r = m0r + 8;
            *(float2*)&out[((size_t)m0r * TD + t) * VV + n] =
                make_float2(acc[mt][nf][0], acc[mt][nf][1]);
            *(float2*)&out[((size_t)m1r * TD + t) * VV + n] =
                make_float2(acc[mt][nf][2], acc[mt][nf][3]);
            if (acc[mt][nf][0] > bv[mt * 2])     { bv[mt * 2] = acc[mt][nf][0];     bix[mt * 2] = n; }
            if (acc[mt][nf][1] > bv[mt * 2])     { bv[mt * 2] = acc[mt][nf][1];     bix[mt * 2] = n + 1; }
            if (acc[mt][nf][2] > bv[mt * 2 + 1]) { bv[mt * 2 + 1] = acc[mt][nf][2]; bix[mt * 2 + 1] = n; }
            if (acc[mt][nf][3] > bv[mt * 2 + 1]) { bv[mt * 2 + 1] = acc[mt][nf][3]; bix[mt * 2 + 1] = n + 1; }
        }
    }
#pragma unroll
    for (int off = 1; off <= 2; off <<= 1) {
#pragma unroll
        for (int e = 0; e < 8; e++) {
            float ov = __shfl_xor_sync(0xffffffffu, bv[e], off);
            int   oi = __shfl_xor_sync(0xffffffffu, bix[e], off);
            if (ov > bv[e] || (ov == bv[e] && oi < bix[e])) { bv[e] = ov; bix[e] = oi; }
        }
    }
    float* sval = (float*)sml;             // [8 warps][64 rows]
    int*   sidx = (int*)(sval + 8 * 64);
    if (tg == 0) {
#pragma unroll
        for (int mt = 0; mt < 4; mt++) {
#pragma unroll
            for (int rr = 0; rr < 2; rr++) {
                const int row = mt * 16 + rr * 8 + g;
                sval[warp * 64 + row] = bv[mt * 2 + rr];
                sidx[warp * 64 + row] = bix[mt * 2 + rr];
            }
        }
    }
    __syncthreads();
    if (tid < 64) {
        float best = sval[tid]; int bi = sidx[tid];
#pragma unroll
        for (int w = 1; w < 8; w++) {
            float ov = sval[w * 64 + tid]; int oi = sidx[w * 64 + tid];
            if (ov > best || (ov == best && oi < bi)) { best = ov; bi = oi; }
        }
        g_pval[blockIdx.x * 64 + tid] = best;
        g_pidx[blockIdx.x * 64 + tid] = bi;
    }
}

// ---------------- prep kernels ----------------

__global__ void split_hilo(const float* __restrict__ in,
                           bf* __restrict__ hi, bf* __restrict__ lo, int n)
{
    int idx = blockIdx.x * 256 + threadIdx.x;
    if (idx < n) {
        float x = in[idx];
        bf h = __float2bfloat16_rn(x);
        hi[idx] = h;
        lo[idx] = __float2bfloat16_rn(x - __bfloat162float(h));
    }
}

__global__ __launch_bounds__(256) void wout_split(const float* __restrict__ W)
{
    __shared__ float tile[32][33];
    const int v0 = blockIdx.x * 32, k0 = blockIdx.y * 32;
    const int tx = threadIdx.x, ty = threadIdx.y;
#pragma unroll
    for (int i = 0; i < 4; i++)
        tile[ty + i * 8][tx] = W[(size_t)(k0 + ty + i * 8) * VV + v0 + tx];
    __syncthreads();
#pragma unroll
    for (int i = 0; i < 4; i++) {
        const int v = v0 + ty + i * 8;
        const int k = k0 + tx;
        float w = tile[tx][ty + i * 8];
        bf hi = __float2bfloat16_rn(w);
        g_WoutHiT[(size_t)v * XCK + k] = hi;
        g_WoutLoT[(size_t)v * XCK + k] = __float2bfloat16_rn(w - __bfloat162float(hi));
    }
}

__global__ __launch_bounds__(256) void init_kernel(
    const float* __restrict__ latent, const int* __restrict__ style,
    const float* __restrict__ style_emb, const float* __restrict__ W_l2h,
    const float* __restrict__ b_l2h, const float* __restrict__ emb)
{
    __shared__ float cat[8][KCAT];
    const int bg = blockIdx.y, tid = threadIdx.x;
    const int j = blockIdx.x * 256 + tid;
    for (int idx = tid; idx < 8 * KCAT; idx += 256) {
        int bb = idx / KCAT, k = idx % KCAT;
        int b = bg * 8 + bb;
        cat[bb][k] = (k < LAT) ? latent[b * LAT + k]
                               : style_emb[style[b] * STY + (k - LAT)];
    }
    __syncthreads();
    float acc[8];
    const float bj = b_l2h[j];
#pragma unroll
    for (int bb = 0; bb < 8; bb++) acc[bb] = bj;
    for (int k = 0; k < KCAT; k++) {
        float w = W_l2h[(size_t)k * HH + j];
#pragma unroll
        for (int bb = 0; bb < 8; bb++) acc[bb] += cat[bb][k] * w;
    }
#pragma unroll
    for (int bb = 0; bb < 8; bb++) {
        const int b = bg * 8 + bb;
        g_h[b * HH + j] = acc[bb];
        bf hi = __float2bfloat16_rn(acc[bb]);
        g_XHhi[b * HH + j] = hi;
        g_XHlo[b * HH + j] = __float2bfloat16_rn(acc[bb] - __bfloat162float(hi));
    }
    if (blockIdx.x == 0) {
        for (int idx = tid; idx < 8 * EE; idx += 256) {
            int bb = idx / EE, i = idx % EE;
            float x = emb[EE + i];                 // BOS token = 1
            bf hi = __float2bfloat16_rn(x);
            g_XEhi[(bg * 8 + bb) * EE + i] = hi;
            g_XElo[(bg * 8 + bb) * EE + i] = __float2bfloat16_rn(x - __bfloat162float(hi));
        }
    }
}

// ---------------- fused per-step middle kernel ----------------
__global__ __launch_bounds__(512) void step_mid(
    const float* __restrict__ b_ih, const float* __restrict__ b_hh,
    const float* __restrict__ enc)
{
    __shared__ float hs[HH];
    __shared__ float at[TENC];
    __shared__ float part[8][TENC];
    const int b = blockIdx.x, tid = threadIdx.x;

#pragma unroll
    for (int j = tid; j < HH; j += 512) {
        float ir = g_gi[(size_t)b * G3 + j]            + b_ih[j];
        float iz = g_gi[(size_t)b * G3 + HH + j]       + b_ih[HH + j];
        float inn = g_gi[(size_t)b * G3 + 2 * HH + j]  + b_ih[2 * HH + j];
        float hr = g_gh[(size_t)b * G3 + j]            + b_hh[j];
        float hz = g_gh[(size_t)b * G3 + HH + j]       + b_hh[HH + j];
        float hn = g_gh[(size_t)b * G3 + 2 * HH + j]   + b_hh[2 * HH + j];
        float r  = 1.f / (1.f + expf(-(ir + hr)));
        float zz = 1.f / (1.f + expf(-(iz + hz)));
        float n  = tanhf(inn + r * hn);
        float hnew = (1.f - zz) * n + zz * g_h[b * HH + j];
        hs[j] = hnew;
        g_h[b * HH + j] = hnew;
        bf hi = __float2bfloat16_rn(hnew);
        bf lo = __float2bfloat16_rn(hnew - __bfloat162float(hi));
        g_XHhi[b * HH + j] = hi;             g_XHlo[b * HH + j] = lo;
        g_Ahi[(size_t)b * XCK + j] = hi;     g_Alo[(size_t)b * XCK + j] = lo;
    }
    __syncthreads();

    {
        const int t = tid & 63, sl = tid >> 6;
        const float* ew = g_encwaT + (size_t)b * HH * TENC;
        float p = 0.f;
        const int kend = sl * 128 + 128;
#pragma unroll 4
        for (int k = sl * 128; k < kend; k++) p += hs[k] * ew[(size_t)k * TENC + t];
        part[sl][t] = p;
    }
    __syncthreads();
    if (tid < 64) {
        float s = 0.f;
#pragma unroll
        for (int sl = 0; sl < 8; sl++) s += part[sl][tid];
        at[tid] = s;
    }
    __syncthreads();
    if (tid == 0) {
        float m = at[0];
        for (int i = 1; i < TENC; i++) m = fmaxf(m, at[i]);
        float ssum = 0.f;
        for (int i = 0; i < TENC; i++) { float e2 = expf(at[i] - m); at[i] = e2; ssum += e2; }
        float inv = 1.f / ssum;
        for (int i = 0; i < TENC; i++) at[i] *= inv;
    }
    __syncthreads();

#pragma unroll
    for (int j = tid; j < HH; j += 512) {
        float c = 0.f;
        const float* eb = enc + (size_t)b * TENC * HH + j;
#pragma unroll 8
        for (int t2 = 0; t2 < TENC; t2++) c += at[t2] * eb[(size_t)t2 * HH];
        bf hi = __float2bfloat16_rn(c);
        g_Ahi[(size_t)b * XCK + HH + j] = hi;
        g_Alo[(size_t)b * XCK + HH + j] = __float2bfloat16_rn(c - __bfloat162float(hi));
    }
}

// Final argmax reduce over NBLK partials + embedding gather.
__global__ __launch_bounds__(128) void argmax_final(const float* __restrict__ emb)
{
    __shared__ float sv[128];
    __shared__ int   si[128];
    const int b = blockIdx.x, tid = threadIdx.x;
    float best = -FLT_MAX; int bi = 0x7fffffff;
    if (tid < NBLK) { best = g_pval[tid * 64 + b]; bi = g_pidx[tid * 64 + b]; }
    sv[tid] = best; si[tid] = bi;
    __syncthreads();
    for (int sft = 64; sft > 0; sft >>= 1) {
        if (tid < sft) {
            float ov = sv[tid + sft]; int oi = si[tid + sft];
            if (ov > sv[tid] || (ov == sv[tid] && oi < si[tid])) { sv[tid] = ov; si[tid] = oi; }
        }
        __syncthreads();
    }
    const int tok = si[0];
    for (int e = tid; e < EE; e += 128) {
        float x = emb[(size_t)tok * EE + e];
        bf hi = __float2bfloat16_rn(x);
        g_XEhi[b * EE + e] = hi;
        g_XElo[b * EE + e] = __float2bfloat16_rn(x - __bfloat162float(hi));
    }
}

// ---------------- host launcher ----------------
extern "C" void kernel_launch(void* const* d_in, const int* in_sizes, int n_in,
                              void* d_out, int out_size)
{
    int ci = 0;
    const float* latent    = (const float*)d_in[ci++];
    const int*   style     = (const int*)  d_in[ci++];
    const float* enc       = (const float*)d_in[ci++];
    if (ci < n_in && in_sizes[ci] == 1) ci++;           // skip max_length scalar if present
    const float* emb       = (const float*)d_in[ci++];
    const float* style_emb = (const float*)d_in[ci++];
    const float* W_l2h     = (const float*)d_in[ci++];
    const float* b_l2h     = (const float*)d_in[ci++];
    const float* W_ih      = (const float*)d_in[ci++];
    const float* W_hh      = (const float*)d_in[ci++];
    const float* b_ih      = (const float*)d_in[ci++];
    const float* b_hh      = (const float*)d_in[ci++];
    const float* W_a       = (const float*)d_in[ci++];
    const float* W_out     = (const float*)d_in[ci++];
    const float* b_out     = (const float*)d_in[ci++];
    float* out = (float*)d_out;

    const int TD = out_size / (BB * VV);                // decode length (32)

    bf *pEncHi, *pEncLo, *pWaHi, *pWaLo, *pWihHi, *pWihLo, *pWhhHi, *pWhhLo;
    cudaGetSymbolAddress((void**)&pEncHi, g_EncHi);
    cudaGetSymbolAddress((void**)&pEncLo, g_EncLo);
    cudaGetSymbolAddress((void**)&pWaHi, g_WaHi);
    cudaGetSymbolAddress((void**)&pWaLo, g_WaLo);
    cudaGetSymbolAddress((void**)&pWihHi, g_WihHi);
    cudaGetSymbolAddress((void**)&pWihLo, g_WihLo);
    cudaGetSymbolAddress((void**)&pWhhHi, g_WhhHi);
    cudaGetSymbolAddress((void**)&pWhhLo, g_WhhLo);

    cudaFuncSetAttribute(logits_mma, cudaFuncAttributeMaxDynamicSharedMemorySize,
                         Cfg<4>::SMEM);
    cudaFuncSetAttribute(gates_mma, cudaFuncAttributeMaxDynamicSharedMemorySize,
                         Cfg<2>::SMEM);
    cudaFuncSetAttribute(encwa_mma, cudaFuncAttributeMaxDynamicSharedMemorySize,
                         Cfg<2>::SMEM);

    // one-time per-launch prep
    wout_split<<<dim3(VV / 32, XCK / 32), dim3(32, 8)>>>(W_out);
    split_hilo<<<(BB * TENC * HH + 255) / 256, 256>>>(enc, pEncHi, pEncLo, BB * TENC * HH);
    split_hilo<<<(HH * HH + 255) / 256, 256>>>(W_a, pWaHi, pWaLo, HH * HH);
    split_hilo<<<(G3 * EE + 255) / 256, 256>>>(W_ih, pWihHi, pWihLo, G3 * EE);
    split_hilo<<<(G3 * HH + 255) / 256, 256>>>(W_hh, pWhhHi, pWhhLo, G3 * HH);
    init_kernel<<<dim3(4, 8), 256>>>(latent, style, style_emb, W_l2h, b_l2h, emb);
    encwa_mma<<<dim3(HH / 128, (BB * TENC) / 64), 256, Cfg<2>::SMEM>>>();

    for (int t = 0; t < TD; t++) {
        gates_mma<<<dim3(G3 / 128, 2), 256, Cfg<2>::SMEM>>>();
        step_mid<<<BB, 512>>>(b_ih, b_hh, enc);
        logits_mma<<<NBLK, 256, Cfg<4>::SMEM>>>(b_out, out, t, TD);
        argmax_final<<<BB, 128>>>(emb);
    }
}

// round 11
// speedup vs baseline: 2.9668x; 1.0020x over previous
#include <cuda_runtime.h>
#include <cuda_bf16.h>
#include <math.h>
#include <float.h>
#include <stdint.h>

// Problem constants
#define BB   64
#define TENC 64
#define HH   1024
#define EE   512
#define VV   32000
#define LAT  128
#define STY  64
#define KCAT 192      // LAT + STY
#define G3   3072     // 3*H
#define XCK  2048     // 2*H
#define NBLK (VV / 256)   // 125 logits blocks
#define NSPK 6            // gates split-K partials (2 gi + 4 gh)

#define APAD 72

typedef __nv_bfloat16 bf;

// ---------------- static device scratch (allocation-free) ----------------
__device__ __align__(256) float g_encwaT[BB * HH * TENC]; // enc@Wa^T transposed [b][k][t]
__device__ __align__(256) float g_h  [BB * HH];           // hidden state fp32
__device__ __align__(256) float g_gp [NSPK * BB * G3];    // gates split-K partials
__device__ __align__(256) float g_pval[NBLK * BB];        // per-block argmax partial vals
__device__ __align__(256) int   g_pidx[NBLK * BB];        // per-block argmax partial idx

// bf16 hi/lo splits
__device__ __align__(256) bf g_WoutHiT[(size_t)VV * XCK]; // W_out^T [V][K]
__device__ __align__(256) bf g_WoutLoT[(size_t)VV * XCK];
__device__ __align__(256) bf g_Ahi[BB * XCK];             // logits A: [h|ctx]
__device__ __align__(256) bf g_Alo[BB * XCK];
__device__ __align__(256) bf g_XEhi[BB * EE];             // gates A (x part)
__device__ __align__(256) bf g_XElo[BB * EE];
__device__ __align__(256) bf g_XHhi[BB * HH];             // gates A (h part)
__device__ __align__(256) bf g_XHlo[BB * HH];
__device__ __align__(256) bf g_EncHi[BB * TENC * HH];     // encoder outputs
__device__ __align__(256) bf g_EncLo[BB * TENC * HH];
__device__ __align__(256) bf g_WaHi[HH * HH];             // W_a [k][h]
__device__ __align__(256) bf g_WaLo[HH * HH];
__device__ __align__(256) bf g_WihHi[G3 * EE];            // W_ih [n][k] (native layout)
__device__ __align__(256) bf g_WihLo[G3 * EE];
__device__ __align__(256) bf g_WhhHi[G3 * HH];            // W_hh [n][k] (native layout)
__device__ __align__(256) bf g_WhhLo[G3 * HH];

// ---------------- PTX helpers ----------------

__device__ __forceinline__ void mma16816(float* c, const unsigned* a, const unsigned* b)
{
    asm volatile(
        "mma.sync.aligned.m16n8k16.row.col.f32.bf16.bf16.f32 "
        "{%0,%1,%2,%3}, {%4,%5,%6,%7}, {%8,%9}, {%0,%1,%2,%3};\n"
        : "+f"(c[0]), "+f"(c[1]), "+f"(c[2]), "+f"(c[3])
        : "r"(a[0]), "r"(a[1]), "r"(a[2]), "r"(a[3]), "r"(b[0]), "r"(b[1]));
}

__device__ __forceinline__ void cpasync16(void* sdst, const void* gsrc)
{
    unsigned sa = (unsigned)__cvta_generic_to_shared(sdst);
    asm volatile("cp.async.cg.shared.global [%0], [%1], 16;\n" :: "r"(sa), "l"(gsrc));
}
__device__ __forceinline__ void cpasync16s(unsigned saddr, const void* gsrc)
{
    asm volatile("cp.async.cg.shared.global [%0], [%1], 16;\n" :: "r"(saddr), "l"(gsrc));
}

__device__ __forceinline__ void ldsm4(unsigned& r0, unsigned& r1, unsigned& r2, unsigned& r3,
                                      uint32_t saddr)
{
    asm volatile("ldmatrix.sync.aligned.m8n8.x4.shared.b16 {%0,%1,%2,%3}, [%4];"
                 : "=r"(r0), "=r"(r1), "=r"(r2), "=r"(r3) : "r"(saddr));
}

__device__ __forceinline__ uint32_t smem_u32(const void* p)
{
    uint32_t a;
    asm("{ .reg .u64 t; cvta.to.shared.u64 t, %1; cvt.u32.u64 %0, t; }" : "=r"(a) : "l"(p));
    return a;
}

// ---------------- generic hi/lo warp-MMA path (gates/encwa; k=64, 2-stage) ------

template<int NF> struct Cfg {
    static const int BN = 64 * NF;
    static const int SA = 64 * APAD;
    static const int SW = BN * APAD;
    static const int STAGE = 2 * SA + 2 * SW;
    static const int SMEM = 2 * STAGE * 2;
};

template<int NF>
__device__ __forceinline__ void load_stage_t(
    bf* st,
    const bf* __restrict__ Ahi, const bf* __restrict__ Alo, int lda,
    const bf* __restrict__ Whi, const bf* __restrict__ Wlo, int ldw,
    int k0, int tid)
{
    bf* sAhi = st;
    bf* sAlo = st + Cfg<NF>::SA;
    bf* sWhi = st + 2 * Cfg<NF>::SA;
    bf* sWlo = st + 2 * Cfg<NF>::SA + Cfg<NF>::SW;
#pragma unroll
    for (int i = 0; i < 2; i++) {
        int c = tid + i * 256;
        int r = c >> 3, cc = (c & 7) * 8;
        cpasync16(&sAhi[r * APAD + cc], &Ahi[(size_t)r * lda + k0 + cc]);
        cpasync16(&sAlo[r * APAD + cc], &Alo[(size_t)r * lda + k0 + cc]);
    }
#pragma unroll
    for (int i = 0; i < 2 * NF; i++) {
        int c = tid + i * 256;
        int r = c >> 3, cc = (c & 7) * 8;
        cpasync16(&sWhi[r * APAD + cc], &Whi[(size_t)r * ldw + k0 + cc]);
        cpasync16(&sWlo[r * APAD + cc], &Wlo[(size_t)r * ldw + k0 + cc]);
    }
    asm volatile("cp.async.commit_group;\n");
}

template<int NF>
__device__ __forceinline__ void compute_stage_t(
    uint32_t sbase, int warp, int lane, float acc[4][NF][4])
{
    const uint32_t oAlo = Cfg<NF>::SA * 2;
    const uint32_t oWhi = 2 * Cfg<NF>::SA * 2;
    const uint32_t oWlo = (2 * Cfg<NF>::SA + Cfg<NF>::SW) * 2;
    const uint32_t aoff = ((uint32_t)((lane & 7) + ((lane >> 3) & 1) * 8)) * (APAD * 2)
                        + ((uint32_t)(lane >> 4)) * 16;
    const uint32_t boff = ((uint32_t)((lane & 7) + (lane >> 4) * 8)) * (APAD * 2)
                        + ((uint32_t)((lane >> 3) & 1)) * 16;
    const uint32_t wn = (uint32_t)warp * (8 * NF) * (APAD * 2);

#pragma unroll
    for (int kf = 0; kf < 4; kf++) {
        const uint32_t kb = (uint32_t)kf * 32;
        unsigned bhi[NF][2], blo[NF][2];
#pragma unroll
        for (int np = 0; np < NF / 2; np++) {
            const uint32_t ba = sbase + wn + (uint32_t)np * 16 * (APAD * 2) + boff + kb;
            ldsm4(bhi[2 * np][0], bhi[2 * np][1], bhi[2 * np + 1][0], bhi[2 * np + 1][1],
                  ba + oWhi);
            ldsm4(blo[2 * np][0], blo[2 * np][1], blo[2 * np + 1][0], blo[2 * np + 1][1],
                  ba + oWlo);
        }
#pragma unroll
        for (int mt = 0; mt < 4; mt++) {
            const uint32_t aa = sbase + (uint32_t)mt * 16 * (APAD * 2) + aoff + kb;
            unsigned ahi[4], alo[4];
            ldsm4(ahi[0], ahi[1], ahi[2], ahi[3], aa);
            ldsm4(alo[0], alo[1], alo[2], alo[3], aa + oAlo);
#pragma unroll
            for (int nf = 0; nf < NF; nf++) {
                mma16816(acc[mt][nf], ahi, bhi[nf]);
                mma16816(acc[mt][nf], alo, bhi[nf]);
                mma16816(acc[mt][nf], ahi, blo[nf]);
            }
        }
    }
}

template<int NF>
__device__ __forceinline__ void mainloop_t(
    const bf* Ahi, const bf* Alo, int lda,
    const bf* Whi, const bf* Wlo, int ldw,
    int nchunks, float acc[4][NF][4], bf* sm)
{
    const int tid = threadIdx.x, warp = tid >> 5, lane = tid & 31;
    const uint32_t sb = smem_u32(sm);
#pragma unroll
    for (int mt = 0; mt < 4; mt++)
#pragma unroll
        for (int nf = 0; nf < NF; nf++)
#pragma unroll
            for (int i = 0; i < 4; i++) acc[mt][nf][i] = 0.f;

    load_stage_t<NF>(sm, Ahi, Alo, lda, Whi, Wlo, ldw, 0, tid);

    for (int kc = 0; kc < nchunks; kc++) {
        const uint32_t curb = sb + (uint32_t)(kc & 1) * (Cfg<NF>::STAGE * 2);
        if (kc + 1 < nchunks) {
            bf* nxt = sm + ((kc + 1) & 1) * Cfg<NF>::STAGE;
            load_stage_t<NF>(nxt, Ahi, Alo, lda, Whi, Wlo, ldw, (kc + 1) * 64, tid);
        } else {
            asm volatile("cp.async.commit_group;\n");
        }
        asm volatile("cp.async.wait_group 1;\n");
        __syncthreads();
        compute_stage_t<NF>(curb, warp, lane, acc);
        __syncthreads();
    }
}

// ---------------- GRU gates (split-K=6) ----------------
// grid (24, 6): z 0..1 -> gi (K=256 each, over x/W_ih); z 2..5 -> gh (K=256 each).
__global__ __launch_bounds__(256) void gates_mma(void)
{
    extern __shared__ bf smg[];
    const int nt = blockIdx.x;
    const int z = blockIdx.y;
    float acc[4][2][4];
    if (z < 2) {
        const int k0 = z * 256;
        mainloop_t<2>(g_XEhi + k0, g_XElo + k0, EE,
                      g_WihHi + (size_t)nt * 128 * EE + k0,
                      g_WihLo + (size_t)nt * 128 * EE + k0, EE,
                      4, acc, smg);
    } else {
        const int k0 = (z - 2) * 256;
        mainloop_t<2>(g_XHhi + k0, g_XHlo + k0, HH,
                      g_WhhHi + (size_t)nt * 128 * HH + k0,
                      g_WhhLo + (size_t)nt * 128 * HH + k0, HH,
                      4, acc, smg);
    }
    float* C = g_gp + (size_t)z * BB * G3;
    const int tid = threadIdx.x, warp = tid >> 5, lane = tid & 31;
    const int g = lane >> 2, tg = lane & 3;
#pragma unroll
    for (int mt = 0; mt < 4; mt++) {
#pragma unroll
        for (int nf = 0; nf < 2; nf++) {
            const int n = nt * 128 + warp * 16 + nf * 8 + tg * 2;
            const int m0r = mt * 16 + g, m1r = m0r + 8;
            *(float2*)&C[(size_t)m0r * G3 + n] = make_float2(acc[mt][nf][0], acc[mt][nf][1]);
            *(float2*)&C[(size_t)m1r * G3 + n] = make_float2(acc[mt][nf][2], acc[mt][nf][3]);
        }
    }
}

// enc_wa with transposed epilogue: g_encwaT[b][k][t]. grid (8, 64), NF=2.
__global__ __launch_bounds__(256) void encwa_mma(void)
{
    extern __shared__ bf sme[];
    const int n0 = blockIdx.x * 128;
    const int m0g = blockIdx.y * 64;
    float acc[4][2][4];
    mainloop_t<2>(g_EncHi + (size_t)m0g * HH, g_EncLo + (size_t)m0g * HH, HH,
                  g_WaHi + (size_t)n0 * HH, g_WaLo + (size_t)n0 * HH, HH,
                  HH / 64, acc, sme);
    const int tid = threadIdx.x, warp = tid >> 5, lane = tid & 31;
    const int g = lane >> 2, tg = lane & 3;
    const int b = m0g >> 6;
    float* dst = g_encwaT + (size_t)b * HH * TENC;
#pragma unroll
    for (int mt = 0; mt < 4; mt++) {
#pragma unroll
        for (int nf = 0; nf < 2; nf++) {
            const int n = n0 + warp * 16 + nf * 8 + tg * 2;
            const int t0 = (m0g + mt * 16 + g) & 63, t1 = t0 + 8;
            dst[(size_t)n * TENC + t0]       = acc[mt][nf][0];
            dst[(size_t)(n + 1) * TENC + t0] = acc[mt][nf][1];
            dst[(size_t)n * TENC + t1]       = acc[mt][nf][2];
            dst[(size_t)(n + 1) * TENC + t1] = acc[mt][nf][3];
        }
    }
}

// ---------------- logits: k=32 chunks, 4-stage pipeline, term-major MMAs ----------------
// Stage layout (AP32=40-elem padded rows, 80 B): [Ahi 64x40 | Alo | Whi 256x40 | Wlo]
#define AP32   40
#define SA32   (64 * AP32)               // 2560 elems
#define SW32   (256 * AP32)              // 10240 elems
#define ST32   (2 * SA32 + 2 * SW32)     // 25600 elems = 51200 B
#define LSMEM  (4 * ST32 * 2)            // 204800 B

__device__ __forceinline__ void lg_load(uint32_t sb, int buf, int k0, int n0, int tid)
{
    const uint32_t st = sb + (uint32_t)buf * (ST32 * 2);
    {   // A: 64 rows x 4 chunks per stream; 256 chunks -> 1 per thread per stream
        int r = tid >> 2, c = tid & 3;
        cpasync16s(st + r * 80 + c * 16,            &g_Ahi[(size_t)r * XCK + k0 + c * 8]);
        cpasync16s(st + SA32 * 2 + r * 80 + c * 16, &g_Alo[(size_t)r * XCK + k0 + c * 8]);
    }
#pragma unroll
    for (int i = 0; i < 4; i++) {        // W: 256 rows x 4 chunks per stream
        int idx = tid + i * 256;
        int r = idx >> 2, c = idx & 3;
        uint32_t off = r * 80 + c * 16;
        cpasync16s(st + 2 * SA32 * 2 + off,
                   &g_WoutHiT[(size_t)(n0 + r) * XCK + k0 + c * 8]);
        cpasync16s(st + 2 * SA32 * 2 + SW32 * 2 + off,
                   &g_WoutLoT[(size_t)(n0 + r) * XCK + k0 + c * 8]);
    }
    asm volatile("cp.async.commit_group;\n");
}

__global__ __launch_bounds__(256, 1) void logits_mma(
    const float* __restrict__ bias, float* __restrict__ out, int t, int TD)
{
    extern __shared__ bf sml[];
    const uint32_t sb = smem_u32(sml);
    const int tid = threadIdx.x, warp = tid >> 5, lane = tid & 31;
    const int n0 = blockIdx.x * 256;

    float acc[4][4][4];
#pragma unroll
    for (int mt = 0; mt < 4; mt++)
#pragma unroll
        for (int nf = 0; nf < 4; nf++)
#pragma unroll
            for (int i = 0; i < 4; i++) acc[mt][nf][i] = 0.f;

    lg_load(sb, 0, 0, n0, tid);
    lg_load(sb, 1, 32, n0, tid);
    lg_load(sb, 2, 64, n0, tid);

    const uint32_t aoff = ((uint32_t)((lane & 7) + ((lane >> 3) & 1) * 8)) * 80
                        + ((uint32_t)(lane >> 4)) * 16;
    const uint32_t boff = ((uint32_t)((lane & 7) + (lane >> 4) * 8)) * 80
                        + ((uint32_t)((lane >> 3) & 1)) * 16;
    const uint32_t wn = (uint32_t)warp * 32 * 80;

    for (int c = 0; c < 64; c++) {
        asm volatile("cp.async.wait_group 2;\n");
        __syncthreads();
        const uint32_t base = sb + (uint32_t)(c & 3) * (ST32 * 2);
#pragma unroll
        for (int kf = 0; kf < 2; kf++) {
            const uint32_t kb = (uint32_t)kf * 32;
            unsigned ahi[4][4], alo[4][4], bhi[4][2], blo[4][2];
#pragma unroll
            for (int mt = 0; mt < 4; mt++) {
                const uint32_t aa = base + (uint32_t)mt * 16 * 80 + aoff + kb;
                ldsm4(ahi[mt][0], ahi[mt][1], ahi[mt][2], ahi[mt][3], aa);
                ldsm4(alo[mt][0], alo[mt][1], alo[mt][2], alo[mt][3], aa + SA32 * 2);
            }
#pragma unroll
            for (int np = 0; np < 2; np++) {
                const uint32_t ba = base + 2 * SA32 * 2 + wn
                                  + (uint32_t)np * 16 * 80 + boff + kb;
                ldsm4(bhi[2 * np][0], bhi[2 * np][1], bhi[2 * np + 1][0], bhi[2 * np + 1][1],
                      ba);
                ldsm4(blo[2 * np][0], blo[2 * np][1], blo[2 * np + 1][0], blo[2 * np + 1][1],
                      ba + SW32 * 2);
            }
            // term-major: dependent MMAs on the same acc are 16 apart
#pragma unroll
            for (int mt = 0; mt < 4; mt++)
#pragma unroll
                for (int nf = 0; nf < 4; nf++)
                    mma16816(acc[mt][nf], ahi[mt], bhi[nf]);
#pragma unroll
            for (int mt = 0; mt < 4; mt++)
#pragma unroll
                for (int nf = 0; nf < 4; nf++)
                    mma16816(acc[mt][nf], alo[mt], bhi[nf]);
#pragma unroll
            for (int mt = 0; mt < 4; mt++)
#pragma unroll
                for (int nf = 0; nf < 4; nf++)
                    mma16816(acc[mt][nf], ahi[mt], blo[nf]);
        }
        __syncthreads();
        if (c + 3 < 64) lg_load(sb, (c + 3) & 3, (c + 3) * 32, n0, tid);
        else asm volatile("cp.async.commit_group;\n");
    }

    // epilogue: bias + store + fused per-block argmax partials
    const int g = lane >> 2, tg = lane & 3;
    float bv[8]; int bix[8];
#pragma unroll
    for (int e = 0; e < 8; e++) { bv[e] = -FLT_MAX; bix[e] = 0; }

#pragma unroll
    for (int mt = 0; mt < 4; mt++) {
#pragma unroll
        for (int nf = 0; nf < 4; nf++) {
            const int n = n0 + warp * 32 + nf * 8 + tg * 2;
            const float b0v = bias[n], b1v = bias[n + 1];
            acc[mt][nf][0] += b0v; acc[mt][nf][1] += b1v;
            acc[mt][nf][2] += b0v; acc[mt][nf][3] += b1v;
            const int m0r = mt * 16 + g, m1r = m0r + 8;
            *(float2*)&out[((size_t)m0r * TD + t) * VV + n] =
                make_float2(acc[mt][nf][0], acc[mt][nf][1]);
            *(float2*)&out[((size_t)m1r * TD + t) * VV + n] =
                make_float2(acc[mt][nf][2], acc[mt][nf][3]);
            if (acc[mt][nf][0] > bv[mt * 2])     { bv[mt * 2] = acc[mt][nf][0];     bix[mt * 2] = n; }
            if (acc[mt][nf][1] > bv[mt * 2])     { bv[mt * 2] = acc[mt][nf][1];     bix[mt * 2] = n + 1; }
            if (acc[mt][nf][2] > bv[mt * 2 + 1]) { bv[mt * 2 + 1] = acc[mt][nf][2]; bix[mt * 2 + 1] = n; }
            if (acc[mt][nf][3] > bv[mt * 2 + 1]) { bv[mt * 2 + 1] = acc[mt][nf][3]; bix[mt * 2 + 1] = n + 1; }
        }
    }
#pragma unroll
    for (int off = 1; off <= 2; off <<= 1) {
#pragma unroll
        for (int e = 0; e < 8; e++) {
            float ov = __shfl_xor_sync(0xffffffffu, bv[e], off);
            int   oi = __shfl_xor_sync(0xffffffffu, bix[e], off);
            if (ov > bv[e] || (ov == bv[e] && oi < bix[e])) { bv[e] = ov; bix[e] = oi; }
        }
    }
    float* sval = (float*)sml;             // [8 warps][64 rows]
    int*   sidx = (int*)(sval + 8 * 64);
    if (tg == 0) {
#pragma unroll
        for (int mt = 0; mt < 4; mt++) {
#pragma unroll
            for (int rr = 0; rr < 2; rr++) {
                const int row = mt * 16 + rr * 8 + g;
                sval[warp * 64 + row] = bv[mt * 2 + rr];
                sidx[warp * 64 + row] = bix[mt * 2 + rr];
            }
        }
    }
    __syncthreads();
    if (tid < 64) {
        float best = sval[tid]; int bi = sidx[tid];
#pragma unroll
        for (int w = 1; w < 8; w++) {
            float ov = sval[w * 64 + tid]; int oi = sidx[w * 64 + tid];
            if (ov > best || (ov == best && oi < bi)) { best = ov; bi = oi; }
        }
        g_pval[blockIdx.x * 64 + tid] = best;
        g_pidx[blockIdx.x * 64 + tid] = bi;
    }
}

// ---------------- prep kernels ----------------

__global__ void split_hilo(const float* __restrict__ in,
                           bf* __restrict__ hi, bf* __restrict__ lo, int n)
{
    int idx = blockIdx.x * 256 + threadIdx.x;
    if (idx < n) {
        float x = in[idx];
        bf h = __float2bfloat16_rn(x);
        hi[idx] = h;
        lo[idx] = __float2bfloat16_rn(x - __bfloat162float(h));
    }
}

__global__ __launch_bounds__(256) void wout_split(const float* __restrict__ W)
{
    __shared__ float tile[32][33];
    const int v0 = blockIdx.x * 32, k0 = blockIdx.y * 32;
    const int tx = threadIdx.x, ty = threadIdx.y;
#pragma unroll
    for (int i = 0; i < 4; i++)
        tile[ty + i * 8][tx] = W[(size_t)(k0 + ty + i * 8) * VV + v0 + tx];
    __syncthreads();
#pragma unroll
    for (int i = 0; i < 4; i++) {
        const int v = v0 + ty + i * 8;
        const int k = k0 + tx;
        float w = tile[tx][ty + i * 8];
        bf hi = __float2bfloat16_rn(w);
        g_WoutHiT[(size_t)v * XCK + k] = hi;
        g_WoutLoT[(size_t)v * XCK + k] = __float2bfloat16_rn(w - __bfloat162float(hi));
    }
}

__global__ __launch_bounds__(256) void init_kernel(
    const float* __restrict__ latent, const int* __restrict__ style,
    const float* __restrict__ style_emb, const float* __restrict__ W_l2h,
    const float* __restrict__ b_l2h, const float* __restrict__ emb)
{
    __shared__ float cat[8][KCAT];
    const int bg = blockIdx.y, tid = threadIdx.x;
    const int j = blockIdx.x * 256 + tid;
    for (int idx = tid; idx < 8 * KCAT; idx += 256) {
        int bb = idx / KCAT, k = idx % KCAT;
        int b = bg * 8 + bb;
        cat[bb][k] = (k < LAT) ? latent[b * LAT + k]
                               : style_emb[style[b] * STY + (k - LAT)];
    }
    __syncthreads();
    float acc[8];
    const float bj = b_l2h[j];
#pragma unroll
    for (int bb = 0; bb < 8; bb++) acc[bb] = bj;
    for (int k = 0; k < KCAT; k++) {
        float w = W_l2h[(size_t)k * HH + j];
#pragma unroll
        for (int bb = 0; bb < 8; bb++) acc[bb] += cat[bb][k] * w;
    }
#pragma unroll
    for (int bb = 0; bb < 8; bb++) {
        const int b = bg * 8 + bb;
        g_h[b * HH + j] = acc[bb];
        bf hi = __float2bfloat16_rn(acc[bb]);
        g_XHhi[b * HH + j] = hi;
        g_XHlo[b * HH + j] = __float2bfloat16_rn(acc[bb] - __bfloat162float(hi));
    }
    if (blockIdx.x == 0) {
        for (int idx = tid; idx < 8 * EE; idx += 256) {
            int bb = idx / EE, i = idx % EE;
            float x = emb[EE + i];                 // BOS token = 1
            bf hi = __float2bfloat16_rn(x);
            g_XEhi[(bg * 8 + bb) * EE + i] = hi;
            g_XElo[(bg * 8 + bb) * EE + i] = __float2bfloat16_rn(x - __bfloat162float(hi));
        }
    }
}

// ---------------- fused per-step middle kernel ----------------
__global__ __launch_bounds__(512) void step_mid(
    const float* __restrict__ b_ih, const float* __restrict__ b_hh,
    const float* __restrict__ enc)
{
    __shared__ float hs[HH];
    __shared__ float at[TENC];
    __shared__ float part[8][TENC];
    __shared__ float sred[2];
    const int b = blockIdx.x, tid = threadIdx.x;

    // Phase 1: GRU combine (sum split-K partials z: 0..1 gi, 2..5 gh)
#pragma unroll
    for (int j = tid; j < HH; j += 512) {
        float ir = b_ih[j], iz = b_ih[HH + j], inn = b_ih[2 * HH + j];
        float hr = b_hh[j], hz = b_hh[HH + j], hn = b_hh[2 * HH + j];
#pragma unroll
        for (int z = 0; z < 2; z++) {
            const float* P = g_gp + (size_t)z * BB * G3 + (size_t)b * G3;
            ir += P[j]; iz += P[HH + j]; inn += P[2 * HH + j];
        }
#pragma unroll
        for (int z = 2; z < 6; z++) {
            const float* P = g_gp + (size_t)z * BB * G3 + (size_t)b * G3;
            hr += P[j]; hz += P[HH + j]; hn += P[2 * HH + j];
        }
        float r  = 1.f / (1.f + expf(-(ir + hr)));
        float zz = 1.f / (1.f + expf(-(iz + hz)));
        float n  = tanhf(inn + r * hn);
        float hnew = (1.f - zz) * n + zz * g_h[b * HH + j];
        hs[j] = hnew;
        g_h[b * HH + j] = hnew;
        bf hi = __float2bfloat16_rn(hnew);
        bf lo = __float2bfloat16_rn(hnew - __bfloat162float(hi));
        g_XHhi[b * HH + j] = hi;             g_XHlo[b * HH + j] = lo;
        g_Ahi[(size_t)b * XCK + j] = hi;     g_Alo[(size_t)b * XCK + j] = lo;
    }
    __syncthreads();

    // Phase 2: scores (coalesced via encwaT)
    {
        const int t = tid & 63, sl = tid >> 6;
        const float* ew = g_encwaT + (size_t)b * HH * TENC;
        float p = 0.f;
        const int kend = sl * 128 + 128;
#pragma unroll 4
        for (int k = sl * 128; k < kend; k++) p += hs[k] * ew[(size_t)k * TENC + t];
        part[sl][t] = p;
    }
    __syncthreads();
    if (tid < 64) {
        float s = 0.f;
#pragma unroll
        for (int sl = 0; sl < 8; sl++) s += part[sl][tid];
        at[tid] = s;
    }
    __syncthreads();
    // parallel softmax over 64 scores
    if (tid < 32) {
        float m = fmaxf(at[tid], at[tid + 32]);
#pragma unroll
        for (int off = 16; off > 0; off >>= 1)
            m = fmaxf(m, __shfl_xor_sync(0xffffffffu, m, off));
        if (tid == 0) sred[0] = m;
    }
    __syncthreads();
    if (tid < 64) at[tid] = expf(at[tid] - sred[0]);
    __syncthreads();
    if (tid < 32) {
        float s = at[tid] + at[tid + 32];
#pragma unroll
        for (int off = 16; off > 0; off >>= 1)
            s += __shfl_xor_sync(0xffffffffu, s, off);
        if (tid == 0) sred[1] = 1.f / s;
    }
    __syncthreads();
    if (tid < 64) at[tid] *= sred[1];
    __syncthreads();

    // Phase 3: ctx
#pragma unroll
    for (int j = tid; j < HH; j += 512) {
        float c = 0.f;
        const float* eb = enc + (size_t)b * TENC * HH + j;
#pragma unroll 8
        for (int t2 = 0; t2 < TENC; t2++) c += at[t2] * eb[(size_t)t2 * HH];
        bf hi = __float2bfloat16_rn(c);
        g_Ahi[(size_t)b * XCK + HH + j] = hi;
        g_Alo[(size_t)b * XCK + HH + j] = __float2bfloat16_rn(c - __bfloat162float(hi));
    }
}

// Final argmax reduce over NBLK partials + embedding gather.
__global__ __launch_bounds__(128) void argmax_final(const float* __restrict__ emb)
{
    __shared__ float sv[128];
    __shared__ int   si[128];
    const int b = blockIdx.x, tid = threadIdx.x;
    float best = -FLT_MAX; int bi = 0x7fffffff;
    if (tid < NBLK) { best = g_pval[tid * 64 + b]; bi = g_pidx[tid * 64 + b]; }
    sv[tid] = best; si[tid] = bi;
    __syncthreads();
    for (int sft = 64; sft > 0; sft >>= 1) {
        if (tid < sft) {
            float ov = sv[tid + sft]; int oi = si[tid + sft];
            if (ov > sv[tid] || (ov == sv[tid] && oi < si[tid])) { sv[tid] = ov; si[tid] = oi; }
        }
        __syncthreads();
    }
    const int tok = si[0];
    for (int e = tid; e < EE; e += 128) {
        float x = emb[(size_t)tok * EE + e];
        bf hi = __float2bfloat16_rn(x);
        g_XEhi[b * EE + e] = hi;
        g_XElo[b * EE + e] = __float2bfloat16_rn(x - __bfloat162float(hi));
    }
}

// ---------------- host launcher ----------------
extern "C" void kernel_launch(void* const* d_in, const int* in_sizes, int n_in,
                              void* d_out, int out_size)
{
    int ci = 0;
    const float* latent    = (const float*)d_in[ci++];
    const int*   style     = (const int*)  d_in[ci++];
    const float* enc       = (const float*)d_in[ci++];
    if (ci < n_in && in_sizes[ci] == 1) ci++;           // skip max_length scalar if present
    const float* emb       = (const float*)d_in[ci++];
    const float* style_emb = (const float*)d_in[ci++];
    const float* W_l2h     = (const float*)d_in[ci++];
    const float* b_l2h     = (const float*)d_in[ci++];
    const float* W_ih      = (const float*)d_in[ci++];
    const float* W_hh      = (const float*)d_in[ci++];
    const float* b_ih      = (const float*)d_in[ci++];
    const float* b_hh      = (const float*)d_in[ci++];
    const float* W_a       = (const float*)d_in[ci++];
    const float* W_out     = (const float*)d_in[ci++];
    const float* b_out     = (const float*)d_in[ci++];
    float* out = (float*)d_out;

    const int TD = out_size / (BB * VV);                // decode length (32)

    bf *pEncHi, *pEncLo, *pWaHi, *pWaLo, *pWihHi, *pWihLo, *pWhhHi, *pWhhLo;
    cudaGetSymbolAddress((void**)&pEncHi, g_EncHi);
    cudaGetSymbolAddress((void**)&pEncLo, g_EncLo);
    cudaGetSymbolAddress((void**)&pWaHi, g_WaHi);
    cudaGetSymbolAddress((void**)&pWaLo, g_WaLo);
    cudaGetSymbolAddress((void**)&pWihHi, g_WihHi);
    cudaGetSymbolAddress((void**)&pWihLo, g_WihLo);
    cudaGetSymbolAddress((void**)&pWhhHi, g_WhhHi);
    cudaGetSymbolAddress((void**)&pWhhLo, g_WhhLo);

    cudaFuncSetAttribute(logits_mma, cudaFuncAttributeMaxDynamicSharedMemorySize, LSMEM);
    cudaFuncSetAttribute(gates_mma, cudaFuncAttributeMaxDynamicSharedMemorySize,
                         Cfg<2>::SMEM);
    cudaFuncSetAttribute(encwa_mma, cudaFuncAttributeMaxDynamicSharedMemorySize,
                         Cfg<2>::SMEM);

    // one-time per-launch prep
    wout_split<<<dim3(VV / 32, XCK / 32), dim3(32, 8)>>>(W_out);
    split_hilo<<<(BB * TENC * HH + 255) / 256, 256>>>(enc, pEncHi, pEncLo, BB * TENC * HH);
    split_hilo<<<(HH * HH + 255) / 256, 256>>>(W_a, pWaHi, pWaLo, HH * HH);
    split_hilo<<<(G3 * EE + 255) / 256, 256>>>(W_ih, pWihHi, pWihLo, G3 * EE);
    split_hilo<<<(G3 * HH + 255) / 256, 256>>>(W_hh, pWhhHi, pWhhLo, G3 * HH);
    init_kernel<<<dim3(4, 8), 256>>>(latent, style, style_emb, W_l2h, b_l2h, emb);
    encwa_mma<<<dim3(HH / 128, (BB * TENC) / 64), 256, Cfg<2>::SMEM>>>();

    for (int t = 0; t < TD; t++) {
        gates_mma<<<dim3(G3 / 128, NSPK), 256, Cfg<2>::SMEM>>>();
        step_mid<<<BB, 512>>>(b_ih, b_hh, enc);
        logits_mma<<<NBLK, 256, LSMEM>>>(b_out, out, t, TD);
        argmax_final<<<BB, 128>>>(emb);
    }
}

// round 12
// speedup vs baseline: 4.0697x; 1.3718x over previous
#include <cuda_runtime.h>
#include <cuda_bf16.h>
#include <cuda_fp16.h>
#include <math.h>
#include <float.h>
#include <stdint.h>

// Problem constants
#define BB   64
#define TENC 64
#define HH   1024
#define EE   512
#define VV   32000
#define LAT  128
#define STY  64
#define KCAT 192      // LAT + STY
#define G3   3072     // 3*H
#define XCK  2048     // 2*H
#define NBLK (VV / 256)   // 125 logits blocks
#define NSPK 6            // gates split-K partials (2 gi + 4 gh)

#define APAD 72

typedef __nv_bfloat16 bf;

// ---------------- static device scratch (allocation-free) ----------------
__device__ __align__(256) float g_encwaT[BB * HH * TENC]; // enc@Wa^T transposed [b][k][t]
__device__ __align__(256) float g_h  [BB * HH];           // hidden state fp32
__device__ __align__(256) float g_gp [NSPK * BB * G3];    // gates split-K partials
__device__ __align__(256) float g_xc [BB * XCK];          // fp32 [h|ctx] (for exact argmax)
// top-2 argmax partials per (block, row)
__device__ __align__(256) float g_pv1[NBLK * BB];
__device__ __align__(256) int   g_pi1[NBLK * BB];
__device__ __align__(256) float g_pv2[NBLK * BB];
__device__ __align__(256) int   g_pi2[NBLK * BB];

// weights / activations
__device__ __align__(256) bf   g_WoutHiT[(size_t)VV * XCK]; // W_out^T [V][K] bf16 hi (exact path)
__device__ __align__(256) bf   g_WoutLoT[(size_t)VV * XCK]; // bf16 lo
__device__ __align__(256) half g_WoutF16T[(size_t)VV * XCK];// W_out^T [V][K] fp16 (fast path)
__device__ __align__(256) half g_Af16[BB * XCK];            // logits A fp16 [h|ctx]
__device__ __align__(256) bf g_XEhi[BB * EE];             // gates A (x part)
__device__ __align__(256) bf g_XElo[BB * EE];
__device__ __align__(256) bf g_XHhi[BB * HH];             // gates A (h part)
__device__ __align__(256) bf g_XHlo[BB * HH];
__device__ __align__(256) bf g_EncHi[BB * TENC * HH];     // encoder outputs
__device__ __align__(256) bf g_EncLo[BB * TENC * HH];
__device__ __align__(256) bf g_WaHi[HH * HH];             // W_a [k][h]
__device__ __align__(256) bf g_WaLo[HH * HH];
__device__ __align__(256) bf g_WihHi[G3 * EE];            // W_ih [n][k]
__device__ __align__(256) bf g_WihLo[G3 * EE];
__device__ __align__(256) bf g_WhhHi[G3 * HH];            // W_hh [n][k]
__device__ __align__(256) bf g_WhhLo[G3 * HH];

// ---------------- PTX helpers ----------------

__device__ __forceinline__ void mma16816(float* c, const unsigned* a, const unsigned* b)
{
    asm volatile(
        "mma.sync.aligned.m16n8k16.row.col.f32.bf16.bf16.f32 "
        "{%0,%1,%2,%3}, {%4,%5,%6,%7}, {%8,%9}, {%0,%1,%2,%3};\n"
        : "+f"(c[0]), "+f"(c[1]), "+f"(c[2]), "+f"(c[3])
        : "r"(a[0]), "r"(a[1]), "r"(a[2]), "r"(a[3]), "r"(b[0]), "r"(b[1]));
}

__device__ __forceinline__ void mma16816h(float* c, const unsigned* a, const unsigned* b)
{
    asm volatile(
        "mma.sync.aligned.m16n8k16.row.col.f32.f16.f16.f32 "
        "{%0,%1,%2,%3}, {%4,%5,%6,%7}, {%8,%9}, {%0,%1,%2,%3};\n"
        : "+f"(c[0]), "+f"(c[1]), "+f"(c[2]), "+f"(c[3])
        : "r"(a[0]), "r"(a[1]), "r"(a[2]), "r"(a[3]), "r"(b[0]), "r"(b[1]));
}

__device__ __forceinline__ void cpasync16(void* sdst, const void* gsrc)
{
    unsigned sa = (unsigned)__cvta_generic_to_shared(sdst);
    asm volatile("cp.async.cg.shared.global [%0], [%1], 16;\n" :: "r"(sa), "l"(gsrc));
}
__device__ __forceinline__ void cpasync16s(unsigned saddr, const void* gsrc)
{
    asm volatile("cp.async.cg.shared.global [%0], [%1], 16;\n" :: "r"(saddr), "l"(gsrc));
}

__device__ __forceinline__ void ldsm4(unsigned& r0, unsigned& r1, unsigned& r2, unsigned& r3,
                                      uint32_t saddr)
{
    asm volatile("ldmatrix.sync.aligned.m8n8.x4.shared.b16 {%0,%1,%2,%3}, [%4];"
                 : "=r"(r0), "=r"(r1), "=r"(r2), "=r"(r3) : "r"(saddr));
}

__device__ __forceinline__ uint32_t smem_u32(const void* p)
{
    uint32_t a;
    asm("{ .reg .u64 t; cvta.to.shared.u64 t, %1; cvt.u32.u64 %0, t; }" : "=r"(a) : "l"(p));
    return a;
}

// top-2 helpers (first-index tiebreak)
__device__ __forceinline__ bool gtpair(float x, int i, float y, int j)
{
    return (x > y) || (x == y && i < j);
}
// merge candidate (x, n) into (v1,i1,v2,i2)
__device__ __forceinline__ void top2_push(float& v1, int& i1, float& v2, int& i2,
                                          float x, int n)
{
    if (gtpair(x, n, v1, i1)) { v2 = v1; i2 = i1; v1 = x; i1 = n; }
    else if (gtpair(x, n, v2, i2)) { v2 = x; i2 = n; }
}
// merge set B into set A
__device__ __forceinline__ void top2_merge(float& a1, int& ai1, float& a2, int& ai2,
                                           float b1, int bi1, float b2, int bi2)
{
    if (gtpair(b1, bi1, a1, ai1)) {
        float n2; int ni2;
        if (gtpair(a1, ai1, b2, bi2)) { n2 = a1; ni2 = ai1; }
        else                          { n2 = b2; ni2 = bi2; }
        a1 = b1; ai1 = bi1; a2 = n2; ai2 = ni2;
    } else {
        if (gtpair(b1, bi1, a2, ai2)) { a2 = b1; ai2 = bi1; }
    }
}

// ---------------- generic hi/lo warp-MMA path (gates/encwa; k=64, 2-stage) ------

template<int NF> struct Cfg {
    static const int BN = 64 * NF;
    static const int SA = 64 * APAD;
    static const int SW = BN * APAD;
    static const int STAGE = 2 * SA + 2 * SW;
    static const int SMEM = 2 * STAGE * 2;
};

template<int NF>
__device__ __forceinline__ void load_stage_t(
    bf* st,
    const bf* __restrict__ Ahi, const bf* __restrict__ Alo, int lda,
    const bf* __restrict__ Whi, const bf* __restrict__ Wlo, int ldw,
    int k0, int tid)
{
    bf* sAhi = st;
    bf* sAlo = st + Cfg<NF>::SA;
    bf* sWhi = st + 2 * Cfg<NF>::SA;
    bf* sWlo = st + 2 * Cfg<NF>::SA + Cfg<NF>::SW;
#pragma unroll
    for (int i = 0; i < 2; i++) {
        int c = tid + i * 256;
        int r = c >> 3, cc = (c & 7) * 8;
        cpasync16(&sAhi[r * APAD + cc], &Ahi[(size_t)r * lda + k0 + cc]);
        cpasync16(&sAlo[r * APAD + cc], &Alo[(size_t)r * lda + k0 + cc]);
    }
#pragma unroll
    for (int i = 0; i < 2 * NF; i++) {
        int c = tid + i * 256;
        int r = c >> 3, cc = (c & 7) * 8;
        cpasync16(&sWhi[r * APAD + cc], &Whi[(size_t)r * ldw + k0 + cc]);
        cpasync16(&sWlo[r * APAD + cc], &Wlo[(size_t)r * ldw + k0 + cc]);
    }
    asm volatile("cp.async.commit_group;\n");
}

template<int NF>
__device__ __forceinline__ void compute_stage_t(
    uint32_t sbase, int warp, int lane, float acc[4][NF][4])
{
    const uint32_t oAlo = Cfg<NF>::SA * 2;
    const uint32_t oWhi = 2 * Cfg<NF>::SA * 2;
    const uint32_t oWlo = (2 * Cfg<NF>::SA + Cfg<NF>::SW) * 2;
    const uint32_t aoff = ((uint32_t)((lane & 7) + ((lane >> 3) & 1) * 8)) * (APAD * 2)
                        + ((uint32_t)(lane >> 4)) * 16;
    const uint32_t boff = ((uint32_t)((lane & 7) + (lane >> 4) * 8)) * (APAD * 2)
                        + ((uint32_t)((lane >> 3) & 1)) * 16;
    const uint32_t wn = (uint32_t)warp * (8 * NF) * (APAD * 2);

#pragma unroll
    for (int kf = 0; kf < 4; kf++) {
        const uint32_t kb = (uint32_t)kf * 32;
        unsigned bhi[NF][2], blo[NF][2];
#pragma unroll
        for (int np = 0; np < NF / 2; np++) {
            const uint32_t ba = sbase + wn + (uint32_t)np * 16 * (APAD * 2) + boff + kb;
            ldsm4(bhi[2 * np][0], bhi[2 * np][1], bhi[2 * np + 1][0], bhi[2 * np + 1][1],
                  ba + oWhi);
            ldsm4(blo[2 * np][0], blo[2 * np][1], blo[2 * np + 1][0], blo[2 * np + 1][1],
                  ba + oWlo);
        }
#pragma unroll
        for (int mt = 0; mt < 4; mt++) {
            const uint32_t aa = sbase + (uint32_t)mt * 16 * (APAD * 2) + aoff + kb;
            unsigned ahi[4], alo[4];
            ldsm4(ahi[0], ahi[1], ahi[2], ahi[3], aa);
            ldsm4(alo[0], alo[1], alo[2], alo[3], aa + oAlo);
#pragma unroll
            for (int nf = 0; nf < NF; nf++) {
                mma16816(acc[mt][nf], ahi, bhi[nf]);
                mma16816(acc[mt][nf], alo, bhi[nf]);
                mma16816(acc[mt][nf], ahi, blo[nf]);
            }
        }
    }
}

template<int NF>
__device__ __forceinline__ void mainloop_t(
    const bf* Ahi, const bf* Alo, int lda,
    const bf* Whi, const bf* Wlo, int ldw,
    int nchunks, float acc[4][NF][4], bf* sm)
{
    const int tid = threadIdx.x, warp = tid >> 5, lane = tid & 31;
    const uint32_t sb = smem_u32(sm);
#pragma unroll
    for (int mt = 0; mt < 4; mt++)
#pragma unroll
        for (int nf = 0; nf < NF; nf++)
#pragma unroll
            for (int i = 0; i < 4; i++) acc[mt][nf][i] = 0.f;

    load_stage_t<NF>(sm, Ahi, Alo, lda, Whi, Wlo, ldw, 0, tid);

    for (int kc = 0; kc < nchunks; kc++) {
        const uint32_t curb = sb + (uint32_t)(kc & 1) * (Cfg<NF>::STAGE * 2);
        if (kc + 1 < nchunks) {
            bf* nxt = sm + ((kc + 1) & 1) * Cfg<NF>::STAGE;
            load_stage_t<NF>(nxt, Ahi, Alo, lda, Whi, Wlo, ldw, (kc + 1) * 64, tid);
        } else {
            asm volatile("cp.async.commit_group;\n");
        }
        asm volatile("cp.async.wait_group 1;\n");
        __syncthreads();
        compute_stage_t<NF>(curb, warp, lane, acc);
        __syncthreads();
    }
}

// ---------------- GRU gates (split-K=6) ----------------
__global__ __launch_bounds__(256) void gates_mma(void)
{
    extern __shared__ bf smg[];
    const int nt = blockIdx.x;
    const int z = blockIdx.y;
    float acc[4][2][4];
    if (z < 2) {
        const int k0 = z * 256;
        mainloop_t<2>(g_XEhi + k0, g_XElo + k0, EE,
                      g_WihHi + (size_t)nt * 128 * EE + k0,
                      g_WihLo + (size_t)nt * 128 * EE + k0, EE,
                      4, acc, smg);
    } else {
        const int k0 = (z - 2) * 256;
        mainloop_t<2>(g_XHhi + k0, g_XHlo + k0, HH,
                      g_WhhHi + (size_t)nt * 128 * HH + k0,
                      g_WhhLo + (size_t)nt * 128 * HH + k0, HH,
                      4, acc, smg);
    }
    float* C = g_gp + (size_t)z * BB * G3;
    const int tid = threadIdx.x, warp = tid >> 5, lane = tid & 31;
    const int g = lane >> 2, tg = lane & 3;
#pragma unroll
    for (int mt = 0; mt < 4; mt++) {
#pragma unroll
        for (int nf = 0; nf < 2; nf++) {
            const int n = nt * 128 + warp * 16 + nf * 8 + tg * 2;
            const int m0r = mt * 16 + g, m1r = m0r + 8;
            *(float2*)&C[(size_t)m0r * G3 + n] = make_float2(acc[mt][nf][0], acc[mt][nf][1]);
            *(float2*)&C[(size_t)m1r * G3 + n] = make_float2(acc[mt][nf][2], acc[mt][nf][3]);
        }
    }
}

// enc_wa with transposed epilogue: g_encwaT[b][k][t]. grid (8, 64), NF=2.
__global__ __launch_bounds__(256) void encwa_mma(void)
{
    extern __shared__ bf sme[];
    const int n0 = blockIdx.x * 128;
    const int m0g = blockIdx.y * 64;
    float acc[4][2][4];
    mainloop_t<2>(g_EncHi + (size_t)m0g * HH, g_EncLo + (size_t)m0g * HH, HH,
                  g_WaHi + (size_t)n0 * HH, g_WaLo + (size_t)n0 * HH, HH,
                  HH / 64, acc, sme);
    const int tid = threadIdx.x, warp = tid >> 5, lane = tid & 31;
    const int g = lane >> 2, tg = lane & 3;
    const int b = m0g >> 6;
    float* dst = g_encwaT + (size_t)b * HH * TENC;
#pragma unroll
    for (int mt = 0; mt < 4; mt++) {
#pragma unroll
        for (int nf = 0; nf < 2; nf++) {
            const int n = n0 + warp * 16 + nf * 8 + tg * 2;
            const int t0 = (m0g + mt * 16 + g) & 63, t1 = t0 + 8;
            dst[(size_t)n * TENC + t0]       = acc[mt][nf][0];
            dst[(size_t)(n + 1) * TENC + t0] = acc[mt][nf][1];
            dst[(size_t)n * TENC + t1]       = acc[mt][nf][2];
            dst[(size_t)(n + 1) * TENC + t1] = acc[mt][nf][3];
        }
    }
}

// ---------------- logits: SINGLE fp16 stream, k=32 chunks, 4-stage pipeline ----------------
#define AP32   40
#define SA32   (64 * AP32)               // 2560 elems
#define SW32   (256 * AP32)              // 10240 elems
#define ST32   (SA32 + SW32)             // 12800 elems = 25600 B
#define LSMEM  (4 * ST32 * 2)            // 102400 B

__device__ __forceinline__ void lg_load(uint32_t sb, int buf, int k0, int n0, int tid)
{
    const uint32_t st = sb + (uint32_t)buf * (ST32 * 2);
    {   // A: 64 rows x 4 x 16B chunks
        int r = tid >> 2, c = tid & 3;
        cpasync16s(st + r * 80 + c * 16, &g_Af16[(size_t)r * XCK + k0 + c * 8]);
    }
#pragma unroll
    for (int i = 0; i < 4; i++) {        // W: 256 rows x 4 chunks
        int idx = tid + i * 256;
        int r = idx >> 2, c = idx & 3;
        cpasync16s(st + SA32 * 2 + r * 80 + c * 16,
                   &g_WoutF16T[(size_t)(n0 + r) * XCK + k0 + c * 8]);
    }
    asm volatile("cp.async.commit_group;\n");
}

__global__ __launch_bounds__(256, 1) void logits_mma(
    const float* __restrict__ bias, float* __restrict__ out, int t, int TD)
{
    extern __shared__ bf sml[];
    const uint32_t sb = smem_u32(sml);
    const int tid = threadIdx.x, warp = tid >> 5, lane = tid & 31;
    const int n0 = blockIdx.x * 256;

    float acc[4][4][4];
#pragma unroll
    for (int mt = 0; mt < 4; mt++)
#pragma unroll
        for (int nf = 0; nf < 4; nf++)
#pragma unroll
            for (int i = 0; i < 4; i++) acc[mt][nf][i] = 0.f;

    lg_load(sb, 0, 0, n0, tid);
    lg_load(sb, 1, 32, n0, tid);
    lg_load(sb, 2, 64, n0, tid);

    const uint32_t aoff = ((uint32_t)((lane & 7) + ((lane >> 3) & 1) * 8)) * 80
                        + ((uint32_t)(lane >> 4)) * 16;
    const uint32_t boff = ((uint32_t)((lane & 7) + (lane >> 4) * 8)) * 80
                        + ((uint32_t)((lane >> 3) & 1)) * 16;
    const uint32_t wn = (uint32_t)warp * 32 * 80;

    for (int c = 0; c < 64; c++) {
        asm volatile("cp.async.wait_group 2;\n");
        __syncthreads();
        const uint32_t base = sb + (uint32_t)(c & 3) * (ST32 * 2);
#pragma unroll
        for (int kf = 0; kf < 2; kf++) {
            const uint32_t kb = (uint32_t)kf * 32;
            unsigned a[4][4], bw[4][2];
#pragma unroll
            for (int mt = 0; mt < 4; mt++) {
                const uint32_t aa = base + (uint32_t)mt * 16 * 80 + aoff + kb;
                ldsm4(a[mt][0], a[mt][1], a[mt][2], a[mt][3], aa);
            }
#pragma unroll
            for (int np = 0; np < 2; np++) {
                const uint32_t ba = base + SA32 * 2 + wn + (uint32_t)np * 16 * 80 + boff + kb;
                ldsm4(bw[2 * np][0], bw[2 * np][1], bw[2 * np + 1][0], bw[2 * np + 1][1], ba);
            }
#pragma unroll
            for (int mt = 0; mt < 4; mt++)
#pragma unroll
                for (int nf = 0; nf < 4; nf++)
                    mma16816h(acc[mt][nf], a[mt], bw[nf]);
        }
        __syncthreads();
        if (c + 3 < 64) lg_load(sb, (c + 3) & 3, (c + 3) * 32, n0, tid);
        else asm volatile("cp.async.commit_group;\n");
    }

    // epilogue: bias + store + fused per-block TOP-2 partials
    const int g = lane >> 2, tg = lane & 3;
    float v1[8], v2[8]; int i1[8], i2[8];
#pragma unroll
    for (int e = 0; e < 8; e++) {
        v1[e] = -FLT_MAX; i1[e] = 0x7fffffff;
        v2[e] = -FLT_MAX; i2[e] = 0x7fffffff;
    }

#pragma unroll
    for (int mt = 0; mt < 4; mt++) {
#pragma unroll
        for (int nf = 0; nf < 4; nf++) {
            const int n = n0 + warp * 32 + nf * 8 + tg * 2;
            const float b0v = bias[n], b1v = bias[n + 1];
            acc[mt][nf][0] += b0v; acc[mt][nf][1] += b1v;
            acc[mt][nf][2] += b0v; acc[mt][nf][3] += b1v;
            const int m0r = mt * 16 + g, m1r = m0r + 8;
            *(float2*)&out[((size_t)m0r * TD + t) * VV + n] =
                make_float2(acc[mt][nf][0], acc[mt][nf][1]);
            *(float2*)&out[((size_t)m1r * TD + t) * VV + n] =
                make_float2(acc[mt][nf][2], acc[mt][nf][3]);
            top2_push(v1[mt * 2],     i1[mt * 2],     v2[mt * 2],     i2[mt * 2],     acc[mt][nf][0], n);
            top2_push(v1[mt * 2],     i1[mt * 2],     v2[mt * 2],     i2[mt * 2],     acc[mt][nf][1], n + 1);
            top2_push(v1[mt * 2 + 1], i1[mt * 2 + 1], v2[mt * 2 + 1], i2[mt * 2 + 1], acc[mt][nf][2], n);
            top2_push(v1[mt * 2 + 1], i1[mt * 2 + 1], v2[mt * 2 + 1], i2[mt * 2 + 1], acc[mt][nf][3], n + 1);
        }
    }
    // merge across the 4 tg lanes of each row group
#pragma unroll
    for (int off = 1; off <= 2; off <<= 1) {
#pragma unroll
        for (int e = 0; e < 8; e++) {
            float o1 = __shfl_xor_sync(0xffffffffu, v1[e], off);
            int   oi1 = __shfl_xor_sync(0xffffffffu, i1[e], off);
            float o2 = __shfl_xor_sync(0xffffffffu, v2[e], off);
            int   oi2 = __shfl_xor_sync(0xffffffffu, i2[e], off);
            top2_merge(v1[e], i1[e], v2[e], i2[e], o1, oi1, o2, oi2);
        }
    }
    // smem reduce across warps
    float* sv1 = (float*)sml;             // [8][64]
    int*   si1 = (int*)(sv1 + 512);
    float* sv2 = (float*)(si1 + 512);
    int*   si2 = (int*)(sv2 + 512);
    if (tg == 0) {
#pragma unroll
        for (int mt = 0; mt < 4; mt++) {
#pragma unroll
            for (int rr = 0; rr < 2; rr++) {
                const int row = mt * 16 + rr * 8 + g;
                sv1[warp * 64 + row] = v1[mt * 2 + rr];
                si1[warp * 64 + row] = i1[mt * 2 + rr];
                sv2[warp * 64 + row] = v2[mt * 2 + rr];
                si2[warp * 64 + row] = i2[mt * 2 + rr];
            }
        }
    }
    __syncthreads();
    if (tid < 64) {
        float a1 = sv1[tid], a2 = sv2[tid]; int ai1 = si1[tid], ai2 = si2[tid];
#pragma unroll
        for (int w = 1; w < 8; w++) {
            top2_merge(a1, ai1, a2, ai2,
                       sv1[w * 64 + tid], si1[w * 64 + tid],
                       sv2[w * 64 + tid], si2[w * 64 + tid]);
        }
        g_pv1[blockIdx.x * 64 + tid] = a1;
        g_pi1[blockIdx.x * 64 + tid] = ai1;
        g_pv2[blockIdx.x * 64 + tid] = a2;
        g_pi2[blockIdx.x * 64 + tid] = ai2;
    }
}

// ---------------- prep kernels ----------------

__global__ void split_hilo(const float* __restrict__ in,
                           bf* __restrict__ hi, bf* __restrict__ lo, int n)
{
    int idx = blockIdx.x * 256 + threadIdx.x;
    if (idx < n) {
        float x = in[idx];
        bf h = __float2bfloat16_rn(x);
        hi[idx] = h;
        lo[idx] = __float2bfloat16_rn(x - __bfloat162float(h));
    }
}

__global__ __launch_bounds__(256) void wout_split(const float* __restrict__ W)
{
    __shared__ float tile[32][33];
    const int v0 = blockIdx.x * 32, k0 = blockIdx.y * 32;
    const int tx = threadIdx.x, ty = threadIdx.y;
#pragma unroll
    for (int i = 0; i < 4; i++)
        tile[ty + i * 8][tx] = W[(size_t)(k0 + ty + i * 8) * VV + v0 + tx];
    __syncthreads();
#pragma unroll
    for (int i = 0; i < 4; i++) {
        const int v = v0 + ty + i * 8;
        const int k = k0 + tx;
        float w = tile[tx][ty + i * 8];
        bf hi = __float2bfloat16_rn(w);
        g_WoutHiT[(size_t)v * XCK + k] = hi;
        g_WoutLoT[(size_t)v * XCK + k] = __float2bfloat16_rn(w - __bfloat162float(hi));
        g_WoutF16T[(size_t)v * XCK + k] = __float2half_rn(w);
    }
}

__global__ __launch_bounds__(256) void init_kernel(
    const float* __restrict__ latent, const int* __restrict__ style,
    const float* __restrict__ style_emb, const float* __restrict__ W_l2h,
    const float* __restrict__ b_l2h, const float* __restrict__ emb)
{
    __shared__ float cat[8][KCAT];
    const int bg = blockIdx.y, tid = threadIdx.x;
    const int j = blockIdx.x * 256 + tid;
    for (int idx = tid; idx < 8 * KCAT; idx += 256) {
        int bb = idx / KCAT, k = idx % KCAT;
        int b = bg * 8 + bb;
        cat[bb][k] = (k < LAT) ? latent[b * LAT + k]
                               : style_emb[style[b] * STY + (k - LAT)];
    }
    __syncthreads();
    float acc[8];
    const float bj = b_l2h[j];
#pragma unroll
    for (int bb = 0; bb < 8; bb++) acc[bb] = bj;
    for (int k = 0; k < KCAT; k++) {
        float w = W_l2h[(size_t)k * HH + j];
#pragma unroll
        for (int bb = 0; bb < 8; bb++) acc[bb] += cat[bb][k] * w;
    }
#pragma unroll
    for (int bb = 0; bb < 8; bb++) {
        const int b = bg * 8 + bb;
        g_h[b * HH + j] = acc[bb];
        bf hi = __float2bfloat16_rn(acc[bb]);
        g_XHhi[b * HH + j] = hi;
        g_XHlo[b * HH + j] = __float2bfloat16_rn(acc[bb] - __bfloat162float(hi));
    }
    if (blockIdx.x == 0) {
        for (int idx = tid; idx < 8 * EE; idx += 256) {
            int bb = idx / EE, i = idx % EE;
            float x = emb[EE + i];                 // BOS token = 1
            bf hi = __float2bfloat16_rn(x);
            g_XEhi[(bg * 8 + bb) * EE + i] = hi;
            g_XElo[(bg * 8 + bb) * EE + i] = __float2bfloat16_rn(x - __bfloat162float(hi));
        }
    }
}

// ---------------- fused per-step middle kernel ----------------
__global__ __launch_bounds__(512) void step_mid(
    const float* __restrict__ b_ih, const float* __restrict__ b_hh,
    const float* __restrict__ enc)
{
    __shared__ float hs[HH];
    __shared__ float at[TENC];
    __shared__ float part[8][TENC];
    __shared__ float sred[2];
    const int b = blockIdx.x, tid = threadIdx.x;

    // Phase 1: GRU combine (sum split-K partials z: 0..1 gi, 2..5 gh)
#pragma unroll
    for (int j = tid; j < HH; j += 512) {
        float ir = b_ih[j], iz = b_ih[HH + j], inn = b_ih[2 * HH + j];
        float hr = b_hh[j], hz = b_hh[HH + j], hn = b_hh[2 * HH + j];
#pragma unroll
        for (int z = 0; z < 2; z++) {
            const float* P = g_gp + (size_t)z * BB * G3 + (size_t)b * G3;
            ir += P[j]; iz += P[HH + j]; inn += P[2 * HH + j];
        }
#pragma unroll
        for (int z = 2; z < 6; z++) {
            const float* P = g_gp + (size_t)z * BB * G3 + (size_t)b * G3;
            hr += P[j]; hz += P[HH + j]; hn += P[2 * HH + j];
        }
        float r  = 1.f / (1.f + expf(-(ir + hr)));
        float zz = 1.f / (1.f + expf(-(iz + hz)));
        float n  = tanhf(inn + r * hn);
        float hnew = (1.f - zz) * n + zz * g_h[b * HH + j];
        hs[j] = hnew;
        g_h[b * HH + j] = hnew;
        bf hi = __float2bfloat16_rn(hnew);
        bf lo = __float2bfloat16_rn(hnew - __bfloat162float(hi));
        g_XHhi[b * HH + j] = hi;             g_XHlo[b * HH + j] = lo;
        g_xc[(size_t)b * XCK + j] = hnew;
        g_Af16[(size_t)b * XCK + j] = __float2half_rn(hnew);
    }
    __syncthreads();

    // Phase 2: scores (coalesced via encwaT)
    {
        const int t = tid & 63, sl = tid >> 6;
        const float* ew = g_encwaT + (size_t)b * HH * TENC;
        float p = 0.f;
        const int kend = sl * 128 + 128;
#pragma unroll 4
        for (int k = sl * 128; k < kend; k++) p += hs[k] * ew[(size_t)k * TENC + t];
        part[sl][t] = p;
    }
    __syncthreads();
    if (tid < 64) {
        float s = 0.f;
#pragma unroll
        for (int sl = 0; sl < 8; sl++) s += part[sl][tid];
        at[tid] = s;
    }
    __syncthreads();
    if (tid < 32) {
        float m = fmaxf(at[tid], at[tid + 32]);
#pragma unroll
        for (int off = 16; off > 0; off >>= 1)
            m = fmaxf(m, __shfl_xor_sync(0xffffffffu, m, off));
        if (tid == 0) sred[0] = m;
    }
    __syncthreads();
    if (tid < 64) at[tid] = expf(at[tid] - sred[0]);
    __syncthreads();
    if (tid < 32) {
        float s = at[tid] + at[tid + 32];
#pragma unroll
        for (int off = 16; off > 0; off >>= 1)
            s += __shfl_xor_sync(0xffffffffu, s, off);
        if (tid == 0) sred[1] = 1.f / s;
    }
    __syncthreads();
    if (tid < 64) at[tid] *= sred[1];
    __syncthreads();

    // Phase 3: ctx
#pragma unroll
    for (int j = tid; j < HH; j += 512) {
        float c = 0.f;
        const float* eb = enc + (size_t)b * TENC * HH + j;
#pragma unroll 8
        for (int t2 = 0; t2 < TENC; t2++) c += at[t2] * eb[(size_t)t2 * HH];
        g_xc[(size_t)b * XCK + HH + j] = c;
        g_Af16[(size_t)b * XCK + HH + j] = __float2half_rn(c);
    }
}

// Final: top-2 reduce over NBLK blocks, EXACT recompute of both candidates,
// pick true winner, gather embedding. grid = BB, 128 threads.
__global__ __launch_bounds__(128) void argmax_final(
    const float* __restrict__ emb, const float* __restrict__ bias)
{
    __shared__ float sv1[128], sv2[128];
    __shared__ int   si1[128], si2[128];
    __shared__ float dsum[128];
    __shared__ int   stok;
    const int b = blockIdx.x, tid = threadIdx.x;

    float a1 = -FLT_MAX, a2 = -FLT_MAX; int ai1 = 0x7fffffff, ai2 = 0x7fffffff;
    if (tid < NBLK) {
        a1 = g_pv1[tid * 64 + b]; ai1 = g_pi1[tid * 64 + b];
        a2 = g_pv2[tid * 64 + b]; ai2 = g_pi2[tid * 64 + b];
    }
    sv1[tid] = a1; si1[tid] = ai1; sv2[tid] = a2; si2[tid] = ai2;
    __syncthreads();
    for (int sft = 64; sft > 0; sft >>= 1) {
        if (tid < sft) {
            float b1 = sv1[tid + sft], b2 = sv2[tid + sft];
            int bj1 = si1[tid + sft], bj2 = si2[tid + sft];
            float c1 = sv1[tid], c2 = sv2[tid];
            int cj1 = si1[tid], cj2 = si2[tid];
            top2_merge(c1, cj1, c2, cj2, b1, bj1, b2, bj2);
            sv1[tid] = c1; si1[tid] = cj1; sv2[tid] = c2; si2[tid] = cj2;
        }
        __syncthreads();
    }
    const int cand1 = si1[0], cand2 = si2[0];

    // exact recompute: d = xc(fp32) . (whi+wlo) + bias
    {
        const int cand = (tid < 64) ? cand1 : cand2;
        const int l = tid & 63;
        const float* xc = g_xc + (size_t)b * XCK;
        const bf* whi = g_WoutHiT + (size_t)cand * XCK;
        const bf* wlo = g_WoutLoT + (size_t)cand * XCK;
        float s = 0.f;
#pragma unroll 8
        for (int k = l; k < XCK; k += 64)
            s += xc[k] * (__bfloat162float(whi[k]) + __bfloat162float(wlo[k]));
        dsum[tid] = s;
    }
    __syncthreads();
    if (tid == 0) {
        float d1 = bias[cand1], d2 = bias[cand2];
        for (int i = 0; i < 64; i++) { d1 += dsum[i]; d2 += dsum[64 + i]; }
        int tok;
        if (d1 > d2)      tok = cand1;
        else if (d2 > d1) tok = cand2;
        else              tok = (cand1 < cand2) ? cand1 : cand2;
        stok = tok;
    }
    __syncthreads();
    const int tok = stok;
    for (int e = tid; e < EE; e += 128) {
        float x = emb[(size_t)tok * EE + e];
        bf hi = __float2bfloat16_rn(x);
        g_XEhi[b * EE + e] = hi;
        g_XElo[b * EE + e] = __float2bfloat16_rn(x - __bfloat162float(hi));
    }
}

// ---------------- host launcher ----------------
extern "C" void kernel_launch(void* const* d_in, const int* in_sizes, int n_in,
                              void* d_out, int out_size)
{
    int ci = 0;
    const float* latent    = (const float*)d_in[ci++];
    const int*   style     = (const int*)  d_in[ci++];
    const float* enc       = (const float*)d_in[ci++];
    if (ci < n_in && in_sizes[ci] == 1) ci++;           // skip max_length scalar if present
    const float* emb       = (const float*)d_in[ci++];
    const float* style_emb = (const float*)d_in[ci++];
    const float* W_l2h     = (const float*)d_in[ci++];
    const float* b_l2h     = (const float*)d_in[ci++];
    const float* W_ih      = (const float*)d_in[ci++];
    const float* W_hh      = (const float*)d_in[ci++];
    const float* b_ih      = (const float*)d_in[ci++];
    const float* b_hh      = (const float*)d_in[ci++];
    const float* W_a       = (const float*)d_in[ci++];
    const float* W_out     = (const float*)d_in[ci++];
    const float* b_out     = (const float*)d_in[ci++];
    float* out = (float*)d_out;

    const int TD = out_size / (BB * VV);                // decode length (32)

    bf *pEncHi, *pEncLo, *pWaHi, *pWaLo, *pWihHi, *pWihLo, *pWhhHi, *pWhhLo;
    cudaGetSymbolAddress((void**)&pEncHi, g_EncHi);
    cudaGetSymbolAddress((void**)&pEncLo, g_EncLo);
    cudaGetSymbolAddress((void**)&pWaHi, g_WaHi);
    cudaGetSymbolAddress((void**)&pWaLo, g_WaLo);
    cudaGetSymbolAddress((void**)&pWihHi, g_WihHi);
    cudaGetSymbolAddress((void**)&pWihLo, g_WihLo);
    cudaGetSymbolAddress((void**)&pWhhHi, g_WhhHi);
    cudaGetSymbolAddress((void**)&pWhhLo, g_WhhLo);

    cudaFuncSetAttribute(logits_mma, cudaFuncAttributeMaxDynamicSharedMemorySize, LSMEM);
    cudaFuncSetAttribute(gates_mma, cudaFuncAttributeMaxDynamicSharedMemorySize,
                         Cfg<2>::SMEM);
    cudaFuncSetAttribute(encwa_mma, cudaFuncAttributeMaxDynamicSharedMemorySize,
                         Cfg<2>::SMEM);

    // one-time per-launch prep
    wout_split<<<dim3(VV / 32, XCK / 32), dim3(32, 8)>>>(W_out);
    split_hilo<<<(BB * TENC * HH + 255) / 256, 256>>>(enc, pEncHi, pEncLo, BB * TENC * HH);
    split_hilo<<<(HH * HH + 255) / 256, 256>>>(W_a, pWaHi, pWaLo, HH * HH);
    split_hilo<<<(G3 * EE + 255) / 256, 256>>>(W_ih, pWihHi, pWihLo, G3 * EE);
    split_hilo<<<(G3 * HH + 255) / 256, 256>>>(W_hh, pWhhHi, pWhhLo, G3 * HH);
    init_kernel<<<dim3(4, 8), 256>>>(latent, style, style_emb, W_l2h, b_l2h, emb);
    encwa_mma<<<dim3(HH / 128, (BB * TENC) / 64), 256, Cfg<2>::SMEM>>>();

    for (int t = 0; t < TD; t++) {
        gates_mma<<<dim3(G3 / 128, NSPK), 256, Cfg<2>::SMEM>>>();
        step_mid<<<BB, 512>>>(b_ih, b_hh, enc);
        logits_mma<<<NBLK, 256, LSMEM>>>(b_out, out, t, TD);
        argmax_final<<<BB, 128>>>(emb, b_out);
    }
}

// round 13
// speedup vs baseline: 4.2875x; 1.0535x over previous
#include <cuda_runtime.h>
#include <cuda_bf16.h>
#include <cuda_fp16.h>
#include <math.h>
#include <float.h>
#include <stdint.h>

// Problem constants
#define BB   64
#define TENC 64
#define HH   1024
#define EE   512
#define VV   32000
#define LAT  128
#define STY  64
#define KCAT 192      // LAT + STY
#define G3   3072     // 3*H
#define XCK  2048     // 2*H
#define NBLK (VV / 256)   // 125 logits blocks
#define NSPK 6            // gates split-K partials (2 gi + 4 gh)

#define APAD 72

typedef __nv_bfloat16 bf;

// ---------------- static device scratch (allocation-free) ----------------
__device__ __align__(256) float g_encwaT[BB * HH * TENC]; // enc@Wa^T transposed [b][k][t]
__device__ __align__(256) float g_h  [BB * HH];           // hidden state fp32
__device__ __align__(256) float g_gp [NSPK * BB * G3];    // gates split-K partials
__device__ __align__(256) float g_xc [BB * XCK];          // fp32 [h|ctx] (for exact argmax)
// top-2 argmax partials per (block, row)
__device__ __align__(256) float g_pv1[NBLK * BB];
__device__ __align__(256) int   g_pi1[NBLK * BB];
__device__ __align__(256) float g_pv2[NBLK * BB];
__device__ __align__(256) int   g_pi2[NBLK * BB];

// weights / activations
__device__ __align__(256) half g_WoutF16T[(size_t)VV * XCK];// W_out^T [V][K] fp16
__device__ __align__(256) half g_Af16[BB * XCK];            // logits A fp16 [h|ctx]
__device__ __align__(256) bf g_XEhi[BB * EE];             // gates A (x part)
__device__ __align__(256) bf g_XElo[BB * EE];
__device__ __align__(256) bf g_XHhi[BB * HH];             // gates A (h part)
__device__ __align__(256) bf g_XHlo[BB * HH];
__device__ __align__(256) bf g_EncHi[BB * TENC * HH];     // encoder outputs
__device__ __align__(256) bf g_EncLo[BB * TENC * HH];
__device__ __align__(256) bf g_WaHi[HH * HH];             // W_a [k][h]
__device__ __align__(256) bf g_WaLo[HH * HH];
__device__ __align__(256) bf g_WihHi[G3 * EE];            // W_ih [n][k]
__device__ __align__(256) bf g_WihLo[G3 * EE];
__device__ __align__(256) bf g_WhhHi[G3 * HH];            // W_hh [n][k]
__device__ __align__(256) bf g_WhhLo[G3 * HH];

// ---------------- PTX helpers ----------------

__device__ __forceinline__ void mma16816(float* c, const unsigned* a, const unsigned* b)
{
    asm volatile(
        "mma.sync.aligned.m16n8k16.row.col.f32.bf16.bf16.f32 "
        "{%0,%1,%2,%3}, {%4,%5,%6,%7}, {%8,%9}, {%0,%1,%2,%3};\n"
        : "+f"(c[0]), "+f"(c[1]), "+f"(c[2]), "+f"(c[3])
        : "r"(a[0]), "r"(a[1]), "r"(a[2]), "r"(a[3]), "r"(b[0]), "r"(b[1]));
}

__device__ __forceinline__ void mma16816h(float* c, const unsigned* a, const unsigned* b)
{
    asm volatile(
        "mma.sync.aligned.m16n8k16.row.col.f32.f16.f16.f32 "
        "{%0,%1,%2,%3}, {%4,%5,%6,%7}, {%8,%9}, {%0,%1,%2,%3};\n"
        : "+f"(c[0]), "+f"(c[1]), "+f"(c[2]), "+f"(c[3])
        : "r"(a[0]), "r"(a[1]), "r"(a[2]), "r"(a[3]), "r"(b[0]), "r"(b[1]));
}

__device__ __forceinline__ void cpasync16(void* sdst, const void* gsrc)
{
    unsigned sa = (unsigned)__cvta_generic_to_shared(sdst);
    asm volatile("cp.async.cg.shared.global [%0], [%1], 16;\n" :: "r"(sa), "l"(gsrc));
}
__device__ __forceinline__ void cpasync16s(unsigned saddr, const void* gsrc)
{
    asm volatile("cp.async.cg.shared.global [%0], [%1], 16;\n" :: "r"(saddr), "l"(gsrc));
}

__device__ __forceinline__ void ldsm4(unsigned& r0, unsigned& r1, unsigned& r2, unsigned& r3,
                                      uint32_t saddr)
{
    asm volatile("ldmatrix.sync.aligned.m8n8.x4.shared.b16 {%0,%1,%2,%3}, [%4];"
                 : "=r"(r0), "=r"(r1), "=r"(r2), "=r"(r3) : "r"(saddr));
}

__device__ __forceinline__ uint32_t smem_u32(const void* p)
{
    uint32_t a;
    asm("{ .reg .u64 t; cvta.to.shared.u64 t, %1; cvt.u32.u64 %0, t; }" : "=r"(a) : "l"(p));
    return a;
}

// top-2 helpers (first-index tiebreak)
__device__ __forceinline__ bool gtpair(float x, int i, float y, int j)
{
    return (x > y) || (x == y && i < j);
}
__device__ __forceinline__ void top2_push(float& v1, int& i1, float& v2, int& i2,
                                          float x, int n)
{
    if (gtpair(x, n, v1, i1)) { v2 = v1; i2 = i1; v1 = x; i1 = n; }
    else if (gtpair(x, n, v2, i2)) { v2 = x; i2 = n; }
}
__device__ __forceinline__ void top2_merge(float& a1, int& ai1, float& a2, int& ai2,
                                           float b1, int bi1, float b2, int bi2)
{
    if (gtpair(b1, bi1, a1, ai1)) {
        float n2; int ni2;
        if (gtpair(a1, ai1, b2, bi2)) { n2 = a1; ni2 = ai1; }
        else                          { n2 = b2; ni2 = bi2; }
        a1 = b1; ai1 = bi1; a2 = n2; ai2 = ni2;
    } else {
        if (gtpair(b1, bi1, a2, ai2)) { a2 = b1; ai2 = bi1; }
    }
}

// ---------------- generic hi/lo warp-MMA path (gates/encwa; k=64, 2-stage) ------

template<int NF> struct Cfg {
    static const int BN = 64 * NF;
    static const int SA = 64 * APAD;
    static const int SW = BN * APAD;
    static const int STAGE = 2 * SA + 2 * SW;
    static const int SMEM = 2 * STAGE * 2;
};

template<int NF>
__device__ __forceinline__ void load_stage_t(
    bf* st,
    const bf* __restrict__ Ahi, const bf* __restrict__ Alo, int lda,
    const bf* __restrict__ Whi, const bf* __restrict__ Wlo, int ldw,
    int k0, int tid)
{
    bf* sAhi = st;
    bf* sAlo = st + Cfg<NF>::SA;
    bf* sWhi = st + 2 * Cfg<NF>::SA;
    bf* sWlo = st + 2 * Cfg<NF>::SA + Cfg<NF>::SW;
#pragma unroll
    for (int i = 0; i < 2; i++) {
        int c = tid + i * 256;
        int r = c >> 3, cc = (c & 7) * 8;
        cpasync16(&sAhi[r * APAD + cc], &Ahi[(size_t)r * lda + k0 + cc]);
        cpasync16(&sAlo[r * APAD + cc], &Alo[(size_t)r * lda + k0 + cc]);
    }
#pragma unroll
    for (int i = 0; i < 2 * NF; i++) {
        int c = tid + i * 256;
        int r = c >> 3, cc = (c & 7) * 8;
        cpasync16(&sWhi[r * APAD + cc], &Whi[(size_t)r * ldw + k0 + cc]);
        cpasync16(&sWlo[r * APAD + cc], &Wlo[(size_t)r * ldw + k0 + cc]);
    }
    asm volatile("cp.async.commit_group;\n");
}

template<int NF>
__device__ __forceinline__ void compute_stage_t(
    uint32_t sbase, int warp, int lane, float acc[4][NF][4])
{
    const uint32_t oAlo = Cfg<NF>::SA * 2;
    const uint32_t oWhi = 2 * Cfg<NF>::SA * 2;
    const uint32_t oWlo = (2 * Cfg<NF>::SA + Cfg<NF>::SW) * 2;
    const uint32_t aoff = ((uint32_t)((lane & 7) + ((lane >> 3) & 1) * 8)) * (APAD * 2)
                        + ((uint32_t)(lane >> 4)) * 16;
    const uint32_t boff = ((uint32_t)((lane & 7) + (lane >> 4) * 8)) * (APAD * 2)
                        + ((uint32_t)((lane >> 3) & 1)) * 16;
    const uint32_t wn = (uint32_t)warp * (8 * NF) * (APAD * 2);

#pragma unroll
    for (int kf = 0; kf < 4; kf++) {
        const uint32_t kb = (uint32_t)kf * 32;
        unsigned bhi[NF][2], blo[NF][2];
#pragma unroll
        for (int np = 0; np < NF / 2; np++) {
            const uint32_t ba = sbase + wn + (uint32_t)np * 16 * (APAD * 2) + boff + kb;
            ldsm4(bhi[2 * np][0], bhi[2 * np][1], bhi[2 * np + 1][0], bhi[2 * np + 1][1],
                  ba + oWhi);
            ldsm4(blo[2 * np][0], blo[2 * np][1], blo[2 * np + 1][0], blo[2 * np + 1][1],
                  ba + oWlo);
        }
#pragma unroll
        for (int mt = 0; mt < 4; mt++) {
            const uint32_t aa = sbase + (uint32_t)mt * 16 * (APAD * 2) + aoff + kb;
            unsigned ahi[4], alo[4];
            ldsm4(ahi[0], ahi[1], ahi[2], ahi[3], aa);
            ldsm4(alo[0], alo[1], alo[2], alo[3], aa + oAlo);
#pragma unroll
            for (int nf = 0; nf < NF; nf++) {
                mma16816(acc[mt][nf], ahi, bhi[nf]);
                mma16816(acc[mt][nf], alo, bhi[nf]);
                mma16816(acc[mt][nf], ahi, blo[nf]);
            }
        }
    }
}

template<int NF>
__device__ __forceinline__ void mainloop_t(
    const bf* Ahi, const bf* Alo, int lda,
    const bf* Whi, const bf* Wlo, int ldw,
    int nchunks, float acc[4][NF][4], bf* sm)
{
    const int tid = threadIdx.x, warp = tid >> 5, lane = tid & 31;
    const uint32_t sb = smem_u32(sm);
#pragma unroll
    for (int mt = 0; mt < 4; mt++)
#pragma unroll
        for (int nf = 0; nf < NF; nf++)
#pragma unroll
            for (int i = 0; i < 4; i++) acc[mt][nf][i] = 0.f;

    load_stage_t<NF>(sm, Ahi, Alo, lda, Whi, Wlo, ldw, 0, tid);

    for (int kc = 0; kc < nchunks; kc++) {
        const uint32_t curb = sb + (uint32_t)(kc & 1) * (Cfg<NF>::STAGE * 2);
        if (kc + 1 < nchunks) {
            bf* nxt = sm + ((kc + 1) & 1) * Cfg<NF>::STAGE;
            load_stage_t<NF>(nxt, Ahi, Alo, lda, Whi, Wlo, ldw, (kc + 1) * 64, tid);
        } else {
            asm volatile("cp.async.commit_group;\n");
        }
        asm volatile("cp.async.wait_group 1;\n");
        __syncthreads();
        compute_stage_t<NF>(curb, warp, lane, acc);
        __syncthreads();
    }
}

// ---------------- GRU gates (split-K=6) ----------------
__global__ __launch_bounds__(256) void gates_mma(void)
{
    extern __shared__ bf smg[];
    const int nt = blockIdx.x;
    const int z = blockIdx.y;
    float acc[4][2][4];
    if (z < 2) {
        const int k0 = z * 256;
        mainloop_t<2>(g_XEhi + k0, g_XElo + k0, EE,
                      g_WihHi + (size_t)nt * 128 * EE + k0,
                      g_WihLo + (size_t)nt * 128 * EE + k0, EE,
                      4, acc, smg);
    } else {
        const int k0 = (z - 2) * 256;
        mainloop_t<2>(g_XHhi + k0, g_XHlo + k0, HH,
                      g_WhhHi + (size_t)nt * 128 * HH + k0,
                      g_WhhLo + (size_t)nt * 128 * HH + k0, HH,
                      4, acc, smg);
    }
    float* C = g_gp + (size_t)z * BB * G3;
    const int tid = threadIdx.x, warp = tid >> 5, lane = tid & 31;
    const int g = lane >> 2, tg = lane & 3;
#pragma unroll
    for (int mt = 0; mt < 4; mt++) {
#pragma unroll
        for (int nf = 0; nf < 2; nf++) {
            const int n = nt * 128 + warp * 16 + nf * 8 + tg * 2;
            const int m0r = mt * 16 + g, m1r = m0r + 8;
            *(float2*)&C[(size_t)m0r * G3 + n] = make_float2(acc[mt][nf][0], acc[mt][nf][1]);
            *(float2*)&C[(size_t)m1r * G3 + n] = make_float2(acc[mt][nf][2], acc[mt][nf][3]);
        }
    }
}

// enc_wa with transposed epilogue: g_encwaT[b][k][t]. grid (8, 64), NF=2.
__global__ __launch_bounds__(256) void encwa_mma(void)
{
    extern __shared__ bf sme[];
    const int n0 = blockIdx.x * 128;
    const int m0g = blockIdx.y * 64;
    float acc[4][2][4];
    mainloop_t<2>(g_EncHi + (size_t)m0g * HH, g_EncLo + (size_t)m0g * HH, HH,
                  g_WaHi + (size_t)n0 * HH, g_WaLo + (size_t)n0 * HH, HH,
                  HH / 64, acc, sme);
    const int tid = threadIdx.x, warp = tid >> 5, lane = tid & 31;
    const int g = lane >> 2, tg = lane & 3;
    const int b = m0g >> 6;
    float* dst = g_encwaT + (size_t)b * HH * TENC;
#pragma unroll
    for (int mt = 0; mt < 4; mt++) {
#pragma unroll
        for (int nf = 0; nf < 2; nf++) {
            const int n = n0 + warp * 16 + nf * 8 + tg * 2;
            const int t0 = (m0g + mt * 16 + g) & 63, t1 = t0 + 8;
            dst[(size_t)n * TENC + t0]       = acc[mt][nf][0];
            dst[(size_t)(n + 1) * TENC + t0] = acc[mt][nf][1];
            dst[(size_t)n * TENC + t1]       = acc[mt][nf][2];
            dst[(size_t)(n + 1) * TENC + t1] = acc[mt][nf][3];
        }
    }
}

// ---------------- logits: fp16 single stream, k=64 chunks, 3-stage pipeline ----------------
// Stage layout (APAD=72 rows): [A 64x72 | W 256x72] fp16
#define LSA    (64 * APAD)               // 4608 elems
#define LSW    (256 * APAD)              // 18432 elems
#define LST    (LSA + LSW)               // 23040 elems = 46080 B
#define LSMEM  (3 * LST * 2)             // 138240 B

__device__ __forceinline__ void lg_load(uint32_t sb, int buf, int k0, int n0, int tid)
{
    const uint32_t st = sb + (uint32_t)buf * (LST * 2);
#pragma unroll
    for (int i = 0; i < 2; i++) {        // A: 64 rows x 8 x 16B chunks
        int idx = tid + i * 256;
        int r = idx >> 3, c = idx & 7;
        cpasync16s(st + r * (APAD * 2) + c * 16, &g_Af16[(size_t)r * XCK + k0 + c * 8]);
    }
#pragma unroll
    for (int i = 0; i < 8; i++) {        // W: 256 rows x 8 chunks
        int idx = tid + i * 256;
        int r = idx >> 3, c = idx & 7;
        cpasync16s(st + LSA * 2 + r * (APAD * 2) + c * 16,
                   &g_WoutF16T[(size_t)(n0 + r) * XCK + k0 + c * 8]);
    }
    asm volatile("cp.async.commit_group;\n");
}

__global__ __launch_bounds__(256, 1) void logits_mma(
    const float* __restrict__ bias, float* __restrict__ out, int t, int TD)
{
    extern __shared__ bf sml[];
    const uint32_t sb = smem_u32(sml);
    const int tid = threadIdx.x, warp = tid >> 5, lane = tid & 31;
    const int n0 = blockIdx.x * 256;

    float acc[4][4][4];
#pragma unroll
    for (int mt = 0; mt < 4; mt++)
#pragma unroll
        for (int nf = 0; nf < 4; nf++)
#pragma unroll
            for (int i = 0; i < 4; i++) acc[mt][nf][i] = 0.f;

    lg_load(sb, 0, 0, n0, tid);
    lg_load(sb, 1, 64, n0, tid);
    lg_load(sb, 2, 128, n0, tid);

    const uint32_t aoff = ((uint32_t)((lane & 7) + ((lane >> 3) & 1) * 8)) * (APAD * 2)
                        + ((uint32_t)(lane >> 4)) * 16;
    const uint32_t boff = ((uint32_t)((lane & 7) + (lane >> 4) * 8)) * (APAD * 2)
                        + ((uint32_t)((lane >> 3) & 1)) * 16;
    const uint32_t wn = (uint32_t)warp * 32 * (APAD * 2);

    for (int c = 0; c < 32; c++) {
        asm volatile("cp.async.wait_group 2;\n");
        __syncthreads();
        const uint32_t base = sb + (uint32_t)(c % 3) * (LST * 2);
#pragma unroll
        for (int kf = 0; kf < 4; kf++) {
            const uint32_t kb = (uint32_t)kf * 32;
            unsigned a[4][4], bw[4][2];
#pragma unroll
            for (int mt = 0; mt < 4; mt++) {
                const uint32_t aa = base + (uint32_t)mt * 16 * (APAD * 2) + aoff + kb;
                ldsm4(a[mt][0], a[mt][1], a[mt][2], a[mt][3], aa);
            }
#pragma unroll
            for (int np = 0; np < 2; np++) {
                const uint32_t ba = base + LSA * 2 + wn + (uint32_t)np * 16 * (APAD * 2)
                                  + boff + kb;
                ldsm4(bw[2 * np][0], bw[2 * np][1], bw[2 * np + 1][0], bw[2 * np + 1][1], ba);
            }
#pragma unroll
            for (int mt = 0; mt < 4; mt++)
#pragma unroll
                for (int nf = 0; nf < 4; nf++)
                    mma16816h(acc[mt][nf], a[mt], bw[nf]);
        }
        __syncthreads();
        if (c + 3 < 32) lg_load(sb, (c + 3) % 3, (c + 3) * 64, n0, tid);
        else asm volatile("cp.async.commit_group;\n");
    }

    // epilogue: bias + store + fused per-block TOP-2 partials
    const int g = lane >> 2, tg = lane & 3;
    float v1[8], v2[8]; int i1[8], i2[8];
#pragma unroll
    for (int e = 0; e < 8; e++) {
        v1[e] = -FLT_MAX; i1[e] = 0x7fffffff;
        v2[e] = -FLT_MAX; i2[e] = 0x7fffffff;
    }

#pragma unroll
    for (int mt = 0; mt < 4; mt++) {
#pragma unroll
        for (int nf = 0; nf < 4; nf++) {
            const int n = n0 + warp * 32 + nf * 8 + tg * 2;
            const float b0v = bias[n], b1v = bias[n + 1];
            acc[mt][nf][0] += b0v; acc[mt][nf][1] += b1v;
            acc[mt][nf][2] += b0v; acc[mt][nf][3] += b1v;
            const int m0r = mt * 16 + g, m1r = m0r + 8;
            *(float2*)&out[((size_t)m0r * TD + t) * VV + n] =
                make_float2(acc[mt][nf][0], acc[mt][nf][1]);
            *(float2*)&out[((size_t)m1r * TD + t) * VV + n] =
                make_float2(acc[mt][nf][2], acc[mt][nf][3]);
            top2_push(v1[mt * 2],     i1[mt * 2],     v2[mt * 2],     i2[mt * 2],     acc[mt][nf][0], n);
            top2_push(v1[mt * 2],     i1[mt * 2],     v2[mt * 2],     i2[mt * 2],     acc[mt][nf][1], n + 1);
            top2_push(v1[mt * 2 + 1], i1[mt * 2 + 1], v2[mt * 2 + 1], i2[mt * 2 + 1], acc[mt][nf][2], n);
            top2_push(v1[mt * 2 + 1], i1[mt * 2 + 1], v2[mt * 2 + 1], i2[mt * 2 + 1], acc[mt][nf][3], n + 1);
        }
    }
#pragma unroll
    for (int off = 1; off <= 2; off <<= 1) {
#pragma unroll
        for (int e = 0; e < 8; e++) {
            float o1 = __shfl_xor_sync(0xffffffffu, v1[e], off);
            int   oi1 = __shfl_xor_sync(0xffffffffu, i1[e], off);
            float o2 = __shfl_xor_sync(0xffffffffu, v2[e], off);
            int   oi2 = __shfl_xor_sync(0xffffffffu, i2[e], off);
            top2_merge(v1[e], i1[e], v2[e], i2[e], o1, oi1, o2, oi2);
        }
    }
    float* sv1 = (float*)sml;             // [8][64]
    int*   si1 = (int*)(sv1 + 512);
    float* sv2 = (float*)(si1 + 512);
    int*   si2 = (int*)(sv2 + 512);
    if (tg == 0) {
#pragma unroll
        for (int mt = 0; mt < 4; mt++) {
#pragma unroll
            for (int rr = 0; rr < 2; rr++) {
                const int row = mt * 16 + rr * 8 + g;
                sv1[warp * 64 + row] = v1[mt * 2 + rr];
                si1[warp * 64 + row] = i1[mt * 2 + rr];
                sv2[warp * 64 + row] = v2[mt * 2 + rr];
                si2[warp * 64 + row] = i2[mt * 2 + rr];
            }
        }
    }
    __syncthreads();
    if (tid < 64) {
        float a1 = sv1[tid], a2 = sv2[tid]; int ai1 = si1[tid], ai2 = si2[tid];
#pragma unroll
        for (int w = 1; w < 8; w++) {
            top2_merge(a1, ai1, a2, ai2,
                       sv1[w * 64 + tid], si1[w * 64 + tid],
                       sv2[w * 64 + tid], si2[w * 64 + tid]);
        }
        g_pv1[blockIdx.x * 64 + tid] = a1;
        g_pi1[blockIdx.x * 64 + tid] = ai1;
        g_pv2[blockIdx.x * 64 + tid] = a2;
        g_pi2[blockIdx.x * 64 + tid] = ai2;
    }
}

// ---------------- prep kernels ----------------

__global__ void split_hilo(const float* __restrict__ in,
                           bf* __restrict__ hi, bf* __restrict__ lo, int n)
{
    int idx = blockIdx.x * 256 + threadIdx.x;
    if (idx < n) {
        float x = in[idx];
        bf h = __float2bfloat16_rn(x);
        hi[idx] = h;
        lo[idx] = __float2bfloat16_rn(x - __bfloat162float(h));
    }
}

// W_out [K][V] fp32 -> fp16 transposed [V][K]
__global__ __launch_bounds__(256) void wout_f16(const float* __restrict__ W)
{
    __shared__ float tile[32][33];
    const int v0 = blockIdx.x * 32, k0 = blockIdx.y * 32;
    const int tx = threadIdx.x, ty = threadIdx.y;
#pragma unroll
    for (int i = 0; i < 4; i++)
        tile[ty + i * 8][tx] = W[(size_t)(k0 + ty + i * 8) * VV + v0 + tx];
    __syncthreads();
#pragma unroll
    for (int i = 0; i < 4; i++) {
        const int v = v0 + ty + i * 8;
        const int k = k0 + tx;
        g_WoutF16T[(size_t)v * XCK + k] = __float2half_rn(tile[tx][ty + i * 8]);
    }
}

__global__ __launch_bounds__(256) void init_kernel(
    const float* __restrict__ latent, const int* __restrict__ style,
    const float* __restrict__ style_emb, const float* __restrict__ W_l2h,
    const float* __restrict__ b_l2h, const float* __restrict__ emb)
{
    __shared__ float cat[8][KCAT];
    const int bg = blockIdx.y, tid = threadIdx.x;
    const int j = blockIdx.x * 256 + tid;
    for (int idx = tid; idx < 8 * KCAT; idx += 256) {
        int bb = idx / KCAT, k = idx % KCAT;
        int b = bg * 8 + bb;
        cat[bb][k] = (k < LAT) ? latent[b * LAT + k]
                               : style_emb[style[b] * STY + (k - LAT)];
    }
    __syncthreads();
    float acc[8];
    const float bj = b_l2h[j];
#pragma unroll
    for (int bb = 0; bb < 8; bb++) acc[bb] = bj;
    for (int k = 0; k < KCAT; k++) {
        float w = W_l2h[(size_t)k * HH + j];
#pragma unroll
        for (int bb = 0; bb < 8; bb++) acc[bb] += cat[bb][k] * w;
    }
#pragma unroll
    for (int bb = 0; bb < 8; bb++) {
        const int b = bg * 8 + bb;
        g_h[b * HH + j] = acc[bb];
        bf hi = __float2bfloat16_rn(acc[bb]);
        g_XHhi[b * HH + j] = hi;
        g_XHlo[b * HH + j] = __float2bfloat16_rn(acc[bb] - __bfloat162float(hi));
    }
    if (blockIdx.x == 0) {
        for (int idx = tid; idx < 8 * EE; idx += 256) {
            int bb = idx / EE, i = idx % EE;
            float x = emb[EE + i];                 // BOS token = 1
            bf hi = __float2bfloat16_rn(x);
            g_XEhi[(bg * 8 + bb) * EE + i] = hi;
            g_XElo[(bg * 8 + bb) * EE + i] = __float2bfloat16_rn(x - __bfloat162float(hi));
        }
    }
}

// ---------------- fused per-step middle kernel ----------------
__global__ __launch_bounds__(512) void step_mid(
    const float* __restrict__ b_ih, const float* __restrict__ b_hh,
    const float* __restrict__ enc)
{
    __shared__ float hs[HH];
    __shared__ float at[TENC];
    __shared__ float part[8][TENC];
    __shared__ float sred[2];
    const int b = blockIdx.x, tid = threadIdx.x;

    // Phase 1: GRU combine
#pragma unroll
    for (int j = tid; j < HH; j += 512) {
        float ir = b_ih[j], iz = b_ih[HH + j], inn = b_ih[2 * HH + j];
        float hr = b_hh[j], hz = b_hh[HH + j], hn = b_hh[2 * HH + j];
#pragma unroll
        for (int z = 0; z < 2; z++) {
            const float* P = g_gp + (size_t)z * BB * G3 + (size_t)b * G3;
            ir += P[j]; iz += P[HH + j]; inn += P[2 * HH + j];
        }
#pragma unroll
        for (int z = 2; z < 6; z++) {
            const float* P = g_gp + (size_t)z * BB * G3 + (size_t)b * G3;
            hr += P[j]; hz += P[HH + j]; hn += P[2 * HH + j];
        }
        float r  = 1.f / (1.f + expf(-(ir + hr)));
        float zz = 1.f / (1.f + expf(-(iz + hz)));
        float n  = tanhf(inn + r * hn);
        float hnew = (1.f - zz) * n + zz * g_h[b * HH + j];
        hs[j] = hnew;
        g_h[b * HH + j] = hnew;
        bf hi = __float2bfloat16_rn(hnew);
        bf lo = __float2bfloat16_rn(hnew - __bfloat162float(hi));
        g_XHhi[b * HH + j] = hi;             g_XHlo[b * HH + j] = lo;
        g_xc[(size_t)b * XCK + j] = hnew;
        g_Af16[(size_t)b * XCK + j] = __float2half_rn(hnew);
    }
    __syncthreads();

    // Phase 2: scores (coalesced via encwaT)
    {
        const int t = tid & 63, sl = tid >> 6;
        const float* ew = g_encwaT + (size_t)b * HH * TENC;
        float p = 0.f;
        const int kend = sl * 128 + 128;
#pragma unroll 4
        for (int k = sl * 128; k < kend; k++) p += hs[k] * ew[(size_t)k * TENC + t];
        part[sl][t] = p;
    }
    __syncthreads();
    if (tid < 64) {
        float s = 0.f;
#pragma unroll
        for (int sl = 0; sl < 8; sl++) s += part[sl][tid];
        at[tid] = s;
    }
    __syncthreads();
    if (tid < 32) {
        float m = fmaxf(at[tid], at[tid + 32]);
#pragma unroll
        for (int off = 16; off > 0; off >>= 1)
            m = fmaxf(m, __shfl_xor_sync(0xffffffffu, m, off));
        if (tid == 0) sred[0] = m;
    }
    __syncthreads();
    if (tid < 64) at[tid] = expf(at[tid] - sred[0]);
    __syncthreads();
    if (tid < 32) {
        float s = at[tid] + at[tid + 32];
#pragma unroll
        for (int off = 16; off > 0; off >>= 1)
            s += __shfl_xor_sync(0xffffffffu, s, off);
        if (tid == 0) sred[1] = 1.f / s;
    }
    __syncthreads();
    if (tid < 64) at[tid] *= sred[1];
    __syncthreads();

    // Phase 3: ctx
#pragma unroll
    for (int j = tid; j < HH; j += 512) {
        float c = 0.f;
        const float* eb = enc + (size_t)b * TENC * HH + j;
#pragma unroll 8
        for (int t2 = 0; t2 < TENC; t2++) c += at[t2] * eb[(size_t)t2 * HH];
        g_xc[(size_t)b * XCK + HH + j] = c;
        g_Af16[(size_t)b * XCK + HH + j] = __float2half_rn(c);
    }
}

// Final: top-2 reduce over NBLK blocks, EXACT recompute from fp32 W_out,
// pick true winner, gather embedding. grid = BB, 128 threads.
__global__ __launch_bounds__(128) void argmax_final(
    const float* __restrict__ emb, const float* __restrict__ bias,
    const float* __restrict__ Wout)
{
    __shared__ float sv1[128], sv2[128];
    __shared__ int   si1[128], si2[128];
    __shared__ float dsum[128];
    __shared__ int   stok;
    const int b = blockIdx.x, tid = threadIdx.x;

    float a1 = -FLT_MAX, a2 = -FLT_MAX; int ai1 = 0x7fffffff, ai2 = 0x7fffffff;
    if (tid < NBLK) {
        a1 = g_pv1[tid * 64 + b]; ai1 = g_pi1[tid * 64 + b];
        a2 = g_pv2[tid * 64 + b]; ai2 = g_pi2[tid * 64 + b];
    }
    sv1[tid] = a1; si1[tid] = ai1; sv2[tid] = a2; si2[tid] = ai2;
    __syncthreads();
    for (int sft = 64; sft > 0; sft >>= 1) {
        if (tid < sft) {
            float b1 = sv1[tid + sft], b2 = sv2[tid + sft];
            int bj1 = si1[tid + sft], bj2 = si2[tid + sft];
            float c1 = sv1[tid], c2 = sv2[tid];
            int cj1 = si1[tid], cj2 = si2[tid];
            top2_merge(c1, cj1, c2, cj2, b1, bj1, b2, bj2);
            sv1[tid] = c1; si1[tid] = cj1; sv2[tid] = c2; si2[tid] = cj2;
        }
        __syncthreads();
    }
    const int cand1 = si1[0], cand2 = si2[0];

    // exact recompute: d = xc(fp32) . W_out[:, cand] + bias (fp32 weights, exact)
    {
        const int cand = (tid < 64) ? cand1 : cand2;
        const int l = tid & 63;
        const float* xc = g_xc + (size_t)b * XCK;
        float s = 0.f;
#pragma unroll 8
        for (int k = l; k < XCK; k += 64)
            s += xc[k] * Wout[(size_t)k * VV + cand];
        dsum[tid] = s;
    }
    __syncthreads();
    if (tid == 0) {
        float d1 = bias[cand1], d2 = bias[cand2];
        for (int i = 0; i < 64; i++) { d1 += dsum[i]; d2 += dsum[64 + i]; }
        int tok;
        if (d1 > d2)      tok = cand1;
        else if (d2 > d1) tok = cand2;
        else              tok = (cand1 < cand2) ? cand1 : cand2;
        stok = tok;
    }
    __syncthreads();
    const int tok = stok;
    for (int e = tid; e < EE; e += 128) {
        float x = emb[(size_t)tok * EE + e];
        bf hi = __float2bfloat16_rn(x);
        g_XEhi[b * EE + e] = hi;
        g_XElo[b * EE + e] = __float2bfloat16_rn(x - __bfloat162float(hi));
    }
}

// ---------------- host launcher ----------------
extern "C" void kernel_launch(void* const* d_in, const int* in_sizes, int n_in,
                              void* d_out, int out_size)
{
    int ci = 0;
    const float* latent    = (const float*)d_in[ci++];
    const int*   style     = (const int*)  d_in[ci++];
    const float* enc       = (const float*)d_in[ci++];
    if (ci < n_in && in_sizes[ci] == 1) ci++;           // skip max_length scalar if present
    const float* emb       = (const float*)d_in[ci++];
    const float* style_emb = (const float*)d_in[ci++];
    const float* W_l2h     = (const float*)d_in[ci++];
    const float* b_l2h     = (const float*)d_in[ci++];
    const float* W_ih      = (const float*)d_in[ci++];
    const float* W_hh      = (const float*)d_in[ci++];
    const float* b_ih      = (const float*)d_in[ci++];
    const float* b_hh      = (const float*)d_in[ci++];
    const float* W_a       = (const float*)d_in[ci++];
    const float* W_out     = (const float*)d_in[ci++];
    const float* b_out     = (const float*)d_in[ci++];
    float* out = (float*)d_out;

    const int TD = out_size / (BB * VV);                // decode length (32)

    bf *pEncHi, *pEncLo, *pWaHi, *pWaLo, *pWihHi, *pWihLo, *pWhhHi, *pWhhLo;
    cudaGetSymbolAddress((void**)&pEncHi, g_EncHi);
    cudaGetSymbolAddress((void**)&pEncLo, g_EncLo);
    cudaGetSymbolAddress((void**)&pWaHi, g_WaHi);
    cudaGetSymbolAddress((void**)&pWaLo, g_WaLo);
    cudaGetSymbolAddress((void**)&pWihHi, g_WihHi);
    cudaGetSymbolAddress((void**)&pWihLo, g_WihLo);
    cudaGetSymbolAddress((void**)&pWhhHi, g_WhhHi);
    cudaGetSymbolAddress((void**)&pWhhLo, g_WhhLo);

    cudaFuncSetAttribute(logits_mma, cudaFuncAttributeMaxDynamicSharedMemorySize, LSMEM);
    cudaFuncSetAttribute(gates_mma, cudaFuncAttributeMaxDynamicSharedMemorySize,
                         Cfg<2>::SMEM);
    cudaFuncSetAttribute(encwa_mma, cudaFuncAttributeMaxDynamicSharedMemorySize,
                         Cfg<2>::SMEM);

    // one-time per-launch prep
    wout_f16<<<dim3(VV / 32, XCK / 32), dim3(32, 8)>>>(W_out);
    split_hilo<<<(BB * TENC * HH + 255) / 256, 256>>>(enc, pEncHi, pEncLo, BB * TENC * HH);
    split_hilo<<<(HH * HH + 255) / 256, 256>>>(W_a, pWaHi, pWaLo, HH * HH);
    split_hilo<<<(G3 * EE + 255) / 256, 256>>>(W_ih, pWihHi, pWihLo, G3 * EE);
    split_hilo<<<(G3 * HH + 255) / 256, 256>>>(W_hh, pWhhHi, pWhhLo, G3 * HH);
    init_kernel<<<dim3(4, 8), 256>>>(latent, style, style_emb, W_l2h, b_l2h, emb);
    encwa_mma<<<dim3(HH / 128, (BB * TENC) / 64), 256, Cfg<2>::SMEM>>>();

    for (int t = 0; t < TD; t++) {
        gates_mma<<<dim3(G3 / 128, NSPK), 256, Cfg<2>::SMEM>>>();
        step_mid<<<BB, 512>>>(b_ih, b_hh, enc);
        logits_mma<<<NBLK, 256, LSMEM>>>(b_out, out, t, TD);
        argmax_final<<<BB, 128>>>(emb, b_out, W_out);
    }
}